// round 11
// baseline (speedup 1.0000x reference)
#include <cuda_runtime.h>
#include <cuda_bf16.h>
#include <math.h>
#include <stdint.h>

// Problem constants
#define B_   2
#define QL_  2048
#define HID_ 2048
#define NH_  32
#define KVH_ 8
#define D_   64

// ===========================================================================
// PTX helpers — BASE PTX ONLY (harness targets plain sm_103: no tcgen05!)
// ===========================================================================
__device__ __forceinline__ uint32_t smem_u32(const void* p) {
    uint32_t a;
    asm("{ .reg .u64 t; cvta.to.shared.u64 t, %1; cvt.u32.u64 %0, t; }"
        : "=r"(a) : "l"(p));
    return a;
}
__device__ __forceinline__ void ldmat_x4(uint32_t* r, uint32_t addr) {
    asm volatile("ldmatrix.sync.aligned.m8n8.x4.shared.b16 {%0,%1,%2,%3}, [%4];"
                 : "=r"(r[0]), "=r"(r[1]), "=r"(r[2]), "=r"(r[3]) : "r"(addr));
}
__device__ __forceinline__ void mma_bf16(float* d, const uint32_t* a, const uint32_t* b) {
    asm volatile("mma.sync.aligned.m16n8k16.row.col.f32.bf16.bf16.f32 "
                 "{%0,%1,%2,%3}, {%4,%5,%6,%7}, {%8,%9}, {%0,%1,%2,%3};"
                 : "+f"(d[0]), "+f"(d[1]), "+f"(d[2]), "+f"(d[3])
                 : "r"(a[0]), "r"(a[1]), "r"(a[2]), "r"(a[3]),
                   "r"(b[0]), "r"(b[1]));
}
__device__ __forceinline__ void cp_async16(uint32_t dst, const void* src) {
    asm volatile("cp.async.cg.shared.global [%0], [%1], 16;"
                 :: "r"(dst), "l"(src));
}
#define CP_COMMIT()  asm volatile("cp.async.commit_group;" ::: "memory")
#define CP_WAIT(n)   asm volatile("cp.async.wait_group %0;" :: "n"(n) : "memory")

// ===========================================================================
// Scratch (device globals — no allocation allowed)
// ===========================================================================
__device__ float g_Q[(size_t)B_ * NH_  * QL_ * D_];   // [b,h,q,d] fp32
__device__ float g_K[(size_t)B_ * KVH_ * QL_ * D_];
__device__ float g_V[(size_t)B_ * KVH_ * QL_ * D_];
__device__ float g_cos[QL_ * 32];
__device__ float g_sin[QL_ * 32];
// bf16 split operands
__device__ __nv_bfloat16 g_Xhi[(size_t)B_ * QL_ * HID_];
__device__ __nv_bfloat16 g_Xlo[(size_t)B_ * QL_ * HID_];
__device__ __nv_bfloat16 g_Whi[(size_t)3072 * HID_];
__device__ __nv_bfloat16 g_Wlo[(size_t)3072 * HID_];
__device__ __nv_bfloat16 g_Ohi[(size_t)HID_ * HID_];
__device__ __nv_bfloat16 g_Olo[(size_t)HID_ * HID_];
__device__ __nv_bfloat16 g_Ahi[(size_t)B_ * QL_ * HID_];
__device__ __nv_bfloat16 g_Alo[(size_t)B_ * QL_ * HID_];
// bf16 attention operands
__device__ __nv_bfloat16 g_Qbh[(size_t)B_ * NH_  * QL_ * D_];
__device__ __nv_bfloat16 g_Qbl[(size_t)B_ * NH_  * QL_ * D_];
__device__ __nv_bfloat16 g_Kbh[(size_t)B_ * KVH_ * QL_ * D_];
__device__ __nv_bfloat16 g_Kbl[(size_t)B_ * KVH_ * QL_ * D_];
__device__ __nv_bfloat16 g_Vth[(size_t)B_ * KVH_ * D_ * QL_]; // V^T [b,kvh,d,seq]
__device__ __nv_bfloat16 g_Vtl[(size_t)B_ * KVH_ * D_ * QL_];

// ===========================================================================
// fp32 -> (bf16 hi, bf16 lo) split
// ===========================================================================
__global__ void split_kernel(const float* __restrict__ src,
                             __nv_bfloat16* __restrict__ hi,
                             __nv_bfloat16* __restrict__ lo, int n)
{
    int i = blockIdx.x * blockDim.x + threadIdx.x;
    if (i >= n) return;
    float v = src[i];
    __nv_bfloat16 h = __float2bfloat16(v);
    hi[i] = h;
    lo[i] = __float2bfloat16(v - __bfloat162float(h));
}

// Transpose + split: W[K, Ncols] -> T[(rowOffset+n), k] bf16 hi/lo, ldT = K.
__global__ void transpose_split_kernel(const float* __restrict__ W,
                                       __nv_bfloat16* __restrict__ Thi,
                                       __nv_bfloat16* __restrict__ Tlo,
                                       int K, int Ncols, int rowOffset)
{
    __shared__ float tile[32][33];
    int k0 = blockIdx.y * 32, n0 = blockIdx.x * 32;
    int tx = threadIdx.x, ty = threadIdx.y;
#pragma unroll
    for (int i = 0; i < 4; i++) {
        int k = k0 + ty + i * 8;
        tile[ty + i * 8][tx] = W[(size_t)k * Ncols + n0 + tx];
    }
    __syncthreads();
#pragma unroll
    for (int i = 0; i < 4; i++) {
        int n = n0 + ty + i * 8;
        float v = tile[tx][ty + i * 8];
        __nv_bfloat16 h = __float2bfloat16(v);
        size_t o = (size_t)(rowOffset + n) * K + k0 + tx;
        Thi[o] = h;
        Tlo[o] = __float2bfloat16(v - __bfloat162float(h));
    }
}

// V transpose+split: g_V [bk, seq, 64] fp32 -> Vt [bk, 64, 2048] bf16 hi/lo
__global__ void vtrans_split_kernel(const float* __restrict__ V,
                                    __nv_bfloat16* __restrict__ Thi,
                                    __nv_bfloat16* __restrict__ Tlo)
{
    __shared__ float tile[32][33];
    int bk = blockIdx.z;
    int s0 = blockIdx.x * 32, d0 = blockIdx.y * 32;
    int tx = threadIdx.x, ty = threadIdx.y;
    const float* Vb = V + (size_t)bk * QL_ * 64;
#pragma unroll
    for (int i = 0; i < 4; i++) {
        int s = s0 + ty + i * 8;
        tile[ty + i * 8][tx] = Vb[(size_t)s * 64 + d0 + tx];
    }
    __syncthreads();
#pragma unroll
    for (int i = 0; i < 4; i++) {
        int d = d0 + ty + i * 8;
        float v = tile[tx][ty + i * 8];
        __nv_bfloat16 h = __float2bfloat16(v);
        size_t o = (size_t)bk * 64 * QL_ + (size_t)d * QL_ + s0 + tx;
        Thi[o] = h;
        Tlo[o] = __float2bfloat16(v - __bfloat162float(h));
    }
}

// ===========================================================================
// mma.sync bf16x3 GEMM. CTA 128x128, 8 warps (2x4), warp 64x32, m16n8k16.
// B fragments now loaded pairwise via ldmatrix.x4 (m0..m3 -> {r0,r2},{r1,r3}).
// ===========================================================================
#define TILE_B   18432
#define STAGE_B  (4 * TILE_B)
#define MMA_SMEM_BYTES (2 * STAGE_B)

template<int MODE>
__global__ void __launch_bounds__(256)
mma_gemm(const __nv_bfloat16* __restrict__ Ahi, const __nv_bfloat16* __restrict__ Alo,
         const __nv_bfloat16* __restrict__ Bhi, const __nv_bfloat16* __restrict__ Blo,
         float* __restrict__ C0, float* __restrict__ C1, float* __restrict__ C2,
         int M, int N, int K)
{
    extern __shared__ char smc[];
    const uint32_t sbase = smem_u32(smc);
    const int tid  = threadIdx.x;
    const int wid  = tid >> 5;
    const int lane = tid & 31;
    const int bx   = blockIdx.x;
    const int by   = blockIdx.y;
    const int wm   = wid >> 2;
    const int wn   = wid & 3;

    float acc[4][4][4];
#pragma unroll
    for (int mt = 0; mt < 4; mt++)
#pragma unroll
        for (int nt = 0; nt < 4; nt++)
#pragma unroll
            for (int r = 0; r < 4; r++) acc[mt][nt][r] = 0.f;

    const int NC = K >> 6;

    auto load_chunk = [&](int ci, int s) {
        const int k0 = ci * 64;
        const uint32_t sb = sbase + s * STAGE_B;
#pragma unroll
        for (int it = 0; it < 4; it++) {
            int f = tid + it * 256;
            int r = f >> 3, seg = f & 7;
            uint32_t dst = sb + r * 144 + seg * 16;
            size_t ga = (size_t)(by * 128 + r) * K + k0 + seg * 8;
            size_t gb = (size_t)(bx * 128 + r) * K + k0 + seg * 8;
            cp_async16(dst,              Ahi + ga);
            cp_async16(dst + TILE_B,     Alo + ga);
            cp_async16(dst + 2 * TILE_B, Bhi + gb);
            cp_async16(dst + 3 * TILE_B, Blo + gb);
        }
        CP_COMMIT();
    };

    load_chunk(0, 0);

    const int ar   = lane & 15;          // 16-row index (A and B x4 loads)
    const int acol = (lane >> 4) * 8;    // col half

    for (int ci = 0; ci < NC; ci++) {
        const int s = ci & 1;
        if (ci + 1 < NC) { load_chunk(ci + 1, s ^ 1); CP_WAIT(1); }
        else             { CP_WAIT(0); }
        __syncthreads();

        const uint32_t sb    = sbase + s * STAGE_B;
        const uint32_t aBase = sb + wm * 64 * 144;
        const uint32_t bBase = sb + 2 * TILE_B + wn * 32 * 144;

#pragma unroll
        for (int ks = 0; ks < 4; ks++) {
            const int kc = ks * 16;
            uint32_t ahi[4][4], alo[4][4], bhi[4][2], blo[4][2];
#pragma unroll
            for (int mt = 0; mt < 4; mt++) {
                uint32_t a = aBase + (mt * 16 + ar) * 144 + (kc + acol) * 2;
                ldmat_x4(ahi[mt], a);
                ldmat_x4(alo[mt], a + TILE_B);
            }
            // B: two n8k16 fragments per ldmatrix.x4
#pragma unroll
            for (int ntp = 0; ntp < 2; ntp++) {
                uint32_t b = bBase + (ntp * 16 + ar) * 144 + (kc + acol) * 2;
                uint32_t r4[4];
                ldmat_x4(r4, b);
                bhi[2 * ntp][0] = r4[0]; bhi[2 * ntp][1] = r4[2];
                bhi[2 * ntp + 1][0] = r4[1]; bhi[2 * ntp + 1][1] = r4[3];
                ldmat_x4(r4, b + TILE_B);
                blo[2 * ntp][0] = r4[0]; blo[2 * ntp][1] = r4[2];
                blo[2 * ntp + 1][0] = r4[1]; blo[2 * ntp + 1][1] = r4[3];
            }
#pragma unroll
            for (int mt = 0; mt < 4; mt++)
#pragma unroll
                for (int nt = 0; nt < 4; nt++)
                    mma_bf16(acc[mt][nt], ahi[mt], bhi[nt]);
#pragma unroll
            for (int mt = 0; mt < 4; mt++)
#pragma unroll
                for (int nt = 0; nt < 4; nt++)
                    mma_bf16(acc[mt][nt], ahi[mt], blo[nt]);
#pragma unroll
            for (int mt = 0; mt < 4; mt++)
#pragma unroll
                for (int nt = 0; nt < 4; nt++)
                    mma_bf16(acc[mt][nt], alo[mt], bhi[nt]);
        }
        __syncthreads();
    }

    const int lrow = lane >> 2;
    const int lcol = (lane & 3) * 2;
#pragma unroll
    for (int mt = 0; mt < 4; mt++) {
#pragma unroll
        for (int nt = 0; nt < 4; nt++) {
            int row0 = by * 128 + wm * 64 + mt * 16 + lrow;
            int col  = bx * 128 + wn * 32 + nt * 8 + lcol;
#pragma unroll
            for (int half = 0; half < 2; half++) {
                int m = row0 + half * 8;
                float2 v = make_float2(acc[mt][nt][half * 2],
                                       acc[mt][nt][half * 2 + 1]);
                if (MODE == 0) {
                    *(float2*)&C0[(size_t)m * N + col] = v;
                } else {
                    int b = m >> 11, t = m & 2047, dd = col & 63;
                    if (col < 2048) {
                        int h = col >> 6;
                        *(float2*)&C0[((((size_t)b * NH_ + h) * QL_ + t) << 6) + dd] = v;
                    } else if (col < 2560) {
                        int h = (col - 2048) >> 6;
                        *(float2*)&C1[((((size_t)b * KVH_ + h) * QL_ + t) << 6) + dd] = v;
                    } else {
                        int h = (col - 2560) >> 6;
                        *(float2*)&C2[((((size_t)b * KVH_ + h) * QL_ + t) << 6) + dd] = v;
                    }
                }
            }
        }
    }
}

// ===========================================================================
// RoPE
// ===========================================================================
__global__ void rope_table_kernel(float* __restrict__ ct, float* __restrict__ st,
                                  int Q)
{
    int idx = blockIdx.x * blockDim.x + threadIdx.x;
    if (idx >= Q * 32) return;
    int j = idx & 31;
    int t = idx >> 5;
    float freq = (float)(1.0 / pow(10000.0, (double)(2 * j) / 64.0));
    float ang  = (float)t * freq;
    double cd, sd;
    sincos((double)ang, &sd, &cd);
    ct[idx] = (float)cd;
    st[idx] = (float)sd;
}

__global__ void rope_apply_bf16(const float* __restrict__ buf,
                                const float* __restrict__ ct,
                                const float* __restrict__ st,
                                __nv_bfloat16* __restrict__ oh,
                                __nv_bfloat16* __restrict__ ol,
                                int Q, int total)
{
    int idx = blockIdx.x * blockDim.x + threadIdx.x;
    if (idx >= total) return;
    int j  = idx & 31;
    int t  = (idx >> 5) % Q;
    int bh = idx / (32 * Q);
    size_t base = ((size_t)bh * Q + t) * 64;

    float c = ct[(t << 5) + j];
    float s = st[(t << 5) + j];
    float x1 = buf[base + j];
    float x2 = buf[base + j + 32];
    float r1 = x1 * c - x2 * s;
    float r2 = x2 * c + x1 * s;
    __nv_bfloat16 h1 = __float2bfloat16(r1);
    __nv_bfloat16 h2 = __float2bfloat16(r2);
    oh[base + j]      = h1;
    oh[base + j + 32] = h2;
    ol[base + j]      = __float2bfloat16(r1 - __bfloat162float(h1));
    ol[base + j + 32] = __float2bfloat16(r2 - __bfloat162float(h2));
}

// ===========================================================================
// Flash attention on mma.sync bf16x3. Grid (QL/128, NH, B), 256 thr, 8 warps.
// ===========================================================================
#define AT_KTILE 9216                  // 64 rows * 144 B
#define AT_STAGE (4 * AT_KTILE)        // 36864
#define AT_Q_OFF (2 * AT_STAGE)        // 73728
#define AT_SMEM  (AT_Q_OFF + 2 * 128 * 144)   // 110592

__global__ void __launch_bounds__(256, 1)
attn_mma(const __nv_bfloat16* __restrict__ Qh, const __nv_bfloat16* __restrict__ Ql,
         const __nv_bfloat16* __restrict__ Kh, const __nv_bfloat16* __restrict__ Kl,
         const __nv_bfloat16* __restrict__ Vth, const __nv_bfloat16* __restrict__ Vtl,
         __nv_bfloat16* __restrict__ Ohi, __nv_bfloat16* __restrict__ Olo)
{
    extern __shared__ char smc[];
    const uint32_t sbase = smem_u32(smc);
    const int tid  = threadIdx.x;
    const int wid  = tid >> 5;
    const int lane = tid & 31;
    const int qt   = blockIdx.x;
    const int h    = blockIdx.y;
    const int b    = blockIdx.z;
    const int kvh  = h >> 2;           // NH/KVH = 4
    const int q0   = qt * 128;

    const __nv_bfloat16* Qgh = Qh + (((size_t)b * NH_ + h) * QL_ + q0) * 64;
    const __nv_bfloat16* Qgl = Ql + (((size_t)b * NH_ + h) * QL_ + q0) * 64;
    const __nv_bfloat16* Kgh = Kh + (((size_t)b * KVH_ + kvh) * QL_) * 64;
    const __nv_bfloat16* Kgl = Kl + (((size_t)b * KVH_ + kvh) * QL_) * 64;
    const __nv_bfloat16* Vgh = Vth + (((size_t)b * KVH_ + kvh) * 64) * QL_;
    const __nv_bfloat16* Vgl = Vtl + (((size_t)b * KVH_ + kvh) * 64) * QL_;

#pragma unroll
    for (int it = 0; it < 4; it++) {
        int f = tid + it * 256;
        int r = f >> 3, seg = f & 7;
        uint32_t dst = sbase + AT_Q_OFF + r * 144 + seg * 16;
        cp_async16(dst,               Qgh + (size_t)r * 64 + seg * 8);
        cp_async16(dst + 128 * 144,   Qgl + (size_t)r * 64 + seg * 8);
    }
    CP_COMMIT();

    auto load_kv = [&](int kt, int s) {
        const int k0 = kt * 64;
        const uint32_t sb = sbase + s * AT_STAGE;
#pragma unroll
        for (int it = 0; it < 2; it++) {
            int f = tid + it * 256;
            int r = f >> 3, seg = f & 7;
            uint32_t dst = sb + r * 144 + seg * 16;
            size_t gk = (size_t)(k0 + r) * 64 + seg * 8;
            size_t gv = (size_t)r * QL_ + k0 + seg * 8;
            cp_async16(dst,                Kgh + gk);
            cp_async16(dst + AT_KTILE,     Kgl + gk);
            cp_async16(dst + 2 * AT_KTILE, Vgh + gv);
            cp_async16(dst + 3 * AT_KTILE, Vgl + gv);
        }
        CP_COMMIT();
    };

    load_kv(0, 0);

    CP_WAIT(1);
    __syncthreads();

    const int ar   = lane & 15;
    const int acol = (lane >> 4) * 8;

    uint32_t qfh[4][4], qfl[4][4];
    {
        uint32_t qBase = sbase + AT_Q_OFF + (wid * 16 + ar) * 144;
#pragma unroll
        for (int ks = 0; ks < 4; ks++) {
            uint32_t a = qBase + (ks * 16 + acol) * 2;
            ldmat_x4(qfh[ks], a);
            ldmat_x4(qfl[ks], a + 128 * 144);
        }
    }

    float o[8][4];
#pragma unroll
    for (int nt = 0; nt < 8; nt++)
#pragma unroll
        for (int j = 0; j < 4; j++) o[nt][j] = 0.f;
    float m0 = -1e30f, m1 = -1e30f, l0 = 0.f, l1 = 0.f;

    const int ktiles = qt * 2 + 2;
    const int qg0 = q0 + wid * 16 + (lane >> 2);
    const int qg1 = qg0 + 8;
    const int lc2 = (lane & 3) * 2;

    for (int kt = 0; kt < ktiles; kt++) {
        const int s = kt & 1;
        if (kt + 1 < ktiles) { load_kv(kt + 1, s ^ 1); CP_WAIT(1); }
        else                 { CP_WAIT(0); }
        __syncthreads();

        const uint32_t kb = sbase + s * AT_STAGE;
        const uint32_t vb = kb + 2 * AT_KTILE;
        const int k0 = kt * 64;

        // ---- S = Q K^T (bf16x3), B frags via ldmatrix.x4 pairs ----
        float sf[8][4];
#pragma unroll
        for (int nt = 0; nt < 8; nt++)
#pragma unroll
            for (int j = 0; j < 4; j++) sf[nt][j] = 0.f;

#pragma unroll
        for (int ks = 0; ks < 4; ks++) {
            uint32_t bh[8][2], bl[8][2];
#pragma unroll
            for (int ntp = 0; ntp < 4; ntp++) {
                uint32_t a = kb + (ntp * 16 + ar) * 144 + (ks * 16 + acol) * 2;
                uint32_t r4[4];
                ldmat_x4(r4, a);
                bh[2 * ntp][0] = r4[0]; bh[2 * ntp][1] = r4[2];
                bh[2 * ntp + 1][0] = r4[1]; bh[2 * ntp + 1][1] = r4[3];
                ldmat_x4(r4, a + AT_KTILE);
                bl[2 * ntp][0] = r4[0]; bl[2 * ntp][1] = r4[2];
                bl[2 * ntp + 1][0] = r4[1]; bl[2 * ntp + 1][1] = r4[3];
            }
#pragma unroll
            for (int nt = 0; nt < 8; nt++) mma_bf16(sf[nt], qfh[ks], bh[nt]);
#pragma unroll
            for (int nt = 0; nt < 8; nt++) mma_bf16(sf[nt], qfh[ks], bl[nt]);
#pragma unroll
            for (int nt = 0; nt < 8; nt++) mma_bf16(sf[nt], qfl[ks], bh[nt]);
        }

        // ---- scale + causal mask + row max ----
        const bool domask = (kt >= ktiles - 2);
        float rm0 = -1e30f, rm1 = -1e30f;
#pragma unroll
        for (int nt = 0; nt < 8; nt++) {
            int kg = k0 + nt * 8 + lc2;
#pragma unroll
            for (int j = 0; j < 4; j++) {
                float v = sf[nt][j] * 0.125f;
                if (domask) {
                    int kcol = kg + (j & 1);
                    int qrow = (j < 2) ? qg0 : qg1;
                    if (kcol > qrow) v = -1e30f;
                }
                sf[nt][j] = v;
                if (j < 2) rm0 = fmaxf(rm0, v); else rm1 = fmaxf(rm1, v);
            }
        }
        rm0 = fmaxf(rm0, __shfl_xor_sync(0xffffffffu, rm0, 1));
        rm0 = fmaxf(rm0, __shfl_xor_sync(0xffffffffu, rm0, 2));
        rm1 = fmaxf(rm1, __shfl_xor_sync(0xffffffffu, rm1, 1));
        rm1 = fmaxf(rm1, __shfl_xor_sync(0xffffffffu, rm1, 2));

        float nm0 = fmaxf(m0, rm0), nm1 = fmaxf(m1, rm1);
        float c0 = __expf(m0 - nm0), c1 = __expf(m1 - nm1);

        float rs0 = 0.f, rs1 = 0.f;
        uint32_t ph[8][2], pl[8][2];
#pragma unroll
        for (int nt = 0; nt < 8; nt++) {
            float p0 = __expf(sf[nt][0] - nm0);
            float p1 = __expf(sf[nt][1] - nm0);
            float p2 = __expf(sf[nt][2] - nm1);
            float p3 = __expf(sf[nt][3] - nm1);
            rs0 += p0 + p1;
            rs1 += p2 + p3;
            __nv_bfloat162 h01 = __floats2bfloat162_rn(p0, p1);
            __nv_bfloat162 h23 = __floats2bfloat162_rn(p2, p3);
            ph[nt][0] = *(uint32_t*)&h01;
            ph[nt][1] = *(uint32_t*)&h23;
            __nv_bfloat162 l01 = __floats2bfloat162_rn(
                p0 - __bfloat162float(h01.x), p1 - __bfloat162float(h01.y));
            __nv_bfloat162 l23 = __floats2bfloat162_rn(
                p2 - __bfloat162float(h23.x), p3 - __bfloat162float(h23.y));
            pl[nt][0] = *(uint32_t*)&l01;
            pl[nt][1] = *(uint32_t*)&l23;
        }
        rs0 += __shfl_xor_sync(0xffffffffu, rs0, 1);
        rs0 += __shfl_xor_sync(0xffffffffu, rs0, 2);
        rs1 += __shfl_xor_sync(0xffffffffu, rs1, 1);
        rs1 += __shfl_xor_sync(0xffffffffu, rs1, 2);

        l0 = l0 * c0 + rs0;
        l1 = l1 * c1 + rs1;
        m0 = nm0;
        m1 = nm1;

#pragma unroll
        for (int nt = 0; nt < 8; nt++) {
            o[nt][0] *= c0; o[nt][1] *= c0;
            o[nt][2] *= c1; o[nt][3] *= c1;
        }

        // ---- O += P V  (bf16x3), V frags via ldmatrix.x4 pairs ----
#pragma unroll
        for (int ks = 0; ks < 4; ks++) {
            uint32_t bh[8][2], bl[8][2];
#pragma unroll
            for (int ntp = 0; ntp < 4; ntp++) {
                uint32_t a = vb + (ntp * 16 + ar) * 144 + (ks * 16 + acol) * 2;
                uint32_t r4[4];
                ldmat_x4(r4, a);
                bh[2 * ntp][0] = r4[0]; bh[2 * ntp][1] = r4[2];
                bh[2 * ntp + 1][0] = r4[1]; bh[2 * ntp + 1][1] = r4[3];
                ldmat_x4(r4, a + AT_KTILE);
                bl[2 * ntp][0] = r4[0]; bl[2 * ntp][1] = r4[2];
                bl[2 * ntp + 1][0] = r4[1]; bl[2 * ntp + 1][1] = r4[3];
            }
            uint32_t pah[4] = {ph[2 * ks][0], ph[2 * ks][1],
                               ph[2 * ks + 1][0], ph[2 * ks + 1][1]};
            uint32_t pal[4] = {pl[2 * ks][0], pl[2 * ks][1],
                               pl[2 * ks + 1][0], pl[2 * ks + 1][1]};
#pragma unroll
            for (int nt = 0; nt < 8; nt++) mma_bf16(o[nt], pah, bh[nt]);
#pragma unroll
            for (int nt = 0; nt < 8; nt++) mma_bf16(o[nt], pal, bh[nt]);
#pragma unroll
            for (int nt = 0; nt < 8; nt++) mma_bf16(o[nt], pah, bl[nt]);
        }
        __syncthreads();
    }

    // ---- epilogue ----
    float inv0 = 1.0f / l0, inv1 = 1.0f / l1;
    int gr0 = b * QL_ + q0 + wid * 16 + (lane >> 2);
    int gr1 = gr0 + 8;
#pragma unroll
    for (int nt = 0; nt < 8; nt++) {
        int gc = h * 64 + nt * 8 + lc2;
        float v0 = o[nt][0] * inv0, v1 = o[nt][1] * inv0;
        float v2 = o[nt][2] * inv1, v3 = o[nt][3] * inv1;
        __nv_bfloat162 h01 = __floats2bfloat162_rn(v0, v1);
        __nv_bfloat162 h23 = __floats2bfloat162_rn(v2, v3);
        size_t o0 = (size_t)gr0 * HID_ + gc;
        size_t o1 = (size_t)gr1 * HID_ + gc;
        *(__nv_bfloat162*)&Ohi[o0] = h01;
        *(__nv_bfloat162*)&Ohi[o1] = h23;
        __nv_bfloat162 l01 = __floats2bfloat162_rn(
            v0 - __bfloat162float(h01.x), v1 - __bfloat162float(h01.y));
        __nv_bfloat162 l23 = __floats2bfloat162_rn(
            v2 - __bfloat162float(h23.x), v3 - __bfloat162float(h23.y));
        *(__nv_bfloat162*)&Olo[o0] = l01;
        *(__nv_bfloat162*)&Olo[o1] = l23;
    }
}

// ===========================================================================
extern "C" void kernel_launch(void* const* d_in, const int* in_sizes, int n_in,
                              void* d_out, int out_size)
{
    const float* X  = (const float*)d_in[0];
    const float* Wq = (const float*)d_in[2];
    const float* Wk = (const float*)d_in[3];
    const float* Wv = (const float*)d_in[4];
    const float* Wo = (const float*)d_in[5];
    float* out = (float*)d_out;

    float *qp, *kp, *vp, *cp, *sp;
    __nv_bfloat16 *xhi, *xlo, *whi, *wlo, *ohi, *olo, *ahi, *alo;
    __nv_bfloat16 *qbh, *qbl, *kbh, *kbl, *vth, *vtl;
    cudaGetSymbolAddress((void**)&qp, g_Q);
    cudaGetSymbolAddress((void**)&kp, g_K);
    cudaGetSymbolAddress((void**)&vp, g_V);
    cudaGetSymbolAddress((void**)&cp, g_cos);
    cudaGetSymbolAddress((void**)&sp, g_sin);
    cudaGetSymbolAddress((void**)&xhi, g_Xhi);
    cudaGetSymbolAddress((void**)&xlo, g_Xlo);
    cudaGetSymbolAddress((void**)&whi, g_Whi);
    cudaGetSymbolAddress((void**)&wlo, g_Wlo);
    cudaGetSymbolAddress((void**)&ohi, g_Ohi);
    cudaGetSymbolAddress((void**)&olo, g_Olo);
    cudaGetSymbolAddress((void**)&ahi, g_Ahi);
    cudaGetSymbolAddress((void**)&alo, g_Alo);
    cudaGetSymbolAddress((void**)&qbh, g_Qbh);
    cudaGetSymbolAddress((void**)&qbl, g_Qbl);
    cudaGetSymbolAddress((void**)&kbh, g_Kbh);
    cudaGetSymbolAddress((void**)&kbl, g_Kbl);
    cudaGetSymbolAddress((void**)&vth, g_Vth);
    cudaGetSymbolAddress((void**)&vtl, g_Vtl);

    const int M = B_ * QL_;   // 4096

    cudaFuncSetAttribute(mma_gemm<0>, cudaFuncAttributeMaxDynamicSharedMemorySize, MMA_SMEM_BYTES);
    cudaFuncSetAttribute(mma_gemm<1>, cudaFuncAttributeMaxDynamicSharedMemorySize, MMA_SMEM_BYTES);
    cudaFuncSetAttribute(attn_mma, cudaFuncAttributeMaxDynamicSharedMemorySize, AT_SMEM);

    // Launches 1..5 (so ncu -s 5 -c 1 profiles the QKV GEMM at #6)
    rope_table_kernel<<<(QL_ * 32 + 255) / 256, 256>>>(cp, sp, QL_);
    split_kernel<<<(M * HID_ + 255) / 256, 256>>>(X, xhi, xlo, M * HID_);
    transpose_split_kernel<<<dim3(2048 / 32, HID_ / 32), dim3(32, 8)>>>(Wq, whi, wlo, HID_, 2048, 0);
    transpose_split_kernel<<<dim3(512 / 32,  HID_ / 32), dim3(32, 8)>>>(Wk, whi, wlo, HID_, 512, 2048);
    transpose_split_kernel<<<dim3(512 / 32,  HID_ / 32), dim3(32, 8)>>>(Wv, whi, wlo, HID_, 512, 2560);

    // #6: fused QKV projection on tensor cores (scatter to head layouts, fp32)
    mma_gemm<1><<<dim3(3072 / 128, M / 128), 256, MMA_SMEM_BYTES>>>(
        xhi, xlo, whi, wlo, qp, kp, vp, M, 3072, HID_);

    // RoPE -> bf16 hi/lo Q,K ; V^T split ; Wo transpose (needed only by last GEMM)
    {
        int totq = B_ * NH_  * QL_ * 32;
        int totk = B_ * KVH_ * QL_ * 32;
        rope_apply_bf16<<<(totq + 255) / 256, 256>>>(qp, cp, sp, qbh, qbl, QL_, totq);
        rope_apply_bf16<<<(totk + 255) / 256, 256>>>(kp, cp, sp, kbh, kbl, QL_, totk);
        vtrans_split_kernel<<<dim3(QL_ / 32, 2, B_ * KVH_), dim3(32, 8)>>>(vp, vth, vtl);
        transpose_split_kernel<<<dim3(2048 / 32, HID_ / 32), dim3(32, 8)>>>(Wo, ohi, olo, HID_, 2048, 0);
    }

    // Attention on tensor cores, emits bf16 hi/lo split output
    attn_mma<<<dim3(QL_ / 128, NH_, B_), 256, AT_SMEM>>>(
        qbh, qbl, kbh, kbl, vth, vtl, ahi, alo);

    // Output projection on tensor cores
    mma_gemm<0><<<dim3(HID_ / 128, M / 128), 256, MMA_SMEM_BYTES>>>(
        ahi, alo, ohi, olo, out, nullptr, nullptr, M, HID_, HID_);
}

// round 12
// speedup vs baseline: 1.6922x; 1.6922x over previous
#include <cuda_runtime.h>
#include <cuda_fp16.h>
#include <math.h>
#include <stdint.h>

// Problem constants
#define B_   2
#define QL_  2048
#define HID_ 2048
#define NH_  32
#define KVH_ 8
#define D_   64

// ===========================================================================
// PTX helpers — BASE PTX ONLY (harness targets plain sm_103: no tcgen05!)
// ===========================================================================
__device__ __forceinline__ uint32_t smem_u32(const void* p) {
    uint32_t a;
    asm("{ .reg .u64 t; cvta.to.shared.u64 t, %1; cvt.u32.u64 %0, t; }"
        : "=r"(a) : "l"(p));
    return a;
}
__device__ __forceinline__ void ldmat_x4(uint32_t* r, uint32_t addr) {
    asm volatile("ldmatrix.sync.aligned.m8n8.x4.shared.b16 {%0,%1,%2,%3}, [%4];"
                 : "=r"(r[0]), "=r"(r[1]), "=r"(r[2]), "=r"(r[3]) : "r"(addr));
}
__device__ __forceinline__ void ldmat_x2(uint32_t* r, uint32_t addr) {
    asm volatile("ldmatrix.sync.aligned.m8n8.x2.shared.b16 {%0,%1}, [%2];"
                 : "=r"(r[0]), "=r"(r[1]) : "r"(addr));
}
// fp16 MMA: D(f32) += A(f16) * B(f16)
__device__ __forceinline__ void mma_f16(float* d, const uint32_t* a, const uint32_t* b) {
    asm volatile("mma.sync.aligned.m16n8k16.row.col.f32.f16.f16.f32 "
                 "{%0,%1,%2,%3}, {%4,%5,%6,%7}, {%8,%9}, {%0,%1,%2,%3};"
                 : "+f"(d[0]), "+f"(d[1]), "+f"(d[2]), "+f"(d[3])
                 : "r"(a[0]), "r"(a[1]), "r"(a[2]), "r"(a[3]),
                   "r"(b[0]), "r"(b[1]));
}
__device__ __forceinline__ void cp_async16(uint32_t dst, const void* src) {
    asm volatile("cp.async.cg.shared.global [%0], [%1], 16;"
                 :: "r"(dst), "l"(src));
}
#define CP_COMMIT()  asm volatile("cp.async.commit_group;" ::: "memory")
#define CP_WAIT(n)   asm volatile("cp.async.wait_group %0;" :: "n"(n) : "memory")

// ===========================================================================
// Scratch (device globals — no allocation allowed)
// ===========================================================================
__device__ float g_Q[(size_t)B_ * NH_  * QL_ * D_];   // [b,h,q,d] fp32
__device__ float g_K[(size_t)B_ * KVH_ * QL_ * D_];
__device__ float g_V[(size_t)B_ * KVH_ * QL_ * D_];
__device__ float g_cos[QL_ * 32];
__device__ float g_sin[QL_ * 32];
// fp16 operands (A-side split hi/lo, B-side single rounded)
__device__ __half g_Xhi[(size_t)B_ * QL_ * HID_];     // X split (A of QKV gemm)
__device__ __half g_Xlo[(size_t)B_ * QL_ * HID_];
__device__ __half g_W  [(size_t)3072 * HID_];         // Wq|Wk|Wv transposed [N,K] single
__device__ __half g_Wo [(size_t)HID_ * HID_];         // Wo transposed [N,K] single
__device__ __half g_Ahi[(size_t)B_ * QL_ * HID_];     // attn out split (A of Wo gemm)
__device__ __half g_Alo[(size_t)B_ * QL_ * HID_];
__device__ __half g_Qbh[(size_t)B_ * NH_  * QL_ * D_]; // roped Q split (A of S)
__device__ __half g_Qbl[(size_t)B_ * NH_  * QL_ * D_];
__device__ __half g_Kb [(size_t)B_ * KVH_ * QL_ * D_]; // roped K single (B of S)
__device__ __half g_Vt [(size_t)B_ * KVH_ * D_ * QL_]; // V^T single (B of PV)

// ===========================================================================
// fp32 -> (fp16 hi, fp16 lo) split
// ===========================================================================
__global__ void split_kernel(const float* __restrict__ src,
                             __half* __restrict__ hi,
                             __half* __restrict__ lo, int n)
{
    int i = blockIdx.x * blockDim.x + threadIdx.x;
    if (i >= n) return;
    float v = src[i];
    __half h = __float2half_rn(v);
    hi[i] = h;
    lo[i] = __float2half_rn(v - __half2float(h));
}

// Transpose + round: W[K, Ncols] -> T[(rowOffset+n), k] fp16, ldT = K.
__global__ void transpose_half_kernel(const float* __restrict__ W,
                                      __half* __restrict__ T,
                                      int K, int Ncols, int rowOffset)
{
    __shared__ float tile[32][33];
    int k0 = blockIdx.y * 32, n0 = blockIdx.x * 32;
    int tx = threadIdx.x, ty = threadIdx.y;    // (32, 8)
#pragma unroll
    for (int i = 0; i < 4; i++) {
        int k = k0 + ty + i * 8;
        tile[ty + i * 8][tx] = W[(size_t)k * Ncols + n0 + tx];
    }
    __syncthreads();
#pragma unroll
    for (int i = 0; i < 4; i++) {
        int n = n0 + ty + i * 8;
        T[(size_t)(rowOffset + n) * K + k0 + tx] = __float2half_rn(tile[tx][ty + i * 8]);
    }
}

// V transpose: g_V [bk, seq, 64] fp32 -> Vt [bk, 64, 2048] fp16 single
__global__ void vtrans_half_kernel(const float* __restrict__ V,
                                   __half* __restrict__ T)
{
    __shared__ float tile[32][33];
    int bk = blockIdx.z;
    int s0 = blockIdx.x * 32, d0 = blockIdx.y * 32;
    int tx = threadIdx.x, ty = threadIdx.y;
    const float* Vb = V + (size_t)bk * QL_ * 64;
#pragma unroll
    for (int i = 0; i < 4; i++) {
        int s = s0 + ty + i * 8;
        tile[ty + i * 8][tx] = Vb[(size_t)s * 64 + d0 + tx];
    }
    __syncthreads();
#pragma unroll
    for (int i = 0; i < 4; i++) {
        int d = d0 + ty + i * 8;
        T[(size_t)bk * 64 * QL_ + (size_t)d * QL_ + s0 + tx] =
            __float2half_rn(tile[tx][ty + i * 8]);
    }
}

// ===========================================================================
// mma.sync fp16 2-pass GEMM:  C = A @ B^T, A = Ahi + Alo (fp16), B fp16.
// CTA 128x128, 8 warps (2x4), warp 64x32, m16n8k16, K-chunks of 64, 2-stage.
// SMEM: per stage {Ahi, Alo, B} tiles 128x64 half, 144B row stride.
// ===========================================================================
#define TILE_B   18432                       // 128 rows * 144 B
#define STAGE_B  (3 * TILE_B)                // 55296
#define MMA_SMEM_BYTES (2 * STAGE_B)         // 110592

template<int MODE>
__global__ void __launch_bounds__(256)
mma_gemm(const __half* __restrict__ Ahi, const __half* __restrict__ Alo,
         const __half* __restrict__ Bh,
         float* __restrict__ C0, float* __restrict__ C1, float* __restrict__ C2,
         int M, int N, int K)
{
    extern __shared__ char smc[];
    const uint32_t sbase = smem_u32(smc);
    const int tid  = threadIdx.x;
    const int wid  = tid >> 5;
    const int lane = tid & 31;
    const int bx   = blockIdx.x;
    const int by   = blockIdx.y;
    const int wm   = wid >> 2;
    const int wn   = wid & 3;

    float acc[4][4][4];
#pragma unroll
    for (int mt = 0; mt < 4; mt++)
#pragma unroll
        for (int nt = 0; nt < 4; nt++)
#pragma unroll
            for (int r = 0; r < 4; r++) acc[mt][nt][r] = 0.f;

    const int NC = K >> 6;

    auto load_chunk = [&](int ci, int s) {
        const int k0 = ci * 64;
        const uint32_t sb = sbase + s * STAGE_B;
#pragma unroll
        for (int it = 0; it < 4; it++) {
            int f = tid + it * 256;          // 0..1023
            int r = f >> 3, seg = f & 7;
            uint32_t dst = sb + r * 144 + seg * 16;
            size_t ga = (size_t)(by * 128 + r) * K + k0 + seg * 8;
            size_t gb = (size_t)(bx * 128 + r) * K + k0 + seg * 8;
            cp_async16(dst,              Ahi + ga);
            cp_async16(dst + TILE_B,     Alo + ga);
            cp_async16(dst + 2 * TILE_B, Bh + gb);
        }
        CP_COMMIT();
    };

    load_chunk(0, 0);

    const int ar   = lane & 15;
    const int acol = (lane >> 4) * 8;
    const int br   = lane & 7;
    const int bcol = ((lane >> 3) & 1) * 8;

    for (int ci = 0; ci < NC; ci++) {
        const int s = ci & 1;
        if (ci + 1 < NC) { load_chunk(ci + 1, s ^ 1); CP_WAIT(1); }
        else             { CP_WAIT(0); }
        __syncthreads();

        const uint32_t sb    = sbase + s * STAGE_B;
        const uint32_t aBase = sb + wm * 64 * 144;
        const uint32_t bBase = sb + 2 * TILE_B + wn * 32 * 144;

#pragma unroll
        for (int ks = 0; ks < 4; ks++) {
            const int kc = ks * 16;
            uint32_t ahi[4][4], alo[4][4], bh[4][2];
#pragma unroll
            for (int mt = 0; mt < 4; mt++) {
                uint32_t a = aBase + (mt * 16 + ar) * 144 + (kc + acol) * 2;
                ldmat_x4(ahi[mt], a);
                ldmat_x4(alo[mt], a + TILE_B);
            }
#pragma unroll
            for (int nt = 0; nt < 4; nt++) {
                uint32_t b = bBase + (nt * 8 + br) * 144 + (kc + bcol) * 2;
                ldmat_x2(bh[nt], b);
            }
#pragma unroll
            for (int mt = 0; mt < 4; mt++)
#pragma unroll
                for (int nt = 0; nt < 4; nt++)
                    mma_f16(acc[mt][nt], ahi[mt], bh[nt]);
#pragma unroll
            for (int mt = 0; mt < 4; mt++)
#pragma unroll
                for (int nt = 0; nt < 4; nt++)
                    mma_f16(acc[mt][nt], alo[mt], bh[nt]);
        }
        __syncthreads();
    }

    const int lrow = lane >> 2;
    const int lcol = (lane & 3) * 2;
#pragma unroll
    for (int mt = 0; mt < 4; mt++) {
#pragma unroll
        for (int nt = 0; nt < 4; nt++) {
            int row0 = by * 128 + wm * 64 + mt * 16 + lrow;
            int col  = bx * 128 + wn * 32 + nt * 8 + lcol;
#pragma unroll
            for (int half = 0; half < 2; half++) {
                int m = row0 + half * 8;
                float2 v = make_float2(acc[mt][nt][half * 2],
                                       acc[mt][nt][half * 2 + 1]);
                if (MODE == 0) {
                    *(float2*)&C0[(size_t)m * N + col] = v;
                } else {
                    int b = m >> 11, t = m & 2047, dd = col & 63;
                    if (col < 2048) {
                        int h = col >> 6;
                        *(float2*)&C0[((((size_t)b * NH_ + h) * QL_ + t) << 6) + dd] = v;
                    } else if (col < 2560) {
                        int h = (col - 2048) >> 6;
                        *(float2*)&C1[((((size_t)b * KVH_ + h) * QL_ + t) << 6) + dd] = v;
                    } else {
                        int h = (col - 2560) >> 6;
                        *(float2*)&C2[((((size_t)b * KVH_ + h) * QL_ + t) << 6) + dd] = v;
                    }
                }
            }
        }
    }
}

// ===========================================================================
// RoPE (fp64 trig once — --use_fast_math breaks sincosf at ~2000 rad)
// ===========================================================================
__global__ void rope_table_kernel(float* __restrict__ ct, float* __restrict__ st,
                                  int Q)
{
    int idx = blockIdx.x * blockDim.x + threadIdx.x;
    if (idx >= Q * 32) return;
    int j = idx & 31;
    int t = idx >> 5;
    float freq = (float)(1.0 / pow(10000.0, (double)(2 * j) / 64.0));
    float ang  = (float)t * freq;
    double cd, sd;
    sincos((double)ang, &sd, &cd);
    ct[idx] = (float)cd;
    st[idx] = (float)sd;
}

// RoPE apply for Q: emits fp16 hi/lo split (A operand of S)
__global__ void rope_apply_q(const float* __restrict__ buf,
                             const float* __restrict__ ct,
                             const float* __restrict__ st,
                             __half* __restrict__ oh, __half* __restrict__ ol,
                             int Q, int total)
{
    int idx = blockIdx.x * blockDim.x + threadIdx.x;
    if (idx >= total) return;
    int j  = idx & 31;
    int t  = (idx >> 5) % Q;
    int bh = idx / (32 * Q);
    size_t base = ((size_t)bh * Q + t) * 64;

    float c = ct[(t << 5) + j];
    float s = st[(t << 5) + j];
    float x1 = buf[base + j];
    float x2 = buf[base + j + 32];
    float r1 = x1 * c - x2 * s;
    float r2 = x2 * c + x1 * s;
    __half h1 = __float2half_rn(r1);
    __half h2 = __float2half_rn(r2);
    oh[base + j]      = h1;
    oh[base + j + 32] = h2;
    ol[base + j]      = __float2half_rn(r1 - __half2float(h1));
    ol[base + j + 32] = __float2half_rn(r2 - __half2float(h2));
}

// RoPE apply for K: emits single rounded fp16 (B operand of S)
__global__ void rope_apply_k(const float* __restrict__ buf,
                             const float* __restrict__ ct,
                             const float* __restrict__ st,
                             __half* __restrict__ oh,
                             int Q, int total)
{
    int idx = blockIdx.x * blockDim.x + threadIdx.x;
    if (idx >= total) return;
    int j  = idx & 31;
    int t  = (idx >> 5) % Q;
    int bh = idx / (32 * Q);
    size_t base = ((size_t)bh * Q + t) * 64;

    float c = ct[(t << 5) + j];
    float s = st[(t << 5) + j];
    float x1 = buf[base + j];
    float x2 = buf[base + j + 32];
    oh[base + j]      = __float2half_rn(x1 * c - x2 * s);
    oh[base + j + 32] = __float2half_rn(x2 * c + x1 * s);
}

// ===========================================================================
// Flash attention, fp16 2-pass. Grid (QL/128, NH, B), 256 thr, 8 warps.
// Q split hi/lo (A side); K, V single fp16 (B side).
// SMEM: 2 stages x {K,V}[64][72h] + Q hi/lo [128][72h] = 73728 B -> 2 CTA/SM.
// ===========================================================================
#define AT_KTILE 9216                  // 64 rows * 144 B
#define AT_STAGE (2 * AT_KTILE)        // 18432
#define AT_Q_OFF (2 * AT_STAGE)        // 36864
#define AT_SMEM  (AT_Q_OFF + 2 * 128 * 144)   // 73728

__global__ void __launch_bounds__(256, 2)
attn_mma(const __half* __restrict__ Qh, const __half* __restrict__ Ql,
         const __half* __restrict__ Kh, const __half* __restrict__ Vt,
         __half* __restrict__ Ohi, __half* __restrict__ Olo)
{
    extern __shared__ char smc[];
    const uint32_t sbase = smem_u32(smc);
    const int tid  = threadIdx.x;
    const int wid  = tid >> 5;
    const int lane = tid & 31;
    const int qt   = blockIdx.x;
    const int h    = blockIdx.y;
    const int b    = blockIdx.z;
    const int kvh  = h >> 2;           // NH/KVH = 4
    const int q0   = qt * 128;

    const __half* Qgh = Qh + (((size_t)b * NH_ + h) * QL_ + q0) * 64;
    const __half* Qgl = Ql + (((size_t)b * NH_ + h) * QL_ + q0) * 64;
    const __half* Kg  = Kh + (((size_t)b * KVH_ + kvh) * QL_) * 64;
    const __half* Vg  = Vt + (((size_t)b * KVH_ + kvh) * 64) * QL_;

    // Q loads (commit group 0)
#pragma unroll
    for (int it = 0; it < 4; it++) {
        int f = tid + it * 256;
        int r = f >> 3, seg = f & 7;
        uint32_t dst = sbase + AT_Q_OFF + r * 144 + seg * 16;
        cp_async16(dst,             Qgh + (size_t)r * 64 + seg * 8);
        cp_async16(dst + 128 * 144, Qgl + (size_t)r * 64 + seg * 8);
    }
    CP_COMMIT();

    auto load_kv = [&](int kt, int s) {
        const int k0 = kt * 64;
        const uint32_t sb = sbase + s * AT_STAGE;
#pragma unroll
        for (int it = 0; it < 2; it++) {
            int f = tid + it * 256;
            int r = f >> 3, seg = f & 7;
            uint32_t dst = sb + r * 144 + seg * 16;
            cp_async16(dst,            Kg + (size_t)(k0 + r) * 64 + seg * 8);
            cp_async16(dst + AT_KTILE, Vg + (size_t)r * QL_ + k0 + seg * 8);
        }
        CP_COMMIT();
    };

    load_kv(0, 0);

    CP_WAIT(1);
    __syncthreads();

    const int ar   = lane & 15;
    const int acol = (lane >> 4) * 8;
    const int br   = lane & 7;
    const int bcol = ((lane >> 3) & 1) * 8;

    uint32_t qfh[4][4], qfl[4][4];
    {
        uint32_t qBase = sbase + AT_Q_OFF + (wid * 16 + ar) * 144;
#pragma unroll
        for (int ks = 0; ks < 4; ks++) {
            uint32_t a = qBase + (ks * 16 + acol) * 2;
            ldmat_x4(qfh[ks], a);
            ldmat_x4(qfl[ks], a + 128 * 144);
        }
    }

    float o[8][4];
#pragma unroll
    for (int nt = 0; nt < 8; nt++)
#pragma unroll
        for (int j = 0; j < 4; j++) o[nt][j] = 0.f;
    float m0 = -1e30f, m1 = -1e30f, l0 = 0.f, l1 = 0.f;

    const int ktiles = qt * 2 + 2;
    const int qg0 = q0 + wid * 16 + (lane >> 2);
    const int qg1 = qg0 + 8;
    const int lc2 = (lane & 3) * 2;

    for (int kt = 0; kt < ktiles; kt++) {
        const int s = kt & 1;
        if (kt + 1 < ktiles) { load_kv(kt + 1, s ^ 1); CP_WAIT(1); }
        else                 { CP_WAIT(0); }
        __syncthreads();

        const uint32_t kb = sbase + s * AT_STAGE;
        const uint32_t vb = kb + AT_KTILE;
        const int k0 = kt * 64;

        // ---- S = Q K^T (2 passes: Qhi*K + Qlo*K) ----
        float sf[8][4];
#pragma unroll
        for (int nt = 0; nt < 8; nt++)
#pragma unroll
            for (int j = 0; j < 4; j++) sf[nt][j] = 0.f;

#pragma unroll
        for (int ks = 0; ks < 4; ks++) {
            uint32_t bh[8][2];
#pragma unroll
            for (int nt = 0; nt < 8; nt++) {
                uint32_t a = kb + (nt * 8 + br) * 144 + (ks * 16 + bcol) * 2;
                ldmat_x2(bh[nt], a);
            }
#pragma unroll
            for (int nt = 0; nt < 8; nt++) mma_f16(sf[nt], qfh[ks], bh[nt]);
#pragma unroll
            for (int nt = 0; nt < 8; nt++) mma_f16(sf[nt], qfl[ks], bh[nt]);
        }

        // ---- scale + causal mask + row max ----
        const bool domask = (kt >= ktiles - 2);
        float rm0 = -1e30f, rm1 = -1e30f;
#pragma unroll
        for (int nt = 0; nt < 8; nt++) {
            int kg = k0 + nt * 8 + lc2;
#pragma unroll
            for (int j = 0; j < 4; j++) {
                float v = sf[nt][j] * 0.125f;
                if (domask) {
                    int kcol = kg + (j & 1);
                    int qrow = (j < 2) ? qg0 : qg1;
                    if (kcol > qrow) v = -1e30f;
                }
                sf[nt][j] = v;
                if (j < 2) rm0 = fmaxf(rm0, v); else rm1 = fmaxf(rm1, v);
            }
        }
        rm0 = fmaxf(rm0, __shfl_xor_sync(0xffffffffu, rm0, 1));
        rm0 = fmaxf(rm0, __shfl_xor_sync(0xffffffffu, rm0, 2));
        rm1 = fmaxf(rm1, __shfl_xor_sync(0xffffffffu, rm1, 1));
        rm1 = fmaxf(rm1, __shfl_xor_sync(0xffffffffu, rm1, 2));

        float nm0 = fmaxf(m0, rm0), nm1 = fmaxf(m1, rm1);
        float c0 = __expf(m0 - nm0), c1 = __expf(m1 - nm1);

        // ---- exp + row sum + pack P to fp16 hi/lo A-fragments ----
        float rs0 = 0.f, rs1 = 0.f;
        uint32_t ph[8][2], pl[8][2];
#pragma unroll
        for (int nt = 0; nt < 8; nt++) {
            float p0 = __expf(sf[nt][0] - nm0);
            float p1 = __expf(sf[nt][1] - nm0);
            float p2 = __expf(sf[nt][2] - nm1);
            float p3 = __expf(sf[nt][3] - nm1);
            rs0 += p0 + p1;
            rs1 += p2 + p3;
            __half2 h01 = __floats2half2_rn(p0, p1);
            __half2 h23 = __floats2half2_rn(p2, p3);
            ph[nt][0] = *(uint32_t*)&h01;
            ph[nt][1] = *(uint32_t*)&h23;
            __half2 l01 = __floats2half2_rn(
                p0 - __half2float(h01.x), p1 - __half2float(h01.y));
            __half2 l23 = __floats2half2_rn(
                p2 - __half2float(h23.x), p3 - __half2float(h23.y));
            pl[nt][0] = *(uint32_t*)&l01;
            pl[nt][1] = *(uint32_t*)&l23;
        }
        rs0 += __shfl_xor_sync(0xffffffffu, rs0, 1);
        rs0 += __shfl_xor_sync(0xffffffffu, rs0, 2);
        rs1 += __shfl_xor_sync(0xffffffffu, rs1, 1);
        rs1 += __shfl_xor_sync(0xffffffffu, rs1, 2);

        l0 = l0 * c0 + rs0;
        l1 = l1 * c1 + rs1;
        m0 = nm0;
        m1 = nm1;

#pragma unroll
        for (int nt = 0; nt < 8; nt++) {
            o[nt][0] *= c0; o[nt][1] *= c0;
            o[nt][2] *= c1; o[nt][3] *= c1;
        }

        // ---- O += P V (2 passes: Phi*V + Plo*V) ----
#pragma unroll
        for (int ks = 0; ks < 4; ks++) {
            uint32_t bh[8][2];
#pragma unroll
            for (int nt = 0; nt < 8; nt++) {
                uint32_t a = vb + (nt * 8 + br) * 144 + (ks * 16 + bcol) * 2;
                ldmat_x2(bh[nt], a);
            }
            uint32_t pah[4] = {ph[2 * ks][0], ph[2 * ks][1],
                               ph[2 * ks + 1][0], ph[2 * ks + 1][1]};
            uint32_t pal[4] = {pl[2 * ks][0], pl[2 * ks][1],
                               pl[2 * ks + 1][0], pl[2 * ks + 1][1]};
#pragma unroll
            for (int nt = 0; nt < 8; nt++) mma_f16(o[nt], pah, bh[nt]);
#pragma unroll
            for (int nt = 0; nt < 8; nt++) mma_f16(o[nt], pal, bh[nt]);
        }
        __syncthreads();
    }

    // ---- epilogue: O/l -> fp16 hi/lo split, [b*Q + q, h*64 + d] ----
    float inv0 = 1.0f / l0, inv1 = 1.0f / l1;
    int gr0 = b * QL_ + q0 + wid * 16 + (lane >> 2);
    int gr1 = gr0 + 8;
#pragma unroll
    for (int nt = 0; nt < 8; nt++) {
        int gc = h * 64 + nt * 8 + lc2;
        float v0 = o[nt][0] * inv0, v1 = o[nt][1] * inv0;
        float v2 = o[nt][2] * inv1, v3 = o[nt][3] * inv1;
        __half2 h01 = __floats2half2_rn(v0, v1);
        __half2 h23 = __floats2half2_rn(v2, v3);
        size_t o0 = (size_t)gr0 * HID_ + gc;
        size_t o1 = (size_t)gr1 * HID_ + gc;
        *(__half2*)&Ohi[o0] = h01;
        *(__half2*)&Ohi[o1] = h23;
        __half2 l01 = __floats2half2_rn(
            v0 - __half2float(h01.x), v1 - __half2float(h01.y));
        __half2 l23 = __floats2half2_rn(
            v2 - __half2float(h23.x), v3 - __half2float(h23.y));
        *(__half2*)&Olo[o0] = l01;
        *(__half2*)&Olo[o1] = l23;
    }
}

// ===========================================================================
extern "C" void kernel_launch(void* const* d_in, const int* in_sizes, int n_in,
                              void* d_out, int out_size)
{
    const float* X  = (const float*)d_in[0];
    const float* Wq = (const float*)d_in[2];
    const float* Wk = (const float*)d_in[3];
    const float* Wv = (const float*)d_in[4];
    const float* Wo = (const float*)d_in[5];
    float* out = (float*)d_out;

    float *qp, *kp, *vp, *cp, *sp;
    __half *xhi, *xlo, *wp, *wop, *ahi, *alo, *qbh, *qbl, *kb, *vt;
    cudaGetSymbolAddress((void**)&qp, g_Q);
    cudaGetSymbolAddress((void**)&kp, g_K);
    cudaGetSymbolAddress((void**)&vp, g_V);
    cudaGetSymbolAddress((void**)&cp, g_cos);
    cudaGetSymbolAddress((void**)&sp, g_sin);
    cudaGetSymbolAddress((void**)&xhi, g_Xhi);
    cudaGetSymbolAddress((void**)&xlo, g_Xlo);
    cudaGetSymbolAddress((void**)&wp,  g_W);
    cudaGetSymbolAddress((void**)&wop, g_Wo);
    cudaGetSymbolAddress((void**)&ahi, g_Ahi);
    cudaGetSymbolAddress((void**)&alo, g_Alo);
    cudaGetSymbolAddress((void**)&qbh, g_Qbh);
    cudaGetSymbolAddress((void**)&qbl, g_Qbl);
    cudaGetSymbolAddress((void**)&kb,  g_Kb);
    cudaGetSymbolAddress((void**)&vt,  g_Vt);

    const int M = B_ * QL_;   // 4096

    cudaFuncSetAttribute(mma_gemm<0>, cudaFuncAttributeMaxDynamicSharedMemorySize, MMA_SMEM_BYTES);
    cudaFuncSetAttribute(mma_gemm<1>, cudaFuncAttributeMaxDynamicSharedMemorySize, MMA_SMEM_BYTES);
    cudaFuncSetAttribute(attn_mma, cudaFuncAttributeMaxDynamicSharedMemorySize, AT_SMEM);

    // Launches 1..5 (ncu -s 5 -c 1 profiles the QKV GEMM at #6)
    rope_table_kernel<<<(QL_ * 32 + 255) / 256, 256>>>(cp, sp, QL_);
    split_kernel<<<(M * HID_ + 255) / 256, 256>>>(X, xhi, xlo, M * HID_);
    transpose_half_kernel<<<dim3(2048 / 32, HID_ / 32), dim3(32, 8)>>>(Wq, wp, HID_, 2048, 0);
    transpose_half_kernel<<<dim3(512 / 32,  HID_ / 32), dim3(32, 8)>>>(Wk, wp, HID_, 512, 2048);
    transpose_half_kernel<<<dim3(512 / 32,  HID_ / 32), dim3(32, 8)>>>(Wv, wp, HID_, 512, 2560);

    // #6: fused QKV projection on tensor cores (scatter to head layouts, fp32)
    mma_gemm<1><<<dim3(3072 / 128, M / 128), 256, MMA_SMEM_BYTES>>>(
        xhi, xlo, wp, qp, kp, vp, M, 3072, HID_);

    // RoPE -> Q split / K single ; V^T ; Wo transpose
    {
        int totq = B_ * NH_  * QL_ * 32;
        int totk = B_ * KVH_ * QL_ * 32;
        rope_apply_q<<<(totq + 255) / 256, 256>>>(qp, cp, sp, qbh, qbl, QL_, totq);
        rope_apply_k<<<(totk + 255) / 256, 256>>>(kp, cp, sp, kb, QL_, totk);
        vtrans_half_kernel<<<dim3(QL_ / 32, 2, B_ * KVH_), dim3(32, 8)>>>(vp, vt);
        transpose_half_kernel<<<dim3(2048 / 32, HID_ / 32), dim3(32, 8)>>>(Wo, wop, HID_, 2048, 0);
    }

    // Attention on tensor cores, emits fp16 hi/lo split output
    attn_mma<<<dim3(QL_ / 128, NH_, B_), 256, AT_SMEM>>>(
        qbh, qbl, kb, vt, ahi, alo);

    // Output projection on tensor cores
    mma_gemm<0><<<dim3(HID_ / 128, M / 128), 256, MMA_SMEM_BYTES>>>(
        ahi, alo, wop, out, nullptr, nullptr, M, HID_, HID_);
}

// round 13
// speedup vs baseline: 1.6925x; 1.0002x over previous
#include <cuda_runtime.h>
#include <cuda_fp16.h>
#include <math.h>
#include <stdint.h>

// Problem constants
#define B_   2
#define QL_  2048
#define HID_ 2048
#define NH_  32
#define KVH_ 8
#define D_   64

// ===========================================================================
// PTX helpers — BASE PTX ONLY (harness targets plain sm_103: no tcgen05!)
// ===========================================================================
__device__ __forceinline__ uint32_t smem_u32(const void* p) {
    uint32_t a;
    asm("{ .reg .u64 t; cvta.to.shared.u64 t, %1; cvt.u32.u64 %0, t; }"
        : "=r"(a) : "l"(p));
    return a;
}
__device__ __forceinline__ void ldmat_x4(uint32_t* r, uint32_t addr) {
    asm volatile("ldmatrix.sync.aligned.m8n8.x4.shared.b16 {%0,%1,%2,%3}, [%4];"
                 : "=r"(r[0]), "=r"(r[1]), "=r"(r[2]), "=r"(r[3]) : "r"(addr));
}
__device__ __forceinline__ void ldmat_x2(uint32_t* r, uint32_t addr) {
    asm volatile("ldmatrix.sync.aligned.m8n8.x2.shared.b16 {%0,%1}, [%2];"
                 : "=r"(r[0]), "=r"(r[1]) : "r"(addr));
}
// fp16 MMA: D(f32) += A(f16) * B(f16)
__device__ __forceinline__ void mma_f16(float* d, const uint32_t* a, const uint32_t* b) {
    asm volatile("mma.sync.aligned.m16n8k16.row.col.f32.f16.f16.f32 "
                 "{%0,%1,%2,%3}, {%4,%5,%6,%7}, {%8,%9}, {%0,%1,%2,%3};"
                 : "+f"(d[0]), "+f"(d[1]), "+f"(d[2]), "+f"(d[3])
                 : "r"(a[0]), "r"(a[1]), "r"(a[2]), "r"(a[3]),
                   "r"(b[0]), "r"(b[1]));
}
__device__ __forceinline__ void cp_async16(uint32_t dst, const void* src) {
    asm volatile("cp.async.cg.shared.global [%0], [%1], 16;"
                 :: "r"(dst), "l"(src));
}
#define CP_COMMIT()  asm volatile("cp.async.commit_group;" ::: "memory")
#define CP_WAIT(n)   asm volatile("cp.async.wait_group %0;" :: "n"(n) : "memory")

// ===========================================================================
// Scratch (device globals — no allocation allowed)
// ===========================================================================
__device__ float g_Q[(size_t)B_ * NH_  * QL_ * D_];   // [b,h,q,d] fp32
__device__ float g_K[(size_t)B_ * KVH_ * QL_ * D_];
__device__ float g_V[(size_t)B_ * KVH_ * QL_ * D_];
__device__ float g_cos[QL_ * 32];
__device__ float g_sin[QL_ * 32];
// fp16 operands (A-side split hi/lo, B-side single rounded)
__device__ __half g_Xhi[(size_t)B_ * QL_ * HID_];     // X split (A of QKV gemm)
__device__ __half g_Xlo[(size_t)B_ * QL_ * HID_];
__device__ __half g_W  [(size_t)3072 * HID_];         // Wq|Wk|Wv transposed [N,K] single
__device__ __half g_Wo [(size_t)HID_ * HID_];         // Wo transposed [N,K] single
__device__ __half g_Ahi[(size_t)B_ * QL_ * HID_];     // attn out split (A of Wo gemm)
__device__ __half g_Alo[(size_t)B_ * QL_ * HID_];
__device__ __half g_Qbh[(size_t)B_ * NH_  * QL_ * D_]; // roped Q split (A of S)
__device__ __half g_Qbl[(size_t)B_ * NH_  * QL_ * D_];
__device__ __half g_Kb [(size_t)B_ * KVH_ * QL_ * D_]; // roped K single (B of S)
__device__ __half g_Vt [(size_t)B_ * KVH_ * D_ * QL_]; // V^T single (B of PV)

// ===========================================================================
// fp32 -> (fp16 hi, fp16 lo) split
// ===========================================================================
__global__ void split_kernel(const float* __restrict__ src,
                             __half* __restrict__ hi,
                             __half* __restrict__ lo, int n)
{
    int i = blockIdx.x * blockDim.x + threadIdx.x;
    if (i >= n) return;
    float v = src[i];
    __half h = __float2half_rn(v);
    hi[i] = h;
    lo[i] = __float2half_rn(v - __half2float(h));
}

// Transpose + round: W[K, Ncols] -> T[(rowOffset+n), k] fp16, ldT = K.
__global__ void transpose_half_kernel(const float* __restrict__ W,
                                      __half* __restrict__ T,
                                      int K, int Ncols, int rowOffset)
{
    __shared__ float tile[32][33];
    int k0 = blockIdx.y * 32, n0 = blockIdx.x * 32;
    int tx = threadIdx.x, ty = threadIdx.y;    // (32, 8)
#pragma unroll
    for (int i = 0; i < 4; i++) {
        int k = k0 + ty + i * 8;
        tile[ty + i * 8][tx] = W[(size_t)k * Ncols + n0 + tx];
    }
    __syncthreads();
#pragma unroll
    for (int i = 0; i < 4; i++) {
        int n = n0 + ty + i * 8;
        T[(size_t)(rowOffset + n) * K + k0 + tx] = __float2half_rn(tile[tx][ty + i * 8]);
    }
}

// V transpose: g_V [bk, seq, 64] fp32 -> Vt [bk, 64, 2048] fp16 single
__global__ void vtrans_half_kernel(const float* __restrict__ V,
                                   __half* __restrict__ T)
{
    __shared__ float tile[32][33];
    int bk = blockIdx.z;
    int s0 = blockIdx.x * 32, d0 = blockIdx.y * 32;
    int tx = threadIdx.x, ty = threadIdx.y;
    const float* Vb = V + (size_t)bk * QL_ * 64;
#pragma unroll
    for (int i = 0; i < 4; i++) {
        int s = s0 + ty + i * 8;
        tile[ty + i * 8][tx] = Vb[(size_t)s * 64 + d0 + tx];
    }
    __syncthreads();
#pragma unroll
    for (int i = 0; i < 4; i++) {
        int d = d0 + ty + i * 8;
        T[(size_t)bk * 64 * QL_ + (size_t)d * QL_ + s0 + tx] =
            __float2half_rn(tile[tx][ty + i * 8]);
    }
}

// ===========================================================================
// mma.sync fp16 2-pass GEMM:  C = A @ B^T, A = Ahi + Alo (fp16), B fp16.
// CTA tile 128x256, 8 warps (2x4), warp tile 64x64, m16n8k16.
// K-chunks of 64, 3-stage cp.async pipeline.
// SMEM per stage: Ahi(128x72h) + Alo(128x72h) + B(256x72h) = 73728 B.
// ===========================================================================
#define TILE_A   18432                       // 128 rows * 144 B
#define TILE_BB  36864                       // 256 rows * 144 B
#define STAGE_B  (2 * TILE_A + TILE_BB)      // 73728
#define MMA_SMEM_BYTES (3 * STAGE_B)         // 221184

template<int MODE>
__global__ void __launch_bounds__(256)
mma_gemm(const __half* __restrict__ Ahi, const __half* __restrict__ Alo,
         const __half* __restrict__ Bh,
         float* __restrict__ C0, float* __restrict__ C1, float* __restrict__ C2,
         int M, int N, int K)
{
    extern __shared__ char smc[];
    const uint32_t sbase = smem_u32(smc);
    const int tid  = threadIdx.x;
    const int wid  = tid >> 5;
    const int lane = tid & 31;
    const int bx   = blockIdx.x;   // 256-col N tile
    const int by   = blockIdx.y;   // 128-row M tile
    const int wm   = wid >> 2;     // 0..1
    const int wn   = wid & 3;      // 0..3

    float acc[4][8][4];
#pragma unroll
    for (int mt = 0; mt < 4; mt++)
#pragma unroll
        for (int nt = 0; nt < 8; nt++)
#pragma unroll
            for (int r = 0; r < 4; r++) acc[mt][nt][r] = 0.f;

    const int NC = K >> 6;

    auto load_chunk = [&](int ci, int s) {
        const int k0 = ci * 64;
        const uint32_t sb = sbase + s * STAGE_B;
        // A hi/lo: 128 rows x 8 segs
#pragma unroll
        for (int it = 0; it < 4; it++) {
            int f = tid + it * 256;          // 0..1023
            int r = f >> 3, seg = f & 7;
            uint32_t dst = sb + r * 144 + seg * 16;
            size_t ga = (size_t)(by * 128 + r) * K + k0 + seg * 8;
            cp_async16(dst,          Ahi + ga);
            cp_async16(dst + TILE_A, Alo + ga);
        }
        // B: 256 rows x 8 segs
#pragma unroll
        for (int it = 0; it < 8; it++) {
            int f = tid + it * 256;          // 0..2047
            int r = f >> 3, seg = f & 7;
            uint32_t dst = sb + 2 * TILE_A + r * 144 + seg * 16;
            size_t gb = (size_t)(bx * 256 + r) * K + k0 + seg * 8;
            cp_async16(dst, Bh + gb);
        }
        CP_COMMIT();
    };

    load_chunk(0, 0);
    if (NC > 1) load_chunk(1, 1);

    const int ar   = lane & 15;
    const int acol = (lane >> 4) * 8;
    const int br   = lane & 7;
    const int bcol = ((lane >> 3) & 1) * 8;

    for (int ci = 0; ci < NC; ci++) {
        const int s = ci % 3;
        if (ci + 2 < NC) { load_chunk(ci + 2, (ci + 2) % 3); CP_WAIT(2); }
        else if (ci + 1 < NC) { CP_WAIT(1); }
        else { CP_WAIT(0); }
        __syncthreads();

        const uint32_t sb    = sbase + s * STAGE_B;
        const uint32_t aBase = sb + wm * 64 * 144;
        const uint32_t bBase = sb + 2 * TILE_A + wn * 64 * 144;

#pragma unroll
        for (int ks = 0; ks < 4; ks++) {
            const int kc = ks * 16;
            uint32_t ahi[4][4], alo[4][4], bh[8][2];
#pragma unroll
            for (int mt = 0; mt < 4; mt++) {
                uint32_t a = aBase + (mt * 16 + ar) * 144 + (kc + acol) * 2;
                ldmat_x4(ahi[mt], a);
                ldmat_x4(alo[mt], a + TILE_A);
            }
#pragma unroll
            for (int nt = 0; nt < 8; nt++) {
                uint32_t b = bBase + (nt * 8 + br) * 144 + (kc + bcol) * 2;
                ldmat_x2(bh[nt], b);
            }
#pragma unroll
            for (int mt = 0; mt < 4; mt++)
#pragma unroll
                for (int nt = 0; nt < 8; nt++)
                    mma_f16(acc[mt][nt], ahi[mt], bh[nt]);
#pragma unroll
            for (int mt = 0; mt < 4; mt++)
#pragma unroll
                for (int nt = 0; nt < 8; nt++)
                    mma_f16(acc[mt][nt], alo[mt], bh[nt]);
        }
        __syncthreads();
    }

    const int lrow = lane >> 2;
    const int lcol = (lane & 3) * 2;
#pragma unroll
    for (int mt = 0; mt < 4; mt++) {
#pragma unroll
        for (int nt = 0; nt < 8; nt++) {
            int row0 = by * 128 + wm * 64 + mt * 16 + lrow;
            int col  = bx * 256 + wn * 64 + nt * 8 + lcol;
#pragma unroll
            for (int half = 0; half < 2; half++) {
                int m = row0 + half * 8;
                float2 v = make_float2(acc[mt][nt][half * 2],
                                       acc[mt][nt][half * 2 + 1]);
                if (MODE == 0) {
                    *(float2*)&C0[(size_t)m * N + col] = v;
                } else {
                    int b = m >> 11, t = m & 2047, dd = col & 63;
                    if (col < 2048) {
                        int h = col >> 6;
                        *(float2*)&C0[((((size_t)b * NH_ + h) * QL_ + t) << 6) + dd] = v;
                    } else if (col < 2560) {
                        int h = (col - 2048) >> 6;
                        *(float2*)&C1[((((size_t)b * KVH_ + h) * QL_ + t) << 6) + dd] = v;
                    } else {
                        int h = (col - 2560) >> 6;
                        *(float2*)&C2[((((size_t)b * KVH_ + h) * QL_ + t) << 6) + dd] = v;
                    }
                }
            }
        }
    }
}

// ===========================================================================
// RoPE (fp64 trig once — --use_fast_math breaks sincosf at ~2000 rad)
// ===========================================================================
__global__ void rope_table_kernel(float* __restrict__ ct, float* __restrict__ st,
                                  int Q)
{
    int idx = blockIdx.x * blockDim.x + threadIdx.x;
    if (idx >= Q * 32) return;
    int j = idx & 31;
    int t = idx >> 5;
    float freq = (float)(1.0 / pow(10000.0, (double)(2 * j) / 64.0));
    float ang  = (float)t * freq;
    double cd, sd;
    sincos((double)ang, &sd, &cd);
    ct[idx] = (float)cd;
    st[idx] = (float)sd;
}

// RoPE apply for Q: emits fp16 hi/lo split (A operand of S)
__global__ void rope_apply_q(const float* __restrict__ buf,
                             const float* __restrict__ ct,
                             const float* __restrict__ st,
                             __half* __restrict__ oh, __half* __restrict__ ol,
                             int Q, int total)
{
    int idx = blockIdx.x * blockDim.x + threadIdx.x;
    if (idx >= total) return;
    int j  = idx & 31;
    int t  = (idx >> 5) % Q;
    int bh = idx / (32 * Q);
    size_t base = ((size_t)bh * Q + t) * 64;

    float c = ct[(t << 5) + j];
    float s = st[(t << 5) + j];
    float x1 = buf[base + j];
    float x2 = buf[base + j + 32];
    float r1 = x1 * c - x2 * s;
    float r2 = x2 * c + x1 * s;
    __half h1 = __float2half_rn(r1);
    __half h2 = __float2half_rn(r2);
    oh[base + j]      = h1;
    oh[base + j + 32] = h2;
    ol[base + j]      = __float2half_rn(r1 - __half2float(h1));
    ol[base + j + 32] = __float2half_rn(r2 - __half2float(h2));
}

// RoPE apply for K: emits single rounded fp16 (B operand of S)
__global__ void rope_apply_k(const float* __restrict__ buf,
                             const float* __restrict__ ct,
                             const float* __restrict__ st,
                             __half* __restrict__ oh,
                             int Q, int total)
{
    int idx = blockIdx.x * blockDim.x + threadIdx.x;
    if (idx >= total) return;
    int j  = idx & 31;
    int t  = (idx >> 5) % Q;
    int bh = idx / (32 * Q);
    size_t base = ((size_t)bh * Q + t) * 64;

    float c = ct[(t << 5) + j];
    float s = st[(t << 5) + j];
    float x1 = buf[base + j];
    float x2 = buf[base + j + 32];
    oh[base + j]      = __float2half_rn(x1 * c - x2 * s);
    oh[base + j + 32] = __float2half_rn(x2 * c + x1 * s);
}

// ===========================================================================
// Flash attention, fp16 2-pass (UNCHANGED from passing R12).
// Grid (QL/128, NH, B), 256 thr, 8 warps. Q split hi/lo; K, V single fp16.
// ===========================================================================
#define AT_KTILE 9216                  // 64 rows * 144 B
#define AT_STAGE (2 * AT_KTILE)        // 18432
#define AT_Q_OFF (2 * AT_STAGE)        // 36864
#define AT_SMEM  (AT_Q_OFF + 2 * 128 * 144)   // 73728

__global__ void __launch_bounds__(256, 2)
attn_mma(const __half* __restrict__ Qh, const __half* __restrict__ Ql,
         const __half* __restrict__ Kh, const __half* __restrict__ Vt,
         __half* __restrict__ Ohi, __half* __restrict__ Olo)
{
    extern __shared__ char smc[];
    const uint32_t sbase = smem_u32(smc);
    const int tid  = threadIdx.x;
    const int wid  = tid >> 5;
    const int lane = tid & 31;
    const int qt   = blockIdx.x;
    const int h    = blockIdx.y;
    const int b    = blockIdx.z;
    const int kvh  = h >> 2;           // NH/KVH = 4
    const int q0   = qt * 128;

    const __half* Qgh = Qh + (((size_t)b * NH_ + h) * QL_ + q0) * 64;
    const __half* Qgl = Ql + (((size_t)b * NH_ + h) * QL_ + q0) * 64;
    const __half* Kg  = Kh + (((size_t)b * KVH_ + kvh) * QL_) * 64;
    const __half* Vg  = Vt + (((size_t)b * KVH_ + kvh) * 64) * QL_;

#pragma unroll
    for (int it = 0; it < 4; it++) {
        int f = tid + it * 256;
        int r = f >> 3, seg = f & 7;
        uint32_t dst = sbase + AT_Q_OFF + r * 144 + seg * 16;
        cp_async16(dst,             Qgh + (size_t)r * 64 + seg * 8);
        cp_async16(dst + 128 * 144, Qgl + (size_t)r * 64 + seg * 8);
    }
    CP_COMMIT();

    auto load_kv = [&](int kt, int s) {
        const int k0 = kt * 64;
        const uint32_t sb = sbase + s * AT_STAGE;
#pragma unroll
        for (int it = 0; it < 2; it++) {
            int f = tid + it * 256;
            int r = f >> 3, seg = f & 7;
            uint32_t dst = sb + r * 144 + seg * 16;
            cp_async16(dst,            Kg + (size_t)(k0 + r) * 64 + seg * 8);
            cp_async16(dst + AT_KTILE, Vg + (size_t)r * QL_ + k0 + seg * 8);
        }
        CP_COMMIT();
    };

    load_kv(0, 0);

    CP_WAIT(1);
    __syncthreads();

    const int ar   = lane & 15;
    const int acol = (lane >> 4) * 8;
    const int br   = lane & 7;
    const int bcol = ((lane >> 3) & 1) * 8;

    uint32_t qfh[4][4], qfl[4][4];
    {
        uint32_t qBase = sbase + AT_Q_OFF + (wid * 16 + ar) * 144;
#pragma unroll
        for (int ks = 0; ks < 4; ks++) {
            uint32_t a = qBase + (ks * 16 + acol) * 2;
            ldmat_x4(qfh[ks], a);
            ldmat_x4(qfl[ks], a + 128 * 144);
        }
    }

    float o[8][4];
#pragma unroll
    for (int nt = 0; nt < 8; nt++)
#pragma unroll
        for (int j = 0; j < 4; j++) o[nt][j] = 0.f;
    float m0 = -1e30f, m1 = -1e30f, l0 = 0.f, l1 = 0.f;

    const int ktiles = qt * 2 + 2;
    const int qg0 = q0 + wid * 16 + (lane >> 2);
    const int qg1 = qg0 + 8;
    const int lc2 = (lane & 3) * 2;

    for (int kt = 0; kt < ktiles; kt++) {
        const int s = kt & 1;
        if (kt + 1 < ktiles) { load_kv(kt + 1, s ^ 1); CP_WAIT(1); }
        else                 { CP_WAIT(0); }
        __syncthreads();

        const uint32_t kb = sbase + s * AT_STAGE;
        const uint32_t vb = kb + AT_KTILE;
        const int k0 = kt * 64;

        // ---- S = Q K^T (2 passes: Qhi*K + Qlo*K) ----
        float sf[8][4];
#pragma unroll
        for (int nt = 0; nt < 8; nt++)
#pragma unroll
            for (int j = 0; j < 4; j++) sf[nt][j] = 0.f;

#pragma unroll
        for (int ks = 0; ks < 4; ks++) {
            uint32_t bh[8][2];
#pragma unroll
            for (int nt = 0; nt < 8; nt++) {
                uint32_t a = kb + (nt * 8 + br) * 144 + (ks * 16 + bcol) * 2;
                ldmat_x2(bh[nt], a);
            }
#pragma unroll
            for (int nt = 0; nt < 8; nt++) mma_f16(sf[nt], qfh[ks], bh[nt]);
#pragma unroll
            for (int nt = 0; nt < 8; nt++) mma_f16(sf[nt], qfl[ks], bh[nt]);
        }

        // ---- scale + causal mask + row max ----
        const bool domask = (kt >= ktiles - 2);
        float rm0 = -1e30f, rm1 = -1e30f;
#pragma unroll
        for (int nt = 0; nt < 8; nt++) {
            int kg = k0 + nt * 8 + lc2;
#pragma unroll
            for (int j = 0; j < 4; j++) {
                float v = sf[nt][j] * 0.125f;
                if (domask) {
                    int kcol = kg + (j & 1);
                    int qrow = (j < 2) ? qg0 : qg1;
                    if (kcol > qrow) v = -1e30f;
                }
                sf[nt][j] = v;
                if (j < 2) rm0 = fmaxf(rm0, v); else rm1 = fmaxf(rm1, v);
            }
        }
        rm0 = fmaxf(rm0, __shfl_xor_sync(0xffffffffu, rm0, 1));
        rm0 = fmaxf(rm0, __shfl_xor_sync(0xffffffffu, rm0, 2));
        rm1 = fmaxf(rm1, __shfl_xor_sync(0xffffffffu, rm1, 1));
        rm1 = fmaxf(rm1, __shfl_xor_sync(0xffffffffu, rm1, 2));

        float nm0 = fmaxf(m0, rm0), nm1 = fmaxf(m1, rm1);
        float c0 = __expf(m0 - nm0), c1 = __expf(m1 - nm1);

        // ---- exp + row sum + pack P to fp16 hi/lo A-fragments ----
        float rs0 = 0.f, rs1 = 0.f;
        uint32_t ph[8][2], pl[8][2];
#pragma unroll
        for (int nt = 0; nt < 8; nt++) {
            float p0 = __expf(sf[nt][0] - nm0);
            float p1 = __expf(sf[nt][1] - nm0);
            float p2 = __expf(sf[nt][2] - nm1);
            float p3 = __expf(sf[nt][3] - nm1);
            rs0 += p0 + p1;
            rs1 += p2 + p3;
            __half2 h01 = __floats2half2_rn(p0, p1);
            __half2 h23 = __floats2half2_rn(p2, p3);
            ph[nt][0] = *(uint32_t*)&h01;
            ph[nt][1] = *(uint32_t*)&h23;
            __half2 l01 = __floats2half2_rn(
                p0 - __half2float(h01.x), p1 - __half2float(h01.y));
            __half2 l23 = __floats2half2_rn(
                p2 - __half2float(h23.x), p3 - __half2float(h23.y));
            pl[nt][0] = *(uint32_t*)&l01;
            pl[nt][1] = *(uint32_t*)&l23;
        }
        rs0 += __shfl_xor_sync(0xffffffffu, rs0, 1);
        rs0 += __shfl_xor_sync(0xffffffffu, rs0, 2);
        rs1 += __shfl_xor_sync(0xffffffffu, rs1, 1);
        rs1 += __shfl_xor_sync(0xffffffffu, rs1, 2);

        l0 = l0 * c0 + rs0;
        l1 = l1 * c1 + rs1;
        m0 = nm0;
        m1 = nm1;

#pragma unroll
        for (int nt = 0; nt < 8; nt++) {
            o[nt][0] *= c0; o[nt][1] *= c0;
            o[nt][2] *= c1; o[nt][3] *= c1;
        }

        // ---- O += P V (2 passes: Phi*V + Plo*V) ----
#pragma unroll
        for (int ks = 0; ks < 4; ks++) {
            uint32_t bh[8][2];
#pragma unroll
            for (int nt = 0; nt < 8; nt++) {
                uint32_t a = vb + (nt * 8 + br) * 144 + (ks * 16 + bcol) * 2;
                ldmat_x2(bh[nt], a);
            }
            uint32_t pah[4] = {ph[2 * ks][0], ph[2 * ks][1],
                               ph[2 * ks + 1][0], ph[2 * ks + 1][1]};
            uint32_t pal[4] = {pl[2 * ks][0], pl[2 * ks][1],
                               pl[2 * ks + 1][0], pl[2 * ks + 1][1]};
#pragma unroll
            for (int nt = 0; nt < 8; nt++) mma_f16(o[nt], pah, bh[nt]);
#pragma unroll
            for (int nt = 0; nt < 8; nt++) mma_f16(o[nt], pal, bh[nt]);
        }
        __syncthreads();
    }

    // ---- epilogue: O/l -> fp16 hi/lo split, [b*Q + q, h*64 + d] ----
    float inv0 = 1.0f / l0, inv1 = 1.0f / l1;
    int gr0 = b * QL_ + q0 + wid * 16 + (lane >> 2);
    int gr1 = gr0 + 8;
#pragma unroll
    for (int nt = 0; nt < 8; nt++) {
        int gc = h * 64 + nt * 8 + lc2;
        float v0 = o[nt][0] * inv0, v1 = o[nt][1] * inv0;
        float v2 = o[nt][2] * inv1, v3 = o[nt][3] * inv1;
        __half2 h01 = __floats2half2_rn(v0, v1);
        __half2 h23 = __floats2half2_rn(v2, v3);
        size_t o0 = (size_t)gr0 * HID_ + gc;
        size_t o1 = (size_t)gr1 * HID_ + gc;
        *(__half2*)&Ohi[o0] = h01;
        *(__half2*)&Ohi[o1] = h23;
        __half2 l01 = __floats2half2_rn(
            v0 - __half2float(h01.x), v1 - __half2float(h01.y));
        __half2 l23 = __floats2half2_rn(
            v2 - __half2float(h23.x), v3 - __half2float(h23.y));
        *(__half2*)&Olo[o0] = l01;
        *(__half2*)&Olo[o1] = l23;
    }
}

// ===========================================================================
extern "C" void kernel_launch(void* const* d_in, const int* in_sizes, int n_in,
                              void* d_out, int out_size)
{
    const float* X  = (const float*)d_in[0];
    const float* Wq = (const float*)d_in[2];
    const float* Wk = (const float*)d_in[3];
    const float* Wv = (const float*)d_in[4];
    const float* Wo = (const float*)d_in[5];
    float* out = (float*)d_out;

    float *qp, *kp, *vp, *cp, *sp;
    __half *xhi, *xlo, *wp, *wop, *ahi, *alo, *qbh, *qbl, *kb, *vt;
    cudaGetSymbolAddress((void**)&qp, g_Q);
    cudaGetSymbolAddress((void**)&kp, g_K);
    cudaGetSymbolAddress((void**)&vp, g_V);
    cudaGetSymbolAddress((void**)&cp, g_cos);
    cudaGetSymbolAddress((void**)&sp, g_sin);
    cudaGetSymbolAddress((void**)&xhi, g_Xhi);
    cudaGetSymbolAddress((void**)&xlo, g_Xlo);
    cudaGetSymbolAddress((void**)&wp,  g_W);
    cudaGetSymbolAddress((void**)&wop, g_Wo);
    cudaGetSymbolAddress((void**)&ahi, g_Ahi);
    cudaGetSymbolAddress((void**)&alo, g_Alo);
    cudaGetSymbolAddress((void**)&qbh, g_Qbh);
    cudaGetSymbolAddress((void**)&qbl, g_Qbl);
    cudaGetSymbolAddress((void**)&kb,  g_Kb);
    cudaGetSymbolAddress((void**)&vt,  g_Vt);

    const int M = B_ * QL_;   // 4096

    cudaFuncSetAttribute(mma_gemm<0>, cudaFuncAttributeMaxDynamicSharedMemorySize, MMA_SMEM_BYTES);
    cudaFuncSetAttribute(mma_gemm<1>, cudaFuncAttributeMaxDynamicSharedMemorySize, MMA_SMEM_BYTES);
    cudaFuncSetAttribute(attn_mma, cudaFuncAttributeMaxDynamicSharedMemorySize, AT_SMEM);

    // prep
    rope_table_kernel<<<(QL_ * 32 + 255) / 256, 256>>>(cp, sp, QL_);
    split_kernel<<<(M * HID_ + 255) / 256, 256>>>(X, xhi, xlo, M * HID_);
    transpose_half_kernel<<<dim3(2048 / 32, HID_ / 32), dim3(32, 8)>>>(Wq, wp, HID_, 2048, 0);
    transpose_half_kernel<<<dim3(512 / 32,  HID_ / 32), dim3(32, 8)>>>(Wk, wp, HID_, 512, 2048);
    transpose_half_kernel<<<dim3(512 / 32,  HID_ / 32), dim3(32, 8)>>>(Wv, wp, HID_, 512, 2560);

    // fused QKV projection on tensor cores (scatter to head layouts, fp32)
    mma_gemm<1><<<dim3(3072 / 256, M / 128), 256, MMA_SMEM_BYTES>>>(
        xhi, xlo, wp, qp, kp, vp, M, 3072, HID_);

    // RoPE -> Q split / K single ; V^T ; Wo transpose
    {
        int totq = B_ * NH_  * QL_ * 32;
        int totk = B_ * KVH_ * QL_ * 32;
        rope_apply_q<<<(totq + 255) / 256, 256>>>(qp, cp, sp, qbh, qbl, QL_, totq);
        rope_apply_k<<<(totk + 255) / 256, 256>>>(kp, cp, sp, kb, QL_, totk);
        vtrans_half_kernel<<<dim3(QL_ / 32, 2, B_ * KVH_), dim3(32, 8)>>>(vp, vt);
        transpose_half_kernel<<<dim3(2048 / 32, HID_ / 32), dim3(32, 8)>>>(Wo, wop, HID_, 2048, 0);
    }

    // Attention on tensor cores, emits fp16 hi/lo split output
    attn_mma<<<dim3(QL_ / 128, NH_, B_), 256, AT_SMEM>>>(
        qbh, qbl, kb, vt, ahi, alo);

    // Output projection on tensor cores
    mma_gemm<0><<<dim3(HID_ / 256, M / 128), 256, MMA_SMEM_BYTES>>>(
        ahi, alo, wop, out, nullptr, nullptr, M, HID_, HID_);
}

// round 14
// speedup vs baseline: 1.9859x; 1.1734x over previous
#include <cuda_runtime.h>
#include <cuda_fp16.h>
#include <math.h>
#include <stdint.h>

// Problem constants
#define B_   2
#define QL_  2048
#define HID_ 2048
#define NH_  32
#define KVH_ 8
#define D_   64

// ===========================================================================
// PTX helpers — BASE PTX ONLY (harness targets plain sm_103: no tcgen05!)
// ===========================================================================
__device__ __forceinline__ uint32_t smem_u32(const void* p) {
    uint32_t a;
    asm("{ .reg .u64 t; cvta.to.shared.u64 t, %1; cvt.u32.u64 %0, t; }"
        : "=r"(a) : "l"(p));
    return a;
}
__device__ __forceinline__ void ldmat_x4(uint32_t* r, uint32_t addr) {
    asm volatile("ldmatrix.sync.aligned.m8n8.x4.shared.b16 {%0,%1,%2,%3}, [%4];"
                 : "=r"(r[0]), "=r"(r[1]), "=r"(r[2]), "=r"(r[3]) : "r"(addr));
}
__device__ __forceinline__ void ldmat_x2(uint32_t* r, uint32_t addr) {
    asm volatile("ldmatrix.sync.aligned.m8n8.x2.shared.b16 {%0,%1}, [%2];"
                 : "=r"(r[0]), "=r"(r[1]) : "r"(addr));
}
// fp16 MMA: D(f32) += A(f16) * B(f16)
__device__ __forceinline__ void mma_f16(float* d, const uint32_t* a, const uint32_t* b) {
    asm volatile("mma.sync.aligned.m16n8k16.row.col.f32.f16.f16.f32 "
                 "{%0,%1,%2,%3}, {%4,%5,%6,%7}, {%8,%9}, {%0,%1,%2,%3};"
                 : "+f"(d[0]), "+f"(d[1]), "+f"(d[2]), "+f"(d[3])
                 : "r"(a[0]), "r"(a[1]), "r"(a[2]), "r"(a[3]),
                   "r"(b[0]), "r"(b[1]));
}
__device__ __forceinline__ void cp_async16(uint32_t dst, const void* src) {
    asm volatile("cp.async.cg.shared.global [%0], [%1], 16;"
                 :: "r"(dst), "l"(src));
}
#define CP_COMMIT()  asm volatile("cp.async.commit_group;" ::: "memory")
#define CP_WAIT(n)   asm volatile("cp.async.wait_group %0;" :: "n"(n) : "memory")

// ===========================================================================
// Scratch (device globals — no allocation allowed)
// ===========================================================================
__device__ float g_Q[(size_t)B_ * NH_  * QL_ * D_];   // [b,h,q,d] fp32
__device__ float g_K[(size_t)B_ * KVH_ * QL_ * D_];
__device__ float g_V[(size_t)B_ * KVH_ * QL_ * D_];
__device__ float g_cos[QL_ * 32];
__device__ float g_sin[QL_ * 32];
// fp16 operands
__device__ __half g_Xhi[(size_t)B_ * QL_ * HID_];     // X split (A of QKV gemm)
__device__ __half g_Xlo[(size_t)B_ * QL_ * HID_];
__device__ __half g_W  [(size_t)3072 * HID_];         // Wq|Wk|Wv transposed [N,K] single
__device__ __half g_Wo [(size_t)HID_ * HID_];         // Wo transposed [N,K] single
__device__ __half g_A16[(size_t)B_ * QL_ * HID_];     // attn out single fp16 (A of Wo gemm)
__device__ __half g_Qbh[(size_t)B_ * NH_  * QL_ * D_]; // roped Q split (A of S)
__device__ __half g_Qbl[(size_t)B_ * NH_  * QL_ * D_];
__device__ __half g_Kb [(size_t)B_ * KVH_ * QL_ * D_]; // roped K single (B of S)
__device__ __half g_Vt [(size_t)B_ * KVH_ * D_ * QL_]; // V^T single (B of PV)

// ===========================================================================
// fp32 -> (fp16 hi, fp16 lo) split
// ===========================================================================
__global__ void split_kernel(const float* __restrict__ src,
                             __half* __restrict__ hi,
                             __half* __restrict__ lo, int n)
{
    int i = blockIdx.x * blockDim.x + threadIdx.x;
    if (i >= n) return;
    float v = src[i];
    __half h = __float2half_rn(v);
    hi[i] = h;
    lo[i] = __float2half_rn(v - __half2float(h));
}

// Transpose + round: W[K, Ncols] -> T[(rowOffset+n), k] fp16, ldT = K.
__global__ void transpose_half_kernel(const float* __restrict__ W,
                                      __half* __restrict__ T,
                                      int K, int Ncols, int rowOffset)
{
    __shared__ float tile[32][33];
    int k0 = blockIdx.y * 32, n0 = blockIdx.x * 32;
    int tx = threadIdx.x, ty = threadIdx.y;    // (32, 8)
#pragma unroll
    for (int i = 0; i < 4; i++) {
        int k = k0 + ty + i * 8;
        tile[ty + i * 8][tx] = W[(size_t)k * Ncols + n0 + tx];
    }
    __syncthreads();
#pragma unroll
    for (int i = 0; i < 4; i++) {
        int n = n0 + ty + i * 8;
        T[(size_t)(rowOffset + n) * K + k0 + tx] = __float2half_rn(tile[tx][ty + i * 8]);
    }
}

// V transpose: g_V [bk, seq, 64] fp32 -> Vt [bk, 64, 2048] fp16 single
__global__ void vtrans_half_kernel(const float* __restrict__ V,
                                   __half* __restrict__ T)
{
    __shared__ float tile[32][33];
    int bk = blockIdx.z;
    int s0 = blockIdx.x * 32, d0 = blockIdx.y * 32;
    int tx = threadIdx.x, ty = threadIdx.y;
    const float* Vb = V + (size_t)bk * QL_ * 64;
#pragma unroll
    for (int i = 0; i < 4; i++) {
        int s = s0 + ty + i * 8;
        tile[ty + i * 8][tx] = Vb[(size_t)s * 64 + d0 + tx];
    }
    __syncthreads();
#pragma unroll
    for (int i = 0; i < 4; i++) {
        int d = d0 + ty + i * 8;
        T[(size_t)bk * 64 * QL_ + (size_t)d * QL_ + s0 + tx] =
            __float2half_rn(tile[tx][ty + i * 8]);
    }
}

// ===========================================================================
// mma.sync fp16 GEMM:  C = A @ B^T, B fp16 single.
// SPLITA=1: A = Ahi + Alo (2 passes). SPLITA=0: A single (1 pass).
// CTA tile 128x256, 8 warps (2x4), warp tile 64x64, m16n8k16.
// K-chunks of 64, 3-stage cp.async pipeline.
// ===========================================================================
#define TILE_A   18432                       // 128 rows * 144 B
#define TILE_BB  36864                       // 256 rows * 144 B

template<int MODE, int SPLITA>
__global__ void __launch_bounds__(256)
mma_gemm(const __half* __restrict__ Ahi, const __half* __restrict__ Alo,
         const __half* __restrict__ Bh,
         float* __restrict__ C0, float* __restrict__ C1, float* __restrict__ C2,
         int M, int N, int K)
{
    constexpr uint32_t STAGE = (1 + SPLITA) * TILE_A + TILE_BB;
    extern __shared__ char smc[];
    const uint32_t sbase = smem_u32(smc);
    const int tid  = threadIdx.x;
    const int wid  = tid >> 5;
    const int lane = tid & 31;
    const int bx   = blockIdx.x;   // 256-col N tile
    const int by   = blockIdx.y;   // 128-row M tile
    const int wm   = wid >> 2;     // 0..1
    const int wn   = wid & 3;      // 0..3

    float acc[4][8][4];
#pragma unroll
    for (int mt = 0; mt < 4; mt++)
#pragma unroll
        for (int nt = 0; nt < 8; nt++)
#pragma unroll
            for (int r = 0; r < 4; r++) acc[mt][nt][r] = 0.f;

    const int NC = K >> 6;

    auto load_chunk = [&](int ci, int s) {
        const int k0 = ci * 64;
        const uint32_t sb = sbase + s * STAGE;
        // A (hi, and lo when split): 128 rows x 8 segs
#pragma unroll
        for (int it = 0; it < 4; it++) {
            int f = tid + it * 256;          // 0..1023
            int r = f >> 3, seg = f & 7;
            uint32_t dst = sb + r * 144 + seg * 16;
            size_t ga = (size_t)(by * 128 + r) * K + k0 + seg * 8;
            cp_async16(dst, Ahi + ga);
            if (SPLITA) cp_async16(dst + TILE_A, Alo + ga);
        }
        // B: 256 rows x 8 segs
#pragma unroll
        for (int it = 0; it < 8; it++) {
            int f = tid + it * 256;          // 0..2047
            int r = f >> 3, seg = f & 7;
            uint32_t dst = sb + (1 + SPLITA) * TILE_A + r * 144 + seg * 16;
            size_t gb = (size_t)(bx * 256 + r) * K + k0 + seg * 8;
            cp_async16(dst, Bh + gb);
        }
        CP_COMMIT();
    };

    load_chunk(0, 0);
    if (NC > 1) load_chunk(1, 1);

    const int ar   = lane & 15;
    const int acol = (lane >> 4) * 8;
    const int br   = lane & 7;
    const int bcol = ((lane >> 3) & 1) * 8;

    for (int ci = 0; ci < NC; ci++) {
        const int s = ci % 3;
        if (ci + 2 < NC) { load_chunk(ci + 2, (ci + 2) % 3); CP_WAIT(2); }
        else if (ci + 1 < NC) { CP_WAIT(1); }
        else { CP_WAIT(0); }
        __syncthreads();

        const uint32_t sb    = sbase + s * STAGE;
        const uint32_t aBase = sb + wm * 64 * 144;
        const uint32_t bBase = sb + (1 + SPLITA) * TILE_A + wn * 64 * 144;

#pragma unroll
        for (int ks = 0; ks < 4; ks++) {
            const int kc = ks * 16;
            uint32_t ahi[4][4], alo[4][4], bh[8][2];
#pragma unroll
            for (int mt = 0; mt < 4; mt++) {
                uint32_t a = aBase + (mt * 16 + ar) * 144 + (kc + acol) * 2;
                ldmat_x4(ahi[mt], a);
                if (SPLITA) ldmat_x4(alo[mt], a + TILE_A);
            }
#pragma unroll
            for (int nt = 0; nt < 8; nt++) {
                uint32_t b = bBase + (nt * 8 + br) * 144 + (kc + bcol) * 2;
                ldmat_x2(bh[nt], b);
            }
#pragma unroll
            for (int mt = 0; mt < 4; mt++)
#pragma unroll
                for (int nt = 0; nt < 8; nt++)
                    mma_f16(acc[mt][nt], ahi[mt], bh[nt]);
            if (SPLITA) {
#pragma unroll
                for (int mt = 0; mt < 4; mt++)
#pragma unroll
                    for (int nt = 0; nt < 8; nt++)
                        mma_f16(acc[mt][nt], alo[mt], bh[nt]);
            }
        }
        __syncthreads();
    }

    const int lrow = lane >> 2;
    const int lcol = (lane & 3) * 2;
#pragma unroll
    for (int mt = 0; mt < 4; mt++) {
#pragma unroll
        for (int nt = 0; nt < 8; nt++) {
            int row0 = by * 128 + wm * 64 + mt * 16 + lrow;
            int col  = bx * 256 + wn * 64 + nt * 8 + lcol;
#pragma unroll
            for (int half = 0; half < 2; half++) {
                int m = row0 + half * 8;
                float2 v = make_float2(acc[mt][nt][half * 2],
                                       acc[mt][nt][half * 2 + 1]);
                if (MODE == 0) {
                    *(float2*)&C0[(size_t)m * N + col] = v;
                } else {
                    int b = m >> 11, t = m & 2047, dd = col & 63;
                    if (col < 2048) {
                        int h = col >> 6;
                        *(float2*)&C0[((((size_t)b * NH_ + h) * QL_ + t) << 6) + dd] = v;
                    } else if (col < 2560) {
                        int h = (col - 2048) >> 6;
                        *(float2*)&C1[((((size_t)b * KVH_ + h) * QL_ + t) << 6) + dd] = v;
                    } else {
                        int h = (col - 2560) >> 6;
                        *(float2*)&C2[((((size_t)b * KVH_ + h) * QL_ + t) << 6) + dd] = v;
                    }
                }
            }
        }
    }
}

#define MMA_SMEM_SPLIT  (3 * (2 * TILE_A + TILE_BB))   // 221184
#define MMA_SMEM_SINGLE (3 * (TILE_A + TILE_BB))       // 165888

// ===========================================================================
// RoPE (fp64 trig once — --use_fast_math breaks sincosf at ~2000 rad)
// ===========================================================================
__global__ void rope_table_kernel(float* __restrict__ ct, float* __restrict__ st,
                                  int Q)
{
    int idx = blockIdx.x * blockDim.x + threadIdx.x;
    if (idx >= Q * 32) return;
    int j = idx & 31;
    int t = idx >> 5;
    float freq = (float)(1.0 / pow(10000.0, (double)(2 * j) / 64.0));
    float ang  = (float)t * freq;
    double cd, sd;
    sincos((double)ang, &sd, &cd);
    ct[idx] = (float)cd;
    st[idx] = (float)sd;
}

// RoPE apply for Q: emits fp16 hi/lo split (A operand of S)
__global__ void rope_apply_q(const float* __restrict__ buf,
                             const float* __restrict__ ct,
                             const float* __restrict__ st,
                             __half* __restrict__ oh, __half* __restrict__ ol,
                             int Q, int total)
{
    int idx = blockIdx.x * blockDim.x + threadIdx.x;
    if (idx >= total) return;
    int j  = idx & 31;
    int t  = (idx >> 5) % Q;
    int bh = idx / (32 * Q);
    size_t base = ((size_t)bh * Q + t) * 64;

    float c = ct[(t << 5) + j];
    float s = st[(t << 5) + j];
    float x1 = buf[base + j];
    float x2 = buf[base + j + 32];
    float r1 = x1 * c - x2 * s;
    float r2 = x2 * c + x1 * s;
    __half h1 = __float2half_rn(r1);
    __half h2 = __float2half_rn(r2);
    oh[base + j]      = h1;
    oh[base + j + 32] = h2;
    ol[base + j]      = __float2half_rn(r1 - __half2float(h1));
    ol[base + j + 32] = __float2half_rn(r2 - __half2float(h2));
}

// RoPE apply for K: emits single rounded fp16 (B operand of S)
__global__ void rope_apply_k(const float* __restrict__ buf,
                             const float* __restrict__ ct,
                             const float* __restrict__ st,
                             __half* __restrict__ oh,
                             int Q, int total)
{
    int idx = blockIdx.x * blockDim.x + threadIdx.x;
    if (idx >= total) return;
    int j  = idx & 31;
    int t  = (idx >> 5) % Q;
    int bh = idx / (32 * Q);
    size_t base = ((size_t)bh * Q + t) * 64;

    float c = ct[(t << 5) + j];
    float s = st[(t << 5) + j];
    float x1 = buf[base + j];
    float x2 = buf[base + j + 32];
    oh[base + j]      = __float2half_rn(x1 * c - x2 * s);
    oh[base + j + 32] = __float2half_rn(x2 * c + x1 * s);
}

// ===========================================================================
// Flash attention, fp16. S: 2 passes (Q split). PV: 1 pass (P single —
// output is rounded to fp16 anyway, so P-lo precision is discarded).
// Output: single fp16 [b*Q + q, h*64 + d].
// Grid (QL/128, NH, B), 256 thr, 8 warps.
// ===========================================================================
#define AT_KTILE 9216                  // 64 rows * 144 B
#define AT_STAGE (2 * AT_KTILE)        // 18432
#define AT_Q_OFF (2 * AT_STAGE)        // 36864
#define AT_SMEM  (AT_Q_OFF + 2 * 128 * 144)   // 73728

__global__ void __launch_bounds__(256, 2)
attn_mma(const __half* __restrict__ Qh, const __half* __restrict__ Ql,
         const __half* __restrict__ Kh, const __half* __restrict__ Vt,
         __half* __restrict__ O)
{
    extern __shared__ char smc[];
    const uint32_t sbase = smem_u32(smc);
    const int tid  = threadIdx.x;
    const int wid  = tid >> 5;
    const int lane = tid & 31;
    const int qt   = blockIdx.x;
    const int h    = blockIdx.y;
    const int b    = blockIdx.z;
    const int kvh  = h >> 2;           // NH/KVH = 4
    const int q0   = qt * 128;

    const __half* Qgh = Qh + (((size_t)b * NH_ + h) * QL_ + q0) * 64;
    const __half* Qgl = Ql + (((size_t)b * NH_ + h) * QL_ + q0) * 64;
    const __half* Kg  = Kh + (((size_t)b * KVH_ + kvh) * QL_) * 64;
    const __half* Vg  = Vt + (((size_t)b * KVH_ + kvh) * 64) * QL_;

#pragma unroll
    for (int it = 0; it < 4; it++) {
        int f = tid + it * 256;
        int r = f >> 3, seg = f & 7;
        uint32_t dst = sbase + AT_Q_OFF + r * 144 + seg * 16;
        cp_async16(dst,             Qgh + (size_t)r * 64 + seg * 8);
        cp_async16(dst + 128 * 144, Qgl + (size_t)r * 64 + seg * 8);
    }
    CP_COMMIT();

    auto load_kv = [&](int kt, int s) {
        const int k0 = kt * 64;
        const uint32_t sb = sbase + s * AT_STAGE;
#pragma unroll
        for (int it = 0; it < 2; it++) {
            int f = tid + it * 256;
            int r = f >> 3, seg = f & 7;
            uint32_t dst = sb + r * 144 + seg * 16;
            cp_async16(dst,            Kg + (size_t)(k0 + r) * 64 + seg * 8);
            cp_async16(dst + AT_KTILE, Vg + (size_t)r * QL_ + k0 + seg * 8);
        }
        CP_COMMIT();
    };

    load_kv(0, 0);

    CP_WAIT(1);
    __syncthreads();

    const int ar   = lane & 15;
    const int acol = (lane >> 4) * 8;
    const int br   = lane & 7;
    const int bcol = ((lane >> 3) & 1) * 8;

    uint32_t qfh[4][4], qfl[4][4];
    {
        uint32_t qBase = sbase + AT_Q_OFF + (wid * 16 + ar) * 144;
#pragma unroll
        for (int ks = 0; ks < 4; ks++) {
            uint32_t a = qBase + (ks * 16 + acol) * 2;
            ldmat_x4(qfh[ks], a);
            ldmat_x4(qfl[ks], a + 128 * 144);
        }
    }

    float o[8][4];
#pragma unroll
    for (int nt = 0; nt < 8; nt++)
#pragma unroll
        for (int j = 0; j < 4; j++) o[nt][j] = 0.f;
    float m0 = -1e30f, m1 = -1e30f, l0 = 0.f, l1 = 0.f;

    const int ktiles = qt * 2 + 2;
    const int qg0 = q0 + wid * 16 + (lane >> 2);
    const int qg1 = qg0 + 8;
    const int lc2 = (lane & 3) * 2;

    for (int kt = 0; kt < ktiles; kt++) {
        const int s = kt & 1;
        if (kt + 1 < ktiles) { load_kv(kt + 1, s ^ 1); CP_WAIT(1); }
        else                 { CP_WAIT(0); }
        __syncthreads();

        const uint32_t kb = sbase + s * AT_STAGE;
        const uint32_t vb = kb + AT_KTILE;
        const int k0 = kt * 64;

        // ---- S = Q K^T (2 passes: Qhi*K + Qlo*K) ----
        float sf[8][4];
#pragma unroll
        for (int nt = 0; nt < 8; nt++)
#pragma unroll
            for (int j = 0; j < 4; j++) sf[nt][j] = 0.f;

#pragma unroll
        for (int ks = 0; ks < 4; ks++) {
            uint32_t bh[8][2];
#pragma unroll
            for (int nt = 0; nt < 8; nt++) {
                uint32_t a = kb + (nt * 8 + br) * 144 + (ks * 16 + bcol) * 2;
                ldmat_x2(bh[nt], a);
            }
#pragma unroll
            for (int nt = 0; nt < 8; nt++) mma_f16(sf[nt], qfh[ks], bh[nt]);
#pragma unroll
            for (int nt = 0; nt < 8; nt++) mma_f16(sf[nt], qfl[ks], bh[nt]);
        }

        // ---- scale + causal mask + row max ----
        const bool domask = (kt >= ktiles - 2);
        float rm0 = -1e30f, rm1 = -1e30f;
#pragma unroll
        for (int nt = 0; nt < 8; nt++) {
            int kg = k0 + nt * 8 + lc2;
#pragma unroll
            for (int j = 0; j < 4; j++) {
                float v = sf[nt][j] * 0.125f;
                if (domask) {
                    int kcol = kg + (j & 1);
                    int qrow = (j < 2) ? qg0 : qg1;
                    if (kcol > qrow) v = -1e30f;
                }
                sf[nt][j] = v;
                if (j < 2) rm0 = fmaxf(rm0, v); else rm1 = fmaxf(rm1, v);
            }
        }
        rm0 = fmaxf(rm0, __shfl_xor_sync(0xffffffffu, rm0, 1));
        rm0 = fmaxf(rm0, __shfl_xor_sync(0xffffffffu, rm0, 2));
        rm1 = fmaxf(rm1, __shfl_xor_sync(0xffffffffu, rm1, 1));
        rm1 = fmaxf(rm1, __shfl_xor_sync(0xffffffffu, rm1, 2));

        float nm0 = fmaxf(m0, rm0), nm1 = fmaxf(m1, rm1);
        float c0 = __expf(m0 - nm0), c1 = __expf(m1 - nm1);

        // ---- exp + row sum + pack P (single fp16) ----
        float rs0 = 0.f, rs1 = 0.f;
        uint32_t ph[8][2];
#pragma unroll
        for (int nt = 0; nt < 8; nt++) {
            float p0 = __expf(sf[nt][0] - nm0);
            float p1 = __expf(sf[nt][1] - nm0);
            float p2 = __expf(sf[nt][2] - nm1);
            float p3 = __expf(sf[nt][3] - nm1);
            rs0 += p0 + p1;
            rs1 += p2 + p3;
            __half2 h01 = __floats2half2_rn(p0, p1);
            __half2 h23 = __floats2half2_rn(p2, p3);
            ph[nt][0] = *(uint32_t*)&h01;
            ph[nt][1] = *(uint32_t*)&h23;
        }
        rs0 += __shfl_xor_sync(0xffffffffu, rs0, 1);
        rs0 += __shfl_xor_sync(0xffffffffu, rs0, 2);
        rs1 += __shfl_xor_sync(0xffffffffu, rs1, 1);
        rs1 += __shfl_xor_sync(0xffffffffu, rs1, 2);

        l0 = l0 * c0 + rs0;
        l1 = l1 * c1 + rs1;
        m0 = nm0;
        m1 = nm1;

#pragma unroll
        for (int nt = 0; nt < 8; nt++) {
            o[nt][0] *= c0; o[nt][1] *= c0;
            o[nt][2] *= c1; o[nt][3] *= c1;
        }

        // ---- O += P V (single pass) ----
#pragma unroll
        for (int ks = 0; ks < 4; ks++) {
            uint32_t bh[8][2];
#pragma unroll
            for (int nt = 0; nt < 8; nt++) {
                uint32_t a = vb + (nt * 8 + br) * 144 + (ks * 16 + bcol) * 2;
                ldmat_x2(bh[nt], a);
            }
            uint32_t pah[4] = {ph[2 * ks][0], ph[2 * ks][1],
                               ph[2 * ks + 1][0], ph[2 * ks + 1][1]};
#pragma unroll
            for (int nt = 0; nt < 8; nt++) mma_f16(o[nt], pah, bh[nt]);
        }
        __syncthreads();
    }

    // ---- epilogue: O/l -> single fp16, [b*Q + q, h*64 + d] ----
    float inv0 = 1.0f / l0, inv1 = 1.0f / l1;
    int gr0 = b * QL_ + q0 + wid * 16 + (lane >> 2);
    int gr1 = gr0 + 8;
#pragma unroll
    for (int nt = 0; nt < 8; nt++) {
        int gc = h * 64 + nt * 8 + lc2;
        __half2 h01 = __floats2half2_rn(o[nt][0] * inv0, o[nt][1] * inv0);
        __half2 h23 = __floats2half2_rn(o[nt][2] * inv1, o[nt][3] * inv1);
        *(__half2*)&O[(size_t)gr0 * HID_ + gc] = h01;
        *(__half2*)&O[(size_t)gr1 * HID_ + gc] = h23;
    }
}

// ===========================================================================
extern "C" void kernel_launch(void* const* d_in, const int* in_sizes, int n_in,
                              void* d_out, int out_size)
{
    const float* X  = (const float*)d_in[0];
    const float* Wq = (const float*)d_in[2];
    const float* Wk = (const float*)d_in[3];
    const float* Wv = (const float*)d_in[4];
    const float* Wo = (const float*)d_in[5];
    float* out = (float*)d_out;

    float *qp, *kp, *vp, *cp, *sp;
    __half *xhi, *xlo, *wp, *wop, *a16, *qbh, *qbl, *kb, *vt;
    cudaGetSymbolAddress((void**)&qp, g_Q);
    cudaGetSymbolAddress((void**)&kp, g_K);
    cudaGetSymbolAddress((void**)&vp, g_V);
    cudaGetSymbolAddress((void**)&cp, g_cos);
    cudaGetSymbolAddress((void**)&sp, g_sin);
    cudaGetSymbolAddress((void**)&xhi, g_Xhi);
    cudaGetSymbolAddress((void**)&xlo, g_Xlo);
    cudaGetSymbolAddress((void**)&wp,  g_W);
    cudaGetSymbolAddress((void**)&wop, g_Wo);
    cudaGetSymbolAddress((void**)&a16, g_A16);
    cudaGetSymbolAddress((void**)&qbh, g_Qbh);
    cudaGetSymbolAddress((void**)&qbl, g_Qbl);
    cudaGetSymbolAddress((void**)&kb,  g_Kb);
    cudaGetSymbolAddress((void**)&vt,  g_Vt);

    const int M = B_ * QL_;   // 4096

    cudaFuncSetAttribute((const void*)mma_gemm<1, 1>,
                         cudaFuncAttributeMaxDynamicSharedMemorySize, MMA_SMEM_SPLIT);
    cudaFuncSetAttribute((const void*)mma_gemm<0, 0>,
                         cudaFuncAttributeMaxDynamicSharedMemorySize, MMA_SMEM_SINGLE);
    cudaFuncSetAttribute(attn_mma, cudaFuncAttributeMaxDynamicSharedMemorySize, AT_SMEM);

    // prep
    rope_table_kernel<<<(QL_ * 32 + 255) / 256, 256>>>(cp, sp, QL_);
    split_kernel<<<(M * HID_ + 255) / 256, 256>>>(X, xhi, xlo, M * HID_);
    transpose_half_kernel<<<dim3(2048 / 32, HID_ / 32), dim3(32, 8)>>>(Wq, wp, HID_, 2048, 0);
    transpose_half_kernel<<<dim3(512 / 32,  HID_ / 32), dim3(32, 8)>>>(Wk, wp, HID_, 512, 2048);
    transpose_half_kernel<<<dim3(512 / 32,  HID_ / 32), dim3(32, 8)>>>(Wv, wp, HID_, 512, 2560);

    // fused QKV projection (A split, 2 passes), scatter to head layouts (fp32)
    mma_gemm<1, 1><<<dim3(3072 / 256, M / 128), 256, MMA_SMEM_SPLIT>>>(
        xhi, xlo, wp, qp, kp, vp, M, 3072, HID_);

    // RoPE -> Q split / K single ; V^T ; Wo transpose
    {
        int totq = B_ * NH_  * QL_ * 32;
        int totk = B_ * KVH_ * QL_ * 32;
        rope_apply_q<<<(totq + 255) / 256, 256>>>(qp, cp, sp, qbh, qbl, QL_, totq);
        rope_apply_k<<<(totk + 255) / 256, 256>>>(kp, cp, sp, kb, QL_, totk);
        vtrans_half_kernel<<<dim3(QL_ / 32, 2, B_ * KVH_), dim3(32, 8)>>>(vp, vt);
        transpose_half_kernel<<<dim3(2048 / 32, HID_ / 32), dim3(32, 8)>>>(Wo, wop, HID_, 2048, 0);
    }

    // Attention on tensor cores, single-fp16 output
    attn_mma<<<dim3(QL_ / 128, NH_, B_), 256, AT_SMEM>>>(
        qbh, qbl, kb, vt, a16);

    // Output projection (A single, 1 pass)
    mma_gemm<0, 0><<<dim3(HID_ / 256, M / 128), 256, MMA_SMEM_SINGLE>>>(
        a16, nullptr, wop, out, nullptr, nullptr, M, HID_, HID_);
}

// round 15
// speedup vs baseline: 2.3843x; 1.2006x over previous
#include <cuda_runtime.h>
#include <cuda_fp16.h>
#include <math.h>
#include <stdint.h>

// Problem constants
#define B_   2
#define QL_  2048
#define HID_ 2048
#define NH_  32
#define KVH_ 8
#define D_   64

// ===========================================================================
// PTX helpers — BASE PTX ONLY (harness targets plain sm_103: no tcgen05!)
// ===========================================================================
__device__ __forceinline__ uint32_t smem_u32(const void* p) {
    uint32_t a;
    asm("{ .reg .u64 t; cvta.to.shared.u64 t, %1; cvt.u32.u64 %0, t; }"
        : "=r"(a) : "l"(p));
    return a;
}
__device__ __forceinline__ void ldmat_x4(uint32_t* r, uint32_t addr) {
    asm volatile("ldmatrix.sync.aligned.m8n8.x4.shared.b16 {%0,%1,%2,%3}, [%4];"
                 : "=r"(r[0]), "=r"(r[1]), "=r"(r[2]), "=r"(r[3]) : "r"(addr));
}
__device__ __forceinline__ void ldmat_x2(uint32_t* r, uint32_t addr) {
    asm volatile("ldmatrix.sync.aligned.m8n8.x2.shared.b16 {%0,%1}, [%2];"
                 : "=r"(r[0]), "=r"(r[1]) : "r"(addr));
}
// fp16 MMA: D(f32) += A(f16) * B(f16)
__device__ __forceinline__ void mma_f16(float* d, const uint32_t* a, const uint32_t* b) {
    asm volatile("mma.sync.aligned.m16n8k16.row.col.f32.f16.f16.f32 "
                 "{%0,%1,%2,%3}, {%4,%5,%6,%7}, {%8,%9}, {%0,%1,%2,%3};"
                 : "+f"(d[0]), "+f"(d[1]), "+f"(d[2]), "+f"(d[3])
                 : "r"(a[0]), "r"(a[1]), "r"(a[2]), "r"(a[3]),
                   "r"(b[0]), "r"(b[1]));
}
__device__ __forceinline__ void cp_async16(uint32_t dst, const void* src) {
    asm volatile("cp.async.cg.shared.global [%0], [%1], 16;"
                 :: "r"(dst), "l"(src));
}
#define CP_COMMIT()  asm volatile("cp.async.commit_group;" ::: "memory")
#define CP_WAIT(n)   asm volatile("cp.async.wait_group %0;" :: "n"(n) : "memory")

// ===========================================================================
// Scratch (device globals — no allocation allowed)
// ===========================================================================
__device__ float g_Q[(size_t)B_ * NH_  * QL_ * D_];   // [b,h,q,d] fp32
__device__ float g_K[(size_t)B_ * KVH_ * QL_ * D_];
__device__ float g_V[(size_t)B_ * KVH_ * QL_ * D_];
__device__ float g_cos[QL_ * 32];
__device__ float g_sin[QL_ * 32];
// fp16 operands
__device__ __half g_X16[(size_t)B_ * QL_ * HID_];     // X single fp16 (A of QKV gemm)
__device__ __half g_W  [(size_t)3072 * HID_];         // Wq|Wk|Wv transposed [N,K] single
__device__ __half g_Wo [(size_t)HID_ * HID_];         // Wo transposed [N,K] single
__device__ __half g_A16[(size_t)B_ * QL_ * HID_];     // attn out single fp16 (A of Wo gemm)
__device__ __half g_Qbh[(size_t)B_ * NH_  * QL_ * D_]; // roped Q split (A of S)
__device__ __half g_Qbl[(size_t)B_ * NH_  * QL_ * D_];
__device__ __half g_Kb [(size_t)B_ * KVH_ * QL_ * D_]; // roped K single (B of S)
__device__ __half g_Vt [(size_t)B_ * KVH_ * D_ * QL_]; // V^T single (B of PV)

// ===========================================================================
// fp32 -> fp16 round
// ===========================================================================
__global__ void round_half_kernel(const float* __restrict__ src,
                                  __half* __restrict__ dst, int n)
{
    int i = blockIdx.x * blockDim.x + threadIdx.x;
    if (i >= n) return;
    dst[i] = __float2half_rn(src[i]);
}

// Transpose + round: W[K, Ncols] -> T[(rowOffset+n), k] fp16, ldT = K.
__global__ void transpose_half_kernel(const float* __restrict__ W,
                                      __half* __restrict__ T,
                                      int K, int Ncols, int rowOffset)
{
    __shared__ float tile[32][33];
    int k0 = blockIdx.y * 32, n0 = blockIdx.x * 32;
    int tx = threadIdx.x, ty = threadIdx.y;    // (32, 8)
#pragma unroll
    for (int i = 0; i < 4; i++) {
        int k = k0 + ty + i * 8;
        tile[ty + i * 8][tx] = W[(size_t)k * Ncols + n0 + tx];
    }
    __syncthreads();
#pragma unroll
    for (int i = 0; i < 4; i++) {
        int n = n0 + ty + i * 8;
        T[(size_t)(rowOffset + n) * K + k0 + tx] = __float2half_rn(tile[tx][ty + i * 8]);
    }
}

// V transpose: g_V [bk, seq, 64] fp32 -> Vt [bk, 64, 2048] fp16 single
__global__ void vtrans_half_kernel(const float* __restrict__ V,
                                   __half* __restrict__ T)
{
    __shared__ float tile[32][33];
    int bk = blockIdx.z;
    int s0 = blockIdx.x * 32, d0 = blockIdx.y * 32;
    int tx = threadIdx.x, ty = threadIdx.y;
    const float* Vb = V + (size_t)bk * QL_ * 64;
#pragma unroll
    for (int i = 0; i < 4; i++) {
        int s = s0 + ty + i * 8;
        tile[ty + i * 8][tx] = Vb[(size_t)s * 64 + d0 + tx];
    }
    __syncthreads();
#pragma unroll
    for (int i = 0; i < 4; i++) {
        int d = d0 + ty + i * 8;
        T[(size_t)bk * 64 * QL_ + (size_t)d * QL_ + s0 + tx] =
            __float2half_rn(tile[tx][ty + i * 8]);
    }
}

// ===========================================================================
// mma.sync fp16 GEMM:  C = A @ B^T, B fp16 single.
// SPLITA=1: A = Ahi + Alo (2 passes). SPLITA=0: A single (1 pass).
// CTA tile 128x256, 8 warps (2x4), warp tile 64x64, m16n8k16.
// K-chunks of 64, 3-stage cp.async pipeline.
// ===========================================================================
#define TILE_A   18432                       // 128 rows * 144 B
#define TILE_BB  36864                       // 256 rows * 144 B

template<int MODE, int SPLITA>
__global__ void __launch_bounds__(256)
mma_gemm(const __half* __restrict__ Ahi, const __half* __restrict__ Alo,
         const __half* __restrict__ Bh,
         float* __restrict__ C0, float* __restrict__ C1, float* __restrict__ C2,
         int M, int N, int K)
{
    constexpr uint32_t STAGE = (1 + SPLITA) * TILE_A + TILE_BB;
    extern __shared__ char smc[];
    const uint32_t sbase = smem_u32(smc);
    const int tid  = threadIdx.x;
    const int wid  = tid >> 5;
    const int lane = tid & 31;
    const int bx   = blockIdx.x;   // 256-col N tile
    const int by   = blockIdx.y;   // 128-row M tile
    const int wm   = wid >> 2;     // 0..1
    const int wn   = wid & 3;      // 0..3

    float acc[4][8][4];
#pragma unroll
    for (int mt = 0; mt < 4; mt++)
#pragma unroll
        for (int nt = 0; nt < 8; nt++)
#pragma unroll
            for (int r = 0; r < 4; r++) acc[mt][nt][r] = 0.f;

    const int NC = K >> 6;

    auto load_chunk = [&](int ci, int s) {
        const int k0 = ci * 64;
        const uint32_t sb = sbase + s * STAGE;
#pragma unroll
        for (int it = 0; it < 4; it++) {
            int f = tid + it * 256;          // 0..1023
            int r = f >> 3, seg = f & 7;
            uint32_t dst = sb + r * 144 + seg * 16;
            size_t ga = (size_t)(by * 128 + r) * K + k0 + seg * 8;
            cp_async16(dst, Ahi + ga);
            if (SPLITA) cp_async16(dst + TILE_A, Alo + ga);
        }
#pragma unroll
        for (int it = 0; it < 8; it++) {
            int f = tid + it * 256;          // 0..2047
            int r = f >> 3, seg = f & 7;
            uint32_t dst = sb + (1 + SPLITA) * TILE_A + r * 144 + seg * 16;
            size_t gb = (size_t)(bx * 256 + r) * K + k0 + seg * 8;
            cp_async16(dst, Bh + gb);
        }
        CP_COMMIT();
    };

    load_chunk(0, 0);
    if (NC > 1) load_chunk(1, 1);

    const int ar   = lane & 15;
    const int acol = (lane >> 4) * 8;
    const int br   = lane & 7;
    const int bcol = ((lane >> 3) & 1) * 8;

    for (int ci = 0; ci < NC; ci++) {
        const int s = ci % 3;
        if (ci + 2 < NC) { load_chunk(ci + 2, (ci + 2) % 3); CP_WAIT(2); }
        else if (ci + 1 < NC) { CP_WAIT(1); }
        else { CP_WAIT(0); }
        __syncthreads();

        const uint32_t sb    = sbase + s * STAGE;
        const uint32_t aBase = sb + wm * 64 * 144;
        const uint32_t bBase = sb + (1 + SPLITA) * TILE_A + wn * 64 * 144;

#pragma unroll
        for (int ks = 0; ks < 4; ks++) {
            const int kc = ks * 16;
            uint32_t ahi[4][4], alo[4][4], bh[8][2];
#pragma unroll
            for (int mt = 0; mt < 4; mt++) {
                uint32_t a = aBase + (mt * 16 + ar) * 144 + (kc + acol) * 2;
                ldmat_x4(ahi[mt], a);
                if (SPLITA) ldmat_x4(alo[mt], a + TILE_A);
            }
#pragma unroll
            for (int nt = 0; nt < 8; nt++) {
                uint32_t b = bBase + (nt * 8 + br) * 144 + (kc + bcol) * 2;
                ldmat_x2(bh[nt], b);
            }
#pragma unroll
            for (int mt = 0; mt < 4; mt++)
#pragma unroll
                for (int nt = 0; nt < 8; nt++)
                    mma_f16(acc[mt][nt], ahi[mt], bh[nt]);
            if (SPLITA) {
#pragma unroll
                for (int mt = 0; mt < 4; mt++)
#pragma unroll
                    for (int nt = 0; nt < 8; nt++)
                        mma_f16(acc[mt][nt], alo[mt], bh[nt]);
            }
        }
        __syncthreads();
    }

    const int lrow = lane >> 2;
    const int lcol = (lane & 3) * 2;
#pragma unroll
    for (int mt = 0; mt < 4; mt++) {
#pragma unroll
        for (int nt = 0; nt < 8; nt++) {
            int row0 = by * 128 + wm * 64 + mt * 16 + lrow;
            int col  = bx * 256 + wn * 64 + nt * 8 + lcol;
#pragma unroll
            for (int half = 0; half < 2; half++) {
                int m = row0 + half * 8;
                float2 v = make_float2(acc[mt][nt][half * 2],
                                       acc[mt][nt][half * 2 + 1]);
                if (MODE == 0) {
                    *(float2*)&C0[(size_t)m * N + col] = v;
                } else {
                    int b = m >> 11, t = m & 2047, dd = col & 63;
                    if (col < 2048) {
                        int h = col >> 6;
                        *(float2*)&C0[((((size_t)b * NH_ + h) * QL_ + t) << 6) + dd] = v;
                    } else if (col < 2560) {
                        int h = (col - 2048) >> 6;
                        *(float2*)&C1[((((size_t)b * KVH_ + h) * QL_ + t) << 6) + dd] = v;
                    } else {
                        int h = (col - 2560) >> 6;
                        *(float2*)&C2[((((size_t)b * KVH_ + h) * QL_ + t) << 6) + dd] = v;
                    }
                }
            }
        }
    }
}

#define MMA_SMEM_SINGLE (3 * (TILE_A + TILE_BB))       // 165888

// ===========================================================================
// RoPE (fp64 trig once — --use_fast_math breaks sincosf at ~2000 rad)
// ===========================================================================
__global__ void rope_table_kernel(float* __restrict__ ct, float* __restrict__ st,
                                  int Q)
{
    int idx = blockIdx.x * blockDim.x + threadIdx.x;
    if (idx >= Q * 32) return;
    int j = idx & 31;
    int t = idx >> 5;
    float freq = (float)(1.0 / pow(10000.0, (double)(2 * j) / 64.0));
    float ang  = (float)t * freq;
    double cd, sd;
    sincos((double)ang, &sd, &cd);
    ct[idx] = (float)cd;
    st[idx] = (float)sd;
}

// RoPE apply for Q: emits fp16 hi/lo split (A operand of S)
__global__ void rope_apply_q(const float* __restrict__ buf,
                             const float* __restrict__ ct,
                             const float* __restrict__ st,
                             __half* __restrict__ oh, __half* __restrict__ ol,
                             int Q, int total)
{
    int idx = blockIdx.x * blockDim.x + threadIdx.x;
    if (idx >= total) return;
    int j  = idx & 31;
    int t  = (idx >> 5) % Q;
    int bh = idx / (32 * Q);
    size_t base = ((size_t)bh * Q + t) * 64;

    float c = ct[(t << 5) + j];
    float s = st[(t << 5) + j];
    float x1 = buf[base + j];
    float x2 = buf[base + j + 32];
    float r1 = x1 * c - x2 * s;
    float r2 = x2 * c + x1 * s;
    __half h1 = __float2half_rn(r1);
    __half h2 = __float2half_rn(r2);
    oh[base + j]      = h1;
    oh[base + j + 32] = h2;
    ol[base + j]      = __float2half_rn(r1 - __half2float(h1));
    ol[base + j + 32] = __float2half_rn(r2 - __half2float(h2));
}

// RoPE apply for K: emits single rounded fp16 (B operand of S)
__global__ void rope_apply_k(const float* __restrict__ buf,
                             const float* __restrict__ ct,
                             const float* __restrict__ st,
                             __half* __restrict__ oh,
                             int Q, int total)
{
    int idx = blockIdx.x * blockDim.x + threadIdx.x;
    if (idx >= total) return;
    int j  = idx & 31;
    int t  = (idx >> 5) % Q;
    int bh = idx / (32 * Q);
    size_t base = ((size_t)bh * Q + t) * 64;

    float c = ct[(t << 5) + j];
    float s = st[(t << 5) + j];
    float x1 = buf[base + j];
    float x2 = buf[base + j + 32];
    oh[base + j]      = __float2half_rn(x1 * c - x2 * s);
    oh[base + j + 32] = __float2half_rn(x2 * c + x1 * s);
}

// ===========================================================================
// Flash attention, fp16. S: 2 passes (Q split). PV: 1 pass (P single).
// Output: single fp16 [b*Q + q, h*64 + d].
// Grid (QL/128, NH, B), 256 thr, 8 warps.
// ===========================================================================
#define AT_KTILE 9216                  // 64 rows * 144 B
#define AT_STAGE (2 * AT_KTILE)        // 18432
#define AT_Q_OFF (2 * AT_STAGE)        // 36864
#define AT_SMEM  (AT_Q_OFF + 2 * 128 * 144)   // 73728

__global__ void __launch_bounds__(256, 2)
attn_mma(const __half* __restrict__ Qh, const __half* __restrict__ Ql,
         const __half* __restrict__ Kh, const __half* __restrict__ Vt,
         __half* __restrict__ O)
{
    extern __shared__ char smc[];
    const uint32_t sbase = smem_u32(smc);
    const int tid  = threadIdx.x;
    const int wid  = tid >> 5;
    const int lane = tid & 31;
    const int qt   = blockIdx.x;
    const int h    = blockIdx.y;
    const int b    = blockIdx.z;
    const int kvh  = h >> 2;           // NH/KVH = 4
    const int q0   = qt * 128;

    const __half* Qgh = Qh + (((size_t)b * NH_ + h) * QL_ + q0) * 64;
    const __half* Qgl = Ql + (((size_t)b * NH_ + h) * QL_ + q0) * 64;
    const __half* Kg  = Kh + (((size_t)b * KVH_ + kvh) * QL_) * 64;
    const __half* Vg  = Vt + (((size_t)b * KVH_ + kvh) * 64) * QL_;

#pragma unroll
    for (int it = 0; it < 4; it++) {
        int f = tid + it * 256;
        int r = f >> 3, seg = f & 7;
        uint32_t dst = sbase + AT_Q_OFF + r * 144 + seg * 16;
        cp_async16(dst,             Qgh + (size_t)r * 64 + seg * 8);
        cp_async16(dst + 128 * 144, Qgl + (size_t)r * 64 + seg * 8);
    }
    CP_COMMIT();

    auto load_kv = [&](int kt, int s) {
        const int k0 = kt * 64;
        const uint32_t sb = sbase + s * AT_STAGE;
#pragma unroll
        for (int it = 0; it < 2; it++) {
            int f = tid + it * 256;
            int r = f >> 3, seg = f & 7;
            uint32_t dst = sb + r * 144 + seg * 16;
            cp_async16(dst,            Kg + (size_t)(k0 + r) * 64 + seg * 8);
            cp_async16(dst + AT_KTILE, Vg + (size_t)r * QL_ + k0 + seg * 8);
        }
        CP_COMMIT();
    };

    load_kv(0, 0);

    CP_WAIT(1);
    __syncthreads();

    const int ar   = lane & 15;
    const int acol = (lane >> 4) * 8;
    const int br   = lane & 7;
    const int bcol = ((lane >> 3) & 1) * 8;

    uint32_t qfh[4][4], qfl[4][4];
    {
        uint32_t qBase = sbase + AT_Q_OFF + (wid * 16 + ar) * 144;
#pragma unroll
        for (int ks = 0; ks < 4; ks++) {
            uint32_t a = qBase + (ks * 16 + acol) * 2;
            ldmat_x4(qfh[ks], a);
            ldmat_x4(qfl[ks], a + 128 * 144);
        }
    }

    float o[8][4];
#pragma unroll
    for (int nt = 0; nt < 8; nt++)
#pragma unroll
        for (int j = 0; j < 4; j++) o[nt][j] = 0.f;
    float m0 = -1e30f, m1 = -1e30f, l0 = 0.f, l1 = 0.f;

    const int ktiles = qt * 2 + 2;
    const int qg0 = q0 + wid * 16 + (lane >> 2);
    const int qg1 = qg0 + 8;
    const int lc2 = (lane & 3) * 2;

    for (int kt = 0; kt < ktiles; kt++) {
        const int s = kt & 1;
        if (kt + 1 < ktiles) { load_kv(kt + 1, s ^ 1); CP_WAIT(1); }
        else                 { CP_WAIT(0); }
        __syncthreads();

        const uint32_t kb = sbase + s * AT_STAGE;
        const uint32_t vb = kb + AT_KTILE;
        const int k0 = kt * 64;

        // ---- S = Q K^T (2 passes: Qhi*K + Qlo*K) ----
        float sf[8][4];
#pragma unroll
        for (int nt = 0; nt < 8; nt++)
#pragma unroll
            for (int j = 0; j < 4; j++) sf[nt][j] = 0.f;

#pragma unroll
        for (int ks = 0; ks < 4; ks++) {
            uint32_t bh[8][2];
#pragma unroll
            for (int nt = 0; nt < 8; nt++) {
                uint32_t a = kb + (nt * 8 + br) * 144 + (ks * 16 + bcol) * 2;
                ldmat_x2(bh[nt], a);
            }
#pragma unroll
            for (int nt = 0; nt < 8; nt++) mma_f16(sf[nt], qfh[ks], bh[nt]);
#pragma unroll
            for (int nt = 0; nt < 8; nt++) mma_f16(sf[nt], qfl[ks], bh[nt]);
        }

        // ---- scale + causal mask + row max ----
        const bool domask = (kt >= ktiles - 2);
        float rm0 = -1e30f, rm1 = -1e30f;
#pragma unroll
        for (int nt = 0; nt < 8; nt++) {
            int kg = k0 + nt * 8 + lc2;
#pragma unroll
            for (int j = 0; j < 4; j++) {
                float v = sf[nt][j] * 0.125f;
                if (domask) {
                    int kcol = kg + (j & 1);
                    int qrow = (j < 2) ? qg0 : qg1;
                    if (kcol > qrow) v = -1e30f;
                }
                sf[nt][j] = v;
                if (j < 2) rm0 = fmaxf(rm0, v); else rm1 = fmaxf(rm1, v);
            }
        }
        rm0 = fmaxf(rm0, __shfl_xor_sync(0xffffffffu, rm0, 1));
        rm0 = fmaxf(rm0, __shfl_xor_sync(0xffffffffu, rm0, 2));
        rm1 = fmaxf(rm1, __shfl_xor_sync(0xffffffffu, rm1, 1));
        rm1 = fmaxf(rm1, __shfl_xor_sync(0xffffffffu, rm1, 2));

        float nm0 = fmaxf(m0, rm0), nm1 = fmaxf(m1, rm1);
        float c0 = __expf(m0 - nm0), c1 = __expf(m1 - nm1);

        // ---- exp + row sum + pack P (single fp16) ----
        float rs0 = 0.f, rs1 = 0.f;
        uint32_t ph[8][2];
#pragma unroll
        for (int nt = 0; nt < 8; nt++) {
            float p0 = __expf(sf[nt][0] - nm0);
            float p1 = __expf(sf[nt][1] - nm0);
            float p2 = __expf(sf[nt][2] - nm1);
            float p3 = __expf(sf[nt][3] - nm1);
            rs0 += p0 + p1;
            rs1 += p2 + p3;
            __half2 h01 = __floats2half2_rn(p0, p1);
            __half2 h23 = __floats2half2_rn(p2, p3);
            ph[nt][0] = *(uint32_t*)&h01;
            ph[nt][1] = *(uint32_t*)&h23;
        }
        rs0 += __shfl_xor_sync(0xffffffffu, rs0, 1);
        rs0 += __shfl_xor_sync(0xffffffffu, rs0, 2);
        rs1 += __shfl_xor_sync(0xffffffffu, rs1, 1);
        rs1 += __shfl_xor_sync(0xffffffffu, rs1, 2);

        l0 = l0 * c0 + rs0;
        l1 = l1 * c1 + rs1;
        m0 = nm0;
        m1 = nm1;

#pragma unroll
        for (int nt = 0; nt < 8; nt++) {
            o[nt][0] *= c0; o[nt][1] *= c0;
            o[nt][2] *= c1; o[nt][3] *= c1;
        }

        // ---- O += P V (single pass) ----
#pragma unroll
        for (int ks = 0; ks < 4; ks++) {
            uint32_t bh[8][2];
#pragma unroll
            for (int nt = 0; nt < 8; nt++) {
                uint32_t a = vb + (nt * 8 + br) * 144 + (ks * 16 + bcol) * 2;
                ldmat_x2(bh[nt], a);
            }
            uint32_t pah[4] = {ph[2 * ks][0], ph[2 * ks][1],
                               ph[2 * ks + 1][0], ph[2 * ks + 1][1]};
#pragma unroll
            for (int nt = 0; nt < 8; nt++) mma_f16(o[nt], pah, bh[nt]);
        }
        __syncthreads();
    }

    // ---- epilogue: O/l -> single fp16, [b*Q + q, h*64 + d] ----
    float inv0 = 1.0f / l0, inv1 = 1.0f / l1;
    int gr0 = b * QL_ + q0 + wid * 16 + (lane >> 2);
    int gr1 = gr0 + 8;
#pragma unroll
    for (int nt = 0; nt < 8; nt++) {
        int gc = h * 64 + nt * 8 + lc2;
        __half2 h01 = __floats2half2_rn(o[nt][0] * inv0, o[nt][1] * inv0);
        __half2 h23 = __floats2half2_rn(o[nt][2] * inv1, o[nt][3] * inv1);
        *(__half2*)&O[(size_t)gr0 * HID_ + gc] = h01;
        *(__half2*)&O[(size_t)gr1 * HID_ + gc] = h23;
    }
}

// ===========================================================================
extern "C" void kernel_launch(void* const* d_in, const int* in_sizes, int n_in,
                              void* d_out, int out_size)
{
    const float* X  = (const float*)d_in[0];
    const float* Wq = (const float*)d_in[2];
    const float* Wk = (const float*)d_in[3];
    const float* Wv = (const float*)d_in[4];
    const float* Wo = (const float*)d_in[5];
    float* out = (float*)d_out;

    float *qp, *kp, *vp, *cp, *sp;
    __half *x16, *wp, *wop, *a16, *qbh, *qbl, *kb, *vt;
    cudaGetSymbolAddress((void**)&qp, g_Q);
    cudaGetSymbolAddress((void**)&kp, g_K);
    cudaGetSymbolAddress((void**)&vp, g_V);
    cudaGetSymbolAddress((void**)&cp, g_cos);
    cudaGetSymbolAddress((void**)&sp, g_sin);
    cudaGetSymbolAddress((void**)&x16, g_X16);
    cudaGetSymbolAddress((void**)&wp,  g_W);
    cudaGetSymbolAddress((void**)&wop, g_Wo);
    cudaGetSymbolAddress((void**)&a16, g_A16);
    cudaGetSymbolAddress((void**)&qbh, g_Qbh);
    cudaGetSymbolAddress((void**)&qbl, g_Qbl);
    cudaGetSymbolAddress((void**)&kb,  g_Kb);
    cudaGetSymbolAddress((void**)&vt,  g_Vt);

    const int M = B_ * QL_;   // 4096

    cudaFuncSetAttribute((const void*)mma_gemm<1, 0>,
                         cudaFuncAttributeMaxDynamicSharedMemorySize, MMA_SMEM_SINGLE);
    cudaFuncSetAttribute((const void*)mma_gemm<0, 0>,
                         cudaFuncAttributeMaxDynamicSharedMemorySize, MMA_SMEM_SINGLE);
    cudaFuncSetAttribute(attn_mma, cudaFuncAttributeMaxDynamicSharedMemorySize, AT_SMEM);

    // prep
    rope_table_kernel<<<(QL_ * 32 + 255) / 256, 256>>>(cp, sp, QL_);
    round_half_kernel<<<(M * HID_ + 255) / 256, 256>>>(X, x16, M * HID_);
    transpose_half_kernel<<<dim3(2048 / 32, HID_ / 32), dim3(32, 8)>>>(Wq, wp, HID_, 2048, 0);
    transpose_half_kernel<<<dim3(512 / 32,  HID_ / 32), dim3(32, 8)>>>(Wk, wp, HID_, 512, 2048);
    transpose_half_kernel<<<dim3(512 / 32,  HID_ / 32), dim3(32, 8)>>>(Wv, wp, HID_, 512, 2560);

    // fused QKV projection (A single, 1 pass), scatter to head layouts (fp32)
    mma_gemm<1, 0><<<dim3(3072 / 256, M / 128), 256, MMA_SMEM_SINGLE>>>(
        x16, nullptr, wp, qp, kp, vp, M, 3072, HID_);

    // RoPE -> Q split / K single ; V^T ; Wo transpose
    {
        int totq = B_ * NH_  * QL_ * 32;
        int totk = B_ * KVH_ * QL_ * 32;
        rope_apply_q<<<(totq + 255) / 256, 256>>>(qp, cp, sp, qbh, qbl, QL_, totq);
        rope_apply_k<<<(totk + 255) / 256, 256>>>(kp, cp, sp, kb, QL_, totk);
        vtrans_half_kernel<<<dim3(QL_ / 32, 2, B_ * KVH_), dim3(32, 8)>>>(vp, vt);
        transpose_half_kernel<<<dim3(2048 / 32, HID_ / 32), dim3(32, 8)>>>(Wo, wop, HID_, 2048, 0);
    }

    // Attention on tensor cores, single-fp16 output
    attn_mma<<<dim3(QL_ / 128, NH_, B_), 256, AT_SMEM>>>(
        qbh, qbl, kb, vt, a16);

    // Output projection (A single, 1 pass)
    mma_gemm<0, 0><<<dim3(HID_ / 256, M / 128), 256, MMA_SMEM_SINGLE>>>(
        a16, nullptr, wop, out, nullptr, nullptr, M, HID_, HID_);
}

// round 16
// speedup vs baseline: 2.3991x; 1.0062x over previous
#include <cuda_runtime.h>
#include <cuda_fp16.h>
#include <math.h>
#include <stdint.h>

// Problem constants
#define B_   2
#define QL_  2048
#define HID_ 2048
#define NH_  32
#define KVH_ 8
#define D_   64

// ===========================================================================
// PTX helpers — BASE PTX ONLY (harness targets plain sm_103: no tcgen05!)
// ===========================================================================
__device__ __forceinline__ uint32_t smem_u32(const void* p) {
    uint32_t a;
    asm("{ .reg .u64 t; cvta.to.shared.u64 t, %1; cvt.u32.u64 %0, t; }"
        : "=r"(a) : "l"(p));
    return a;
}
__device__ __forceinline__ void ldmat_x4(uint32_t* r, uint32_t addr) {
    asm volatile("ldmatrix.sync.aligned.m8n8.x4.shared.b16 {%0,%1,%2,%3}, [%4];"
                 : "=r"(r[0]), "=r"(r[1]), "=r"(r[2]), "=r"(r[3]) : "r"(addr));
}
__device__ __forceinline__ void ldmat_x2(uint32_t* r, uint32_t addr) {
    asm volatile("ldmatrix.sync.aligned.m8n8.x2.shared.b16 {%0,%1}, [%2];"
                 : "=r"(r[0]), "=r"(r[1]) : "r"(addr));
}
// fp16 MMA: D(f32) += A(f16) * B(f16)
__device__ __forceinline__ void mma_f16(float* d, const uint32_t* a, const uint32_t* b) {
    asm volatile("mma.sync.aligned.m16n8k16.row.col.f32.f16.f16.f32 "
                 "{%0,%1,%2,%3}, {%4,%5,%6,%7}, {%8,%9}, {%0,%1,%2,%3};"
                 : "+f"(d[0]), "+f"(d[1]), "+f"(d[2]), "+f"(d[3])
                 : "r"(a[0]), "r"(a[1]), "r"(a[2]), "r"(a[3]),
                   "r"(b[0]), "r"(b[1]));
}
__device__ __forceinline__ void cp_async16(uint32_t dst, const void* src) {
    asm volatile("cp.async.cg.shared.global [%0], [%1], 16;"
                 :: "r"(dst), "l"(src));
}
#define CP_COMMIT()  asm volatile("cp.async.commit_group;" ::: "memory")
#define CP_WAIT(n)   asm volatile("cp.async.wait_group %0;" :: "n"(n) : "memory")

// ===========================================================================
// Scratch (device globals — no allocation allowed)
// ===========================================================================
__device__ float g_cos[QL_ * 32];
__device__ float g_sin[QL_ * 32];
// fp16 operands
__device__ __half g_X16[(size_t)B_ * QL_ * HID_];      // X single fp16 (A of QKV gemm)
__device__ __half g_W  [(size_t)3072 * HID_];          // Wq|Wk|Wv transposed [N,K]
__device__ __half g_Wo [(size_t)HID_ * HID_];          // Wo transposed [N,K]
__device__ __half g_A16[(size_t)B_ * QL_ * HID_];      // attn out fp16 (A of Wo gemm)
__device__ __half g_Qbh[(size_t)B_ * NH_  * QL_ * D_]; // roped Q split (A of S)
__device__ __half g_Qbl[(size_t)B_ * NH_  * QL_ * D_];
__device__ __half g_Kb [(size_t)B_ * KVH_ * QL_ * D_]; // roped K single (B of S)
__device__ __half g_V16[(size_t)B_ * KVH_ * QL_ * D_]; // V fp16 [b,kvh,seq,d]
__device__ __half g_Vt [(size_t)B_ * KVH_ * D_ * QL_]; // V^T single (B of PV)

// ===========================================================================
// fp32 -> fp16 round
// ===========================================================================
__global__ void round_half_kernel(const float* __restrict__ src,
                                  __half* __restrict__ dst, int n)
{
    int i = blockIdx.x * blockDim.x + threadIdx.x;
    if (i >= n) return;
    dst[i] = __float2half_rn(src[i]);
}

// Transpose + round: W[K, Ncols] -> T[(rowOffset+n), k] fp16, ldT = K.
__global__ void transpose_half_kernel(const float* __restrict__ W,
                                      __half* __restrict__ T,
                                      int K, int Ncols, int rowOffset)
{
    __shared__ float tile[32][33];
    int k0 = blockIdx.y * 32, n0 = blockIdx.x * 32;
    int tx = threadIdx.x, ty = threadIdx.y;    // (32, 8)
#pragma unroll
    for (int i = 0; i < 4; i++) {
        int k = k0 + ty + i * 8;
        tile[ty + i * 8][tx] = W[(size_t)k * Ncols + n0 + tx];
    }
    __syncthreads();
#pragma unroll
    for (int i = 0; i < 4; i++) {
        int n = n0 + ty + i * 8;
        T[(size_t)(rowOffset + n) * K + k0 + tx] = __float2half_rn(tile[tx][ty + i * 8]);
    }
}

// V transpose (fp16 -> fp16): g_V16 [bk, seq, 64] -> Vt [bk, 64, 2048]
__global__ void vtrans_h_kernel(const __half* __restrict__ V,
                                __half* __restrict__ T)
{
    __shared__ __half tile[32][34];
    int bk = blockIdx.z;
    int s0 = blockIdx.x * 32, d0 = blockIdx.y * 32;
    int tx = threadIdx.x, ty = threadIdx.y;
    const __half* Vb = V + (size_t)bk * QL_ * 64;
#pragma unroll
    for (int i = 0; i < 4; i++) {
        int s = s0 + ty + i * 8;
        tile[ty + i * 8][tx] = Vb[(size_t)s * 64 + d0 + tx];
    }
    __syncthreads();
#pragma unroll
    for (int i = 0; i < 4; i++) {
        int d = d0 + ty + i * 8;
        T[(size_t)bk * 64 * QL_ + (size_t)d * QL_ + s0 + tx] = tile[tx][ty + i * 8];
    }
}

// ===========================================================================
// mma.sync fp16 GEMM:  C = A @ B^T, B fp16 single, A single (1 pass).
// CTA tile 128x256, 8 warps (2x4), warp tile 64x64, m16n8k16.
// K-chunks of 64, 3-stage cp.async pipeline.
// MODE 0: plain fp32 row-major C0.
// MODE 1: fused RoPE + fp16 epilogue. Each warp's 64-col slab = one head;
//         rotation pair (d, d+32) = acc[mt][nt] / acc[mt][nt+4] same thread.
//         Q -> hi/lo fp16 split; K -> roped single fp16; V -> single fp16.
// ===========================================================================
#define TILE_A   18432                       // 128 rows * 144 B
#define TILE_BB  36864                       // 256 rows * 144 B
#define MMA_SMEM_SINGLE (3 * (TILE_A + TILE_BB))       // 165888

template<int MODE>
__global__ void __launch_bounds__(256)
mma_gemm(const __half* __restrict__ Ah, const __half* __restrict__ Bh,
         float* __restrict__ C0,
         __half* __restrict__ Qh, __half* __restrict__ Ql,
         __half* __restrict__ Kh, __half* __restrict__ Vh,
         const float* __restrict__ ct, const float* __restrict__ st,
         int M, int N, int K)
{
    constexpr uint32_t STAGE = TILE_A + TILE_BB;
    extern __shared__ char smc[];
    const uint32_t sbase = smem_u32(smc);
    const int tid  = threadIdx.x;
    const int wid  = tid >> 5;
    const int lane = tid & 31;
    const int bx   = blockIdx.x;   // 256-col N tile
    const int by   = blockIdx.y;   // 128-row M tile
    const int wm   = wid >> 2;     // 0..1
    const int wn   = wid & 3;      // 0..3

    float acc[4][8][4];
#pragma unroll
    for (int mt = 0; mt < 4; mt++)
#pragma unroll
        for (int nt = 0; nt < 8; nt++)
#pragma unroll
            for (int r = 0; r < 4; r++) acc[mt][nt][r] = 0.f;

    const int NC = K >> 6;

    auto load_chunk = [&](int ci, int s) {
        const int k0 = ci * 64;
        const uint32_t sb = sbase + s * STAGE;
#pragma unroll
        for (int it = 0; it < 4; it++) {
            int f = tid + it * 256;          // 0..1023
            int r = f >> 3, seg = f & 7;
            uint32_t dst = sb + r * 144 + seg * 16;
            size_t ga = (size_t)(by * 128 + r) * K + k0 + seg * 8;
            cp_async16(dst, Ah + ga);
        }
#pragma unroll
        for (int it = 0; it < 8; it++) {
            int f = tid + it * 256;          // 0..2047
            int r = f >> 3, seg = f & 7;
            uint32_t dst = sb + TILE_A + r * 144 + seg * 16;
            size_t gb = (size_t)(bx * 256 + r) * K + k0 + seg * 8;
            cp_async16(dst, Bh + gb);
        }
        CP_COMMIT();
    };

    load_chunk(0, 0);
    if (NC > 1) load_chunk(1, 1);

    const int ar   = lane & 15;
    const int acol = (lane >> 4) * 8;
    const int br   = lane & 7;
    const int bcol = ((lane >> 3) & 1) * 8;

    for (int ci = 0; ci < NC; ci++) {
        const int s = ci % 3;
        if (ci + 2 < NC) { load_chunk(ci + 2, (ci + 2) % 3); CP_WAIT(2); }
        else if (ci + 1 < NC) { CP_WAIT(1); }
        else { CP_WAIT(0); }
        __syncthreads();

        const uint32_t sb    = sbase + s * STAGE;
        const uint32_t aBase = sb + wm * 64 * 144;
        const uint32_t bBase = sb + TILE_A + wn * 64 * 144;

#pragma unroll
        for (int ks = 0; ks < 4; ks++) {
            const int kc = ks * 16;
            uint32_t ah[4][4], bh[8][2];
#pragma unroll
            for (int mt = 0; mt < 4; mt++) {
                uint32_t a = aBase + (mt * 16 + ar) * 144 + (kc + acol) * 2;
                ldmat_x4(ah[mt], a);
            }
#pragma unroll
            for (int nt = 0; nt < 8; nt++) {
                uint32_t b = bBase + (nt * 8 + br) * 144 + (kc + bcol) * 2;
                ldmat_x2(bh[nt], b);
            }
#pragma unroll
            for (int mt = 0; mt < 4; mt++)
#pragma unroll
                for (int nt = 0; nt < 8; nt++)
                    mma_f16(acc[mt][nt], ah[mt], bh[nt]);
        }
        __syncthreads();
    }

    const int lrow = lane >> 2;
    const int lcol = (lane & 3) * 2;

    if (MODE == 0) {
#pragma unroll
        for (int mt = 0; mt < 4; mt++) {
#pragma unroll
            for (int nt = 0; nt < 8; nt++) {
                int row0 = by * 128 + wm * 64 + mt * 16 + lrow;
                int col  = bx * 256 + wn * 64 + nt * 8 + lcol;
#pragma unroll
                for (int half = 0; half < 2; half++) {
                    int m = row0 + half * 8;
                    *(float2*)&C0[(size_t)m * N + col] =
                        make_float2(acc[mt][nt][half * 2], acc[mt][nt][half * 2 + 1]);
                }
            }
        }
    } else {
        // ---- fused RoPE + fp16 epilogue ----
        // Stage cos/sin rows for this tile's 128 tokens (32 KB SMEM).
        float* sc = (float*)smc;
        float* ss = sc + 128 * 32;
        const int t0 = (by * 128) & (QL_ - 1);
        const int bb = (by * 128) >> 11;
        for (int i = tid; i < 128 * 32; i += 256) {
            int idx = (t0 + (i >> 5)) * 32 + (i & 31);
            sc[i] = ct[idx];
            ss[i] = st[idx];
        }
        __syncthreads();

#pragma unroll
        for (int mt = 0; mt < 4; mt++) {
#pragma unroll
            for (int half = 0; half < 2; half++) {
                const int lt = wm * 64 + mt * 16 + lrow + half * 8;
                const int t  = t0 + lt;
#pragma unroll
                for (int ntp = 0; ntp < 4; ntp++) {
                    const int colbase = bx * 256 + wn * 64 + ntp * 8 + lcol;
                    const int d = colbase & 31;     // ntp*8+lcol < 32
                    float v1a = acc[mt][ntp][half * 2];
                    float v1b = acc[mt][ntp][half * 2 + 1];
                    float v2a = acc[mt][ntp + 4][half * 2];
                    float v2b = acc[mt][ntp + 4][half * 2 + 1];

                    if (colbase < 2560) {           // Q or K: apply RoPE
                        float c0v = sc[lt * 32 + d],     s0v = ss[lt * 32 + d];
                        float c1v = sc[lt * 32 + d + 1], s1v = ss[lt * 32 + d + 1];
                        float r1a = v1a * c0v - v2a * s0v;
                        float r2a = v2a * c0v + v1a * s0v;
                        float r1b = v1b * c1v - v2b * s1v;
                        float r2b = v2b * c1v + v1b * s1v;
                        if (colbase < 2048) {       // Q: hi/lo split
                            int h = colbase >> 6;
                            size_t base = ((((size_t)bb * NH_ + h) * QL_ + t) << 6);
                            __half2 h1 = __floats2half2_rn(r1a, r1b);
                            __half2 h2 = __floats2half2_rn(r2a, r2b);
                            *(__half2*)&Qh[base + d]      = h1;
                            *(__half2*)&Qh[base + d + 32] = h2;
                            __half2 l1 = __floats2half2_rn(
                                r1a - __half2float(h1.x), r1b - __half2float(h1.y));
                            __half2 l2 = __floats2half2_rn(
                                r2a - __half2float(h2.x), r2b - __half2float(h2.y));
                            *(__half2*)&Ql[base + d]      = l1;
                            *(__half2*)&Ql[base + d + 32] = l2;
                        } else {                    // K: single fp16
                            int h = (colbase - 2048) >> 6;
                            size_t base = ((((size_t)bb * KVH_ + h) * QL_ + t) << 6);
                            *(__half2*)&Kh[base + d]      = __floats2half2_rn(r1a, r1b);
                            *(__half2*)&Kh[base + d + 32] = __floats2half2_rn(r2a, r2b);
                        }
                    } else {                        // V: no RoPE, single fp16
                        int h = (colbase - 2560) >> 6;
                        size_t base = ((((size_t)bb * KVH_ + h) * QL_ + t) << 6);
                        *(__half2*)&Vh[base + d]      = __floats2half2_rn(v1a, v1b);
                        *(__half2*)&Vh[base + d + 32] = __floats2half2_rn(v2a, v2b);
                    }
                }
            }
        }
    }
}

// ===========================================================================
// RoPE table (fp64 trig once — --use_fast_math breaks sincosf at ~2000 rad)
// ===========================================================================
__global__ void rope_table_kernel(float* __restrict__ ct, float* __restrict__ st,
                                  int Q)
{
    int idx = blockIdx.x * blockDim.x + threadIdx.x;
    if (idx >= Q * 32) return;
    int j = idx & 31;
    int t = idx >> 5;
    float freq = (float)(1.0 / pow(10000.0, (double)(2 * j) / 64.0));
    float ang  = (float)t * freq;
    double cd, sd;
    sincos((double)ang, &sd, &cd);
    ct[idx] = (float)cd;
    st[idx] = (float)sd;
}

// ===========================================================================
// Flash attention, fp16. S: 2 passes (Q split). PV: 1 pass (P single).
// Output: single fp16 [b*Q + q, h*64 + d].
// Grid (QL/128, NH, B), 256 thr, 8 warps.
// ===========================================================================
#define AT_KTILE 9216                  // 64 rows * 144 B
#define AT_STAGE (2 * AT_KTILE)        // 18432
#define AT_Q_OFF (2 * AT_STAGE)        // 36864
#define AT_SMEM  (AT_Q_OFF + 2 * 128 * 144)   // 73728

__global__ void __launch_bounds__(256, 2)
attn_mma(const __half* __restrict__ Qh, const __half* __restrict__ Ql,
         const __half* __restrict__ Kh, const __half* __restrict__ Vt,
         __half* __restrict__ O)
{
    extern __shared__ char smc[];
    const uint32_t sbase = smem_u32(smc);
    const int tid  = threadIdx.x;
    const int wid  = tid >> 5;
    const int lane = tid & 31;
    const int qt   = blockIdx.x;
    const int h    = blockIdx.y;
    const int b    = blockIdx.z;
    const int kvh  = h >> 2;           // NH/KVH = 4
    const int q0   = qt * 128;

    const __half* Qgh = Qh + (((size_t)b * NH_ + h) * QL_ + q0) * 64;
    const __half* Qgl = Ql + (((size_t)b * NH_ + h) * QL_ + q0) * 64;
    const __half* Kg  = Kh + (((size_t)b * KVH_ + kvh) * QL_) * 64;
    const __half* Vg  = Vt + (((size_t)b * KVH_ + kvh) * 64) * QL_;

#pragma unroll
    for (int it = 0; it < 4; it++) {
        int f = tid + it * 256;
        int r = f >> 3, seg = f & 7;
        uint32_t dst = sbase + AT_Q_OFF + r * 144 + seg * 16;
        cp_async16(dst,             Qgh + (size_t)r * 64 + seg * 8);
        cp_async16(dst + 128 * 144, Qgl + (size_t)r * 64 + seg * 8);
    }
    CP_COMMIT();

    auto load_kv = [&](int kt, int s) {
        const int k0 = kt * 64;
        const uint32_t sb = sbase + s * AT_STAGE;
#pragma unroll
        for (int it = 0; it < 2; it++) {
            int f = tid + it * 256;
            int r = f >> 3, seg = f & 7;
            uint32_t dst = sb + r * 144 + seg * 16;
            cp_async16(dst,            Kg + (size_t)(k0 + r) * 64 + seg * 8);
            cp_async16(dst + AT_KTILE, Vg + (size_t)r * QL_ + k0 + seg * 8);
        }
        CP_COMMIT();
    };

    load_kv(0, 0);

    CP_WAIT(1);
    __syncthreads();

    const int ar   = lane & 15;
    const int acol = (lane >> 4) * 8;
    const int br   = lane & 7;
    const int bcol = ((lane >> 3) & 1) * 8;

    uint32_t qfh[4][4], qfl[4][4];
    {
        uint32_t qBase = sbase + AT_Q_OFF + (wid * 16 + ar) * 144;
#pragma unroll
        for (int ks = 0; ks < 4; ks++) {
            uint32_t a = qBase + (ks * 16 + acol) * 2;
            ldmat_x4(qfh[ks], a);
            ldmat_x4(qfl[ks], a + 128 * 144);
        }
    }

    float o[8][4];
#pragma unroll
    for (int nt = 0; nt < 8; nt++)
#pragma unroll
        for (int j = 0; j < 4; j++) o[nt][j] = 0.f;
    float m0 = -1e30f, m1 = -1e30f, l0 = 0.f, l1 = 0.f;

    const int ktiles = qt * 2 + 2;
    const int qg0 = q0 + wid * 16 + (lane >> 2);
    const int qg1 = qg0 + 8;
    const int lc2 = (lane & 3) * 2;

    for (int kt = 0; kt < ktiles; kt++) {
        const int s = kt & 1;
        if (kt + 1 < ktiles) { load_kv(kt + 1, s ^ 1); CP_WAIT(1); }
        else                 { CP_WAIT(0); }
        __syncthreads();

        const uint32_t kb = sbase + s * AT_STAGE;
        const uint32_t vb = kb + AT_KTILE;
        const int k0 = kt * 64;

        // ---- S = Q K^T (2 passes: Qhi*K + Qlo*K) ----
        float sf[8][4];
#pragma unroll
        for (int nt = 0; nt < 8; nt++)
#pragma unroll
            for (int j = 0; j < 4; j++) sf[nt][j] = 0.f;

#pragma unroll
        for (int ks = 0; ks < 4; ks++) {
            uint32_t bh[8][2];
#pragma unroll
            for (int nt = 0; nt < 8; nt++) {
                uint32_t a = kb + (nt * 8 + br) * 144 + (ks * 16 + bcol) * 2;
                ldmat_x2(bh[nt], a);
            }
#pragma unroll
            for (int nt = 0; nt < 8; nt++) mma_f16(sf[nt], qfh[ks], bh[nt]);
#pragma unroll
            for (int nt = 0; nt < 8; nt++) mma_f16(sf[nt], qfl[ks], bh[nt]);
        }

        // ---- scale + causal mask + row max ----
        const bool domask = (kt >= ktiles - 2);
        float rm0 = -1e30f, rm1 = -1e30f;
#pragma unroll
        for (int nt = 0; nt < 8; nt++) {
            int kg = k0 + nt * 8 + lc2;
#pragma unroll
            for (int j = 0; j < 4; j++) {
                float v = sf[nt][j] * 0.125f;
                if (domask) {
                    int kcol = kg + (j & 1);
                    int qrow = (j < 2) ? qg0 : qg1;
                    if (kcol > qrow) v = -1e30f;
                }
                sf[nt][j] = v;
                if (j < 2) rm0 = fmaxf(rm0, v); else rm1 = fmaxf(rm1, v);
            }
        }
        rm0 = fmaxf(rm0, __shfl_xor_sync(0xffffffffu, rm0, 1));
        rm0 = fmaxf(rm0, __shfl_xor_sync(0xffffffffu, rm0, 2));
        rm1 = fmaxf(rm1, __shfl_xor_sync(0xffffffffu, rm1, 1));
        rm1 = fmaxf(rm1, __shfl_xor_sync(0xffffffffu, rm1, 2));

        float nm0 = fmaxf(m0, rm0), nm1 = fmaxf(m1, rm1);
        float c0 = __expf(m0 - nm0), c1 = __expf(m1 - nm1);

        // ---- exp + row sum + pack P (single fp16) ----
        float rs0 = 0.f, rs1 = 0.f;
        uint32_t ph[8][2];
#pragma unroll
        for (int nt = 0; nt < 8; nt++) {
            float p0 = __expf(sf[nt][0] - nm0);
            float p1 = __expf(sf[nt][1] - nm0);
            float p2 = __expf(sf[nt][2] - nm1);
            float p3 = __expf(sf[nt][3] - nm1);
            rs0 += p0 + p1;
            rs1 += p2 + p3;
            __half2 h01 = __floats2half2_rn(p0, p1);
            __half2 h23 = __floats2half2_rn(p2, p3);
            ph[nt][0] = *(uint32_t*)&h01;
            ph[nt][1] = *(uint32_t*)&h23;
        }
        rs0 += __shfl_xor_sync(0xffffffffu, rs0, 1);
        rs0 += __shfl_xor_sync(0xffffffffu, rs0, 2);
        rs1 += __shfl_xor_sync(0xffffffffu, rs1, 1);
        rs1 += __shfl_xor_sync(0xffffffffu, rs1, 2);

        l0 = l0 * c0 + rs0;
        l1 = l1 * c1 + rs1;
        m0 = nm0;
        m1 = nm1;

#pragma unroll
        for (int nt = 0; nt < 8; nt++) {
            o[nt][0] *= c0; o[nt][1] *= c0;
            o[nt][2] *= c1; o[nt][3] *= c1;
        }

        // ---- O += P V (single pass) ----
#pragma unroll
        for (int ks = 0; ks < 4; ks++) {
            uint32_t bh[8][2];
#pragma unroll
            for (int nt = 0; nt < 8; nt++) {
                uint32_t a = vb + (nt * 8 + br) * 144 + (ks * 16 + bcol) * 2;
                ldmat_x2(bh[nt], a);
            }
            uint32_t pah[4] = {ph[2 * ks][0], ph[2 * ks][1],
                               ph[2 * ks + 1][0], ph[2 * ks + 1][1]};
#pragma unroll
            for (int nt = 0; nt < 8; nt++) mma_f16(o[nt], pah, bh[nt]);
        }
        __syncthreads();
    }

    // ---- epilogue: O/l -> single fp16, [b*Q + q, h*64 + d] ----
    float inv0 = 1.0f / l0, inv1 = 1.0f / l1;
    int gr0 = b * QL_ + q0 + wid * 16 + (lane >> 2);
    int gr1 = gr0 + 8;
#pragma unroll
    for (int nt = 0; nt < 8; nt++) {
        int gc = h * 64 + nt * 8 + lc2;
        __half2 h01 = __floats2half2_rn(o[nt][0] * inv0, o[nt][1] * inv0);
        __half2 h23 = __floats2half2_rn(o[nt][2] * inv1, o[nt][3] * inv1);
        *(__half2*)&O[(size_t)gr0 * HID_ + gc] = h01;
        *(__half2*)&O[(size_t)gr1 * HID_ + gc] = h23;
    }
}

// ===========================================================================
extern "C" void kernel_launch(void* const* d_in, const int* in_sizes, int n_in,
                              void* d_out, int out_size)
{
    const float* X  = (const float*)d_in[0];
    const float* Wq = (const float*)d_in[2];
    const float* Wk = (const float*)d_in[3];
    const float* Wv = (const float*)d_in[4];
    const float* Wo = (const float*)d_in[5];
    float* out = (float*)d_out;

    float *cp, *sp;
    __half *x16, *wp, *wop, *a16, *qbh, *qbl, *kb, *v16, *vt;
    cudaGetSymbolAddress((void**)&cp, g_cos);
    cudaGetSymbolAddress((void**)&sp, g_sin);
    cudaGetSymbolAddress((void**)&x16, g_X16);
    cudaGetSymbolAddress((void**)&wp,  g_W);
    cudaGetSymbolAddress((void**)&wop, g_Wo);
    cudaGetSymbolAddress((void**)&a16, g_A16);
    cudaGetSymbolAddress((void**)&qbh, g_Qbh);
    cudaGetSymbolAddress((void**)&qbl, g_Qbl);
    cudaGetSymbolAddress((void**)&kb,  g_Kb);
    cudaGetSymbolAddress((void**)&v16, g_V16);
    cudaGetSymbolAddress((void**)&vt,  g_Vt);

    const int M = B_ * QL_;   // 4096

    cudaFuncSetAttribute((const void*)mma_gemm<1>,
                         cudaFuncAttributeMaxDynamicSharedMemorySize, MMA_SMEM_SINGLE);
    cudaFuncSetAttribute((const void*)mma_gemm<0>,
                         cudaFuncAttributeMaxDynamicSharedMemorySize, MMA_SMEM_SINGLE);
    cudaFuncSetAttribute(attn_mma, cudaFuncAttributeMaxDynamicSharedMemorySize, AT_SMEM);

    // prep (rope table must precede QKV gemm — its epilogue consumes it)
    rope_table_kernel<<<(QL_ * 32 + 255) / 256, 256>>>(cp, sp, QL_);
    round_half_kernel<<<(M * HID_ + 255) / 256, 256>>>(X, x16, M * HID_);
    transpose_half_kernel<<<dim3(2048 / 32, HID_ / 32), dim3(32, 8)>>>(Wq, wp, HID_, 2048, 0);
    transpose_half_kernel<<<dim3(512 / 32,  HID_ / 32), dim3(32, 8)>>>(Wk, wp, HID_, 512, 2048);
    transpose_half_kernel<<<dim3(512 / 32,  HID_ / 32), dim3(32, 8)>>>(Wv, wp, HID_, 512, 2560);

    // fused QKV projection + RoPE + fp16 conversion (single pass)
    mma_gemm<1><<<dim3(3072 / 256, M / 128), 256, MMA_SMEM_SINGLE>>>(
        x16, wp, nullptr, qbh, qbl, kb, v16, cp, sp, M, 3072, HID_);

    // V^T ; Wo transpose
    vtrans_h_kernel<<<dim3(QL_ / 32, 2, B_ * KVH_), dim3(32, 8)>>>(v16, vt);
    transpose_half_kernel<<<dim3(2048 / 32, HID_ / 32), dim3(32, 8)>>>(Wo, wop, HID_, 2048, 0);

    // Attention on tensor cores, single-fp16 output
    attn_mma<<<dim3(QL_ / 128, NH_, B_), 256, AT_SMEM>>>(
        qbh, qbl, kb, vt, a16);

    // Output projection (A single, 1 pass)
    mma_gemm<0><<<dim3(HID_ / 256, M / 128), 256, MMA_SMEM_SINGLE>>>(
        a16, wop, out, nullptr, nullptr, nullptr, nullptr, nullptr, nullptr,
        M, HID_, HID_);
}

// round 17
// speedup vs baseline: 2.5809x; 1.0758x over previous
#include <cuda_runtime.h>
#include <cuda_fp16.h>
#include <math.h>
#include <stdint.h>

// Problem constants
#define B_   2
#define QL_  2048
#define HID_ 2048
#define NH_  32
#define KVH_ 8
#define D_   64

// ===========================================================================
// PTX helpers — BASE PTX ONLY (harness targets plain sm_103: no tcgen05!)
// ===========================================================================
__device__ __forceinline__ uint32_t smem_u32(const void* p) {
    uint32_t a;
    asm("{ .reg .u64 t; cvta.to.shared.u64 t, %1; cvt.u32.u64 %0, t; }"
        : "=r"(a) : "l"(p));
    return a;
}
__device__ __forceinline__ void ldmat_x4(uint32_t* r, uint32_t addr) {
    asm volatile("ldmatrix.sync.aligned.m8n8.x4.shared.b16 {%0,%1,%2,%3}, [%4];"
                 : "=r"(r[0]), "=r"(r[1]), "=r"(r[2]), "=r"(r[3]) : "r"(addr));
}
__device__ __forceinline__ void ldmat_x2(uint32_t* r, uint32_t addr) {
    asm volatile("ldmatrix.sync.aligned.m8n8.x2.shared.b16 {%0,%1}, [%2];"
                 : "=r"(r[0]), "=r"(r[1]) : "r"(addr));
}
// fp16 MMA: D(f32) += A(f16) * B(f16)
__device__ __forceinline__ void mma_f16(float* d, const uint32_t* a, const uint32_t* b) {
    asm volatile("mma.sync.aligned.m16n8k16.row.col.f32.f16.f16.f32 "
                 "{%0,%1,%2,%3}, {%4,%5,%6,%7}, {%8,%9}, {%0,%1,%2,%3};"
                 : "+f"(d[0]), "+f"(d[1]), "+f"(d[2]), "+f"(d[3])
                 : "r"(a[0]), "r"(a[1]), "r"(a[2]), "r"(a[3]),
                   "r"(b[0]), "r"(b[1]));
}
__device__ __forceinline__ void cp_async16(uint32_t dst, const void* src) {
    asm volatile("cp.async.cg.shared.global [%0], [%1], 16;"
                 :: "r"(dst), "l"(src));
}
#define CP_COMMIT()  asm volatile("cp.async.commit_group;" ::: "memory")
#define CP_WAIT(n)   asm volatile("cp.async.wait_group %0;" :: "n"(n) : "memory")

// ===========================================================================
// Scratch (device globals — no allocation allowed)
// ===========================================================================
__device__ float g_cos[QL_ * 32];
__device__ float g_sin[QL_ * 32];
// fp16 operands
__device__ __half g_X16[(size_t)B_ * QL_ * HID_];      // X single fp16 (A of QKV gemm)
__device__ __half g_W  [(size_t)3072 * HID_];          // Wq|Wk|Wv transposed [N,K]
__device__ __half g_Wo [(size_t)HID_ * HID_];          // Wo transposed [N,K]
__device__ __half g_A16[(size_t)B_ * QL_ * HID_];      // attn out fp16 (A of Wo gemm)
__device__ __half g_Qb [(size_t)B_ * NH_  * QL_ * D_]; // roped Q single fp16 (A of S)
__device__ __half g_Kb [(size_t)B_ * KVH_ * QL_ * D_]; // roped K single (B of S)
__device__ __half g_V16[(size_t)B_ * KVH_ * QL_ * D_]; // V fp16 [b,kvh,seq,d]
__device__ __half g_Vt [(size_t)B_ * KVH_ * D_ * QL_]; // V^T single (B of PV)

// ===========================================================================
// fp32 -> fp16 round
// ===========================================================================
__global__ void round_half_kernel(const float* __restrict__ src,
                                  __half* __restrict__ dst, int n)
{
    int i = blockIdx.x * blockDim.x + threadIdx.x;
    if (i >= n) return;
    dst[i] = __float2half_rn(src[i]);
}

// Transpose + round: W[K, Ncols] -> T[(rowOffset+n), k] fp16, ldT = K.
__global__ void transpose_half_kernel(const float* __restrict__ W,
                                      __half* __restrict__ T,
                                      int K, int Ncols, int rowOffset)
{
    __shared__ float tile[32][33];
    int k0 = blockIdx.y * 32, n0 = blockIdx.x * 32;
    int tx = threadIdx.x, ty = threadIdx.y;    // (32, 8)
#pragma unroll
    for (int i = 0; i < 4; i++) {
        int k = k0 + ty + i * 8;
        tile[ty + i * 8][tx] = W[(size_t)k * Ncols + n0 + tx];
    }
    __syncthreads();
#pragma unroll
    for (int i = 0; i < 4; i++) {
        int n = n0 + ty + i * 8;
        T[(size_t)(rowOffset + n) * K + k0 + tx] = __float2half_rn(tile[tx][ty + i * 8]);
    }
}

// V transpose (fp16 -> fp16): g_V16 [bk, seq, 64] -> Vt [bk, 64, 2048]
__global__ void vtrans_h_kernel(const __half* __restrict__ V,
                                __half* __restrict__ T)
{
    __shared__ __half tile[32][34];
    int bk = blockIdx.z;
    int s0 = blockIdx.x * 32, d0 = blockIdx.y * 32;
    int tx = threadIdx.x, ty = threadIdx.y;
    const __half* Vb = V + (size_t)bk * QL_ * 64;
#pragma unroll
    for (int i = 0; i < 4; i++) {
        int s = s0 + ty + i * 8;
        tile[ty + i * 8][tx] = Vb[(size_t)s * 64 + d0 + tx];
    }
    __syncthreads();
#pragma unroll
    for (int i = 0; i < 4; i++) {
        int d = d0 + ty + i * 8;
        T[(size_t)bk * 64 * QL_ + (size_t)d * QL_ + s0 + tx] = tile[tx][ty + i * 8];
    }
}

// ===========================================================================
// mma.sync fp16 GEMM:  C = A @ B^T, A and B single fp16 (1 pass).
// CTA tile 128x256, 8 warps (2x4), warp tile 64x64, m16n8k16.
// K-chunks of 64, 3-stage cp.async pipeline.
// MODE 0: plain fp32 row-major C0.
// MODE 1: fused RoPE + fp16 epilogue. Each warp's 64-col slab = one head;
//         rotation pair (d, d+32) = acc[mt][nt] / acc[mt][nt+4] same thread.
//         Q -> roped single fp16; K -> roped single fp16; V -> single fp16.
// ===========================================================================
#define TILE_A   18432                       // 128 rows * 144 B
#define TILE_BB  36864                       // 256 rows * 144 B
#define MMA_SMEM_SINGLE (3 * (TILE_A + TILE_BB))       // 165888

template<int MODE>
__global__ void __launch_bounds__(256)
mma_gemm(const __half* __restrict__ Ah, const __half* __restrict__ Bh,
         float* __restrict__ C0,
         __half* __restrict__ Qh, __half* __restrict__ Kh, __half* __restrict__ Vh,
         const float* __restrict__ ct, const float* __restrict__ st,
         int M, int N, int K)
{
    constexpr uint32_t STAGE = TILE_A + TILE_BB;
    extern __shared__ char smc[];
    const uint32_t sbase = smem_u32(smc);
    const int tid  = threadIdx.x;
    const int wid  = tid >> 5;
    const int lane = tid & 31;
    const int bx   = blockIdx.x;   // 256-col N tile
    const int by   = blockIdx.y;   // 128-row M tile
    const int wm   = wid >> 2;     // 0..1
    const int wn   = wid & 3;      // 0..3

    float acc[4][8][4];
#pragma unroll
    for (int mt = 0; mt < 4; mt++)
#pragma unroll
        for (int nt = 0; nt < 8; nt++)
#pragma unroll
            for (int r = 0; r < 4; r++) acc[mt][nt][r] = 0.f;

    const int NC = K >> 6;

    auto load_chunk = [&](int ci, int s) {
        const int k0 = ci * 64;
        const uint32_t sb = sbase + s * STAGE;
#pragma unroll
        for (int it = 0; it < 4; it++) {
            int f = tid + it * 256;          // 0..1023
            int r = f >> 3, seg = f & 7;
            uint32_t dst = sb + r * 144 + seg * 16;
            size_t ga = (size_t)(by * 128 + r) * K + k0 + seg * 8;
            cp_async16(dst, Ah + ga);
        }
#pragma unroll
        for (int it = 0; it < 8; it++) {
            int f = tid + it * 256;          // 0..2047
            int r = f >> 3, seg = f & 7;
            uint32_t dst = sb + TILE_A + r * 144 + seg * 16;
            size_t gb = (size_t)(bx * 256 + r) * K + k0 + seg * 8;
            cp_async16(dst, Bh + gb);
        }
        CP_COMMIT();
    };

    load_chunk(0, 0);
    if (NC > 1) load_chunk(1, 1);

    const int ar   = lane & 15;
    const int acol = (lane >> 4) * 8;
    const int br   = lane & 7;
    const int bcol = ((lane >> 3) & 1) * 8;

    for (int ci = 0; ci < NC; ci++) {
        const int s = ci % 3;
        if (ci + 2 < NC) { load_chunk(ci + 2, (ci + 2) % 3); CP_WAIT(2); }
        else if (ci + 1 < NC) { CP_WAIT(1); }
        else { CP_WAIT(0); }
        __syncthreads();

        const uint32_t sb    = sbase + s * STAGE;
        const uint32_t aBase = sb + wm * 64 * 144;
        const uint32_t bBase = sb + TILE_A + wn * 64 * 144;

#pragma unroll
        for (int ks = 0; ks < 4; ks++) {
            const int kc = ks * 16;
            uint32_t ah[4][4], bh[8][2];
#pragma unroll
            for (int mt = 0; mt < 4; mt++) {
                uint32_t a = aBase + (mt * 16 + ar) * 144 + (kc + acol) * 2;
                ldmat_x4(ah[mt], a);
            }
#pragma unroll
            for (int nt = 0; nt < 8; nt++) {
                uint32_t b = bBase + (nt * 8 + br) * 144 + (kc + bcol) * 2;
                ldmat_x2(bh[nt], b);
            }
#pragma unroll
            for (int mt = 0; mt < 4; mt++)
#pragma unroll
                for (int nt = 0; nt < 8; nt++)
                    mma_f16(acc[mt][nt], ah[mt], bh[nt]);
        }
        __syncthreads();
    }

    const int lrow = lane >> 2;
    const int lcol = (lane & 3) * 2;

    if (MODE == 0) {
#pragma unroll
        for (int mt = 0; mt < 4; mt++) {
#pragma unroll
            for (int nt = 0; nt < 8; nt++) {
                int row0 = by * 128 + wm * 64 + mt * 16 + lrow;
                int col  = bx * 256 + wn * 64 + nt * 8 + lcol;
#pragma unroll
                for (int half = 0; half < 2; half++) {
                    int m = row0 + half * 8;
                    *(float2*)&C0[(size_t)m * N + col] =
                        make_float2(acc[mt][nt][half * 2], acc[mt][nt][half * 2 + 1]);
                }
            }
        }
    } else {
        // ---- fused RoPE + fp16 epilogue ----
        float* sc = (float*)smc;
        float* ss = sc + 128 * 32;
        const int t0 = (by * 128) & (QL_ - 1);
        const int bb = (by * 128) >> 11;
        for (int i = tid; i < 128 * 32; i += 256) {
            int idx = (t0 + (i >> 5)) * 32 + (i & 31);
            sc[i] = ct[idx];
            ss[i] = st[idx];
        }
        __syncthreads();

#pragma unroll
        for (int mt = 0; mt < 4; mt++) {
#pragma unroll
            for (int half = 0; half < 2; half++) {
                const int lt = wm * 64 + mt * 16 + lrow + half * 8;
                const int t  = t0 + lt;
#pragma unroll
                for (int ntp = 0; ntp < 4; ntp++) {
                    const int colbase = bx * 256 + wn * 64 + ntp * 8 + lcol;
                    const int d = colbase & 31;     // ntp*8+lcol < 32
                    float v1a = acc[mt][ntp][half * 2];
                    float v1b = acc[mt][ntp][half * 2 + 1];
                    float v2a = acc[mt][ntp + 4][half * 2];
                    float v2b = acc[mt][ntp + 4][half * 2 + 1];

                    if (colbase < 2560) {           // Q or K: apply RoPE
                        float c0v = sc[lt * 32 + d],     s0v = ss[lt * 32 + d];
                        float c1v = sc[lt * 32 + d + 1], s1v = ss[lt * 32 + d + 1];
                        float r1a = v1a * c0v - v2a * s0v;
                        float r2a = v2a * c0v + v1a * s0v;
                        float r1b = v1b * c1v - v2b * s1v;
                        float r2b = v2b * c1v + v1b * s1v;
                        if (colbase < 2048) {       // Q: single fp16
                            int h = colbase >> 6;
                            size_t base = ((((size_t)bb * NH_ + h) * QL_ + t) << 6);
                            *(__half2*)&Qh[base + d]      = __floats2half2_rn(r1a, r1b);
                            *(__half2*)&Qh[base + d + 32] = __floats2half2_rn(r2a, r2b);
                        } else {                    // K: single fp16
                            int h = (colbase - 2048) >> 6;
                            size_t base = ((((size_t)bb * KVH_ + h) * QL_ + t) << 6);
                            *(__half2*)&Kh[base + d]      = __floats2half2_rn(r1a, r1b);
                            *(__half2*)&Kh[base + d + 32] = __floats2half2_rn(r2a, r2b);
                        }
                    } else {                        // V: no RoPE, single fp16
                        int h = (colbase - 2560) >> 6;
                        size_t base = ((((size_t)bb * KVH_ + h) * QL_ + t) << 6);
                        *(__half2*)&Vh[base + d]      = __floats2half2_rn(v1a, v1b);
                        *(__half2*)&Vh[base + d + 32] = __floats2half2_rn(v2a, v2b);
                    }
                }
            }
        }
    }
}

// ===========================================================================
// RoPE table (fp64 trig once — --use_fast_math breaks sincosf at ~2000 rad)
// ===========================================================================
__global__ void rope_table_kernel(float* __restrict__ ct, float* __restrict__ st,
                                  int Q)
{
    int idx = blockIdx.x * blockDim.x + threadIdx.x;
    if (idx >= Q * 32) return;
    int j = idx & 31;
    int t = idx >> 5;
    float freq = (float)(1.0 / pow(10000.0, (double)(2 * j) / 64.0));
    float ang  = (float)t * freq;
    double cd, sd;
    sincos((double)ang, &sd, &cd);
    ct[idx] = (float)cd;
    st[idx] = (float)sd;
}

// ===========================================================================
// Flash attention, fp16, all single-precision operands (1 pass per MMA).
// Output: single fp16 [b*Q + q, h*64 + d].
// Grid (QL/128, NH, B), 256 thr, 8 warps.
// SMEM: 2 stages x {K,V}[64][72h] + Q[128][72h] = 55296 B -> 2 CTA/SM.
// ===========================================================================
#define AT_KTILE 9216                  // 64 rows * 144 B
#define AT_STAGE (2 * AT_KTILE)        // 18432
#define AT_Q_OFF (2 * AT_STAGE)        // 36864
#define AT_SMEM  (AT_Q_OFF + 128 * 144)   // 55296

__global__ void __launch_bounds__(256, 2)
attn_mma(const __half* __restrict__ Qh, const __half* __restrict__ Kh,
         const __half* __restrict__ Vt, __half* __restrict__ O)
{
    extern __shared__ char smc[];
    const uint32_t sbase = smem_u32(smc);
    const int tid  = threadIdx.x;
    const int wid  = tid >> 5;
    const int lane = tid & 31;
    const int qt   = blockIdx.x;
    const int h    = blockIdx.y;
    const int b    = blockIdx.z;
    const int kvh  = h >> 2;           // NH/KVH = 4
    const int q0   = qt * 128;

    const __half* Qg = Qh + (((size_t)b * NH_ + h) * QL_ + q0) * 64;
    const __half* Kg = Kh + (((size_t)b * KVH_ + kvh) * QL_) * 64;
    const __half* Vg = Vt + (((size_t)b * KVH_ + kvh) * 64) * QL_;

#pragma unroll
    for (int it = 0; it < 2; it++) {
        int f = tid + it * 256;        // 0..511
        int r = f >> 2, seg = f & 3;   // 128 rows x 4 segs? No: 128*64*2B = 16KB = 1024 x16B
        (void)r; (void)seg;
    }
    // Q: 128 rows x 8 segs of 16B = 1024 cp.async
#pragma unroll
    for (int it = 0; it < 4; it++) {
        int f = tid + it * 256;
        int r = f >> 3, seg = f & 7;
        uint32_t dst = sbase + AT_Q_OFF + r * 144 + seg * 16;
        cp_async16(dst, Qg + (size_t)r * 64 + seg * 8);
    }
    CP_COMMIT();

    auto load_kv = [&](int kt, int s) {
        const int k0 = kt * 64;
        const uint32_t sb = sbase + s * AT_STAGE;
#pragma unroll
        for (int it = 0; it < 2; it++) {
            int f = tid + it * 256;
            int r = f >> 3, seg = f & 7;
            uint32_t dst = sb + r * 144 + seg * 16;
            cp_async16(dst,            Kg + (size_t)(k0 + r) * 64 + seg * 8);
            cp_async16(dst + AT_KTILE, Vg + (size_t)r * QL_ + k0 + seg * 8);
        }
        CP_COMMIT();
    };

    load_kv(0, 0);

    CP_WAIT(1);
    __syncthreads();

    const int ar   = lane & 15;
    const int acol = (lane >> 4) * 8;
    const int br   = lane & 7;
    const int bcol = ((lane >> 3) & 1) * 8;

    uint32_t qf[4][4];
    {
        uint32_t qBase = sbase + AT_Q_OFF + (wid * 16 + ar) * 144;
#pragma unroll
        for (int ks = 0; ks < 4; ks++)
            ldmat_x4(qf[ks], qBase + (ks * 16 + acol) * 2);
    }

    float o[8][4];
#pragma unroll
    for (int nt = 0; nt < 8; nt++)
#pragma unroll
        for (int j = 0; j < 4; j++) o[nt][j] = 0.f;
    float m0 = -1e30f, m1 = -1e30f, l0 = 0.f, l1 = 0.f;

    const int ktiles = qt * 2 + 2;
    const int qg0 = q0 + wid * 16 + (lane >> 2);
    const int qg1 = qg0 + 8;
    const int lc2 = (lane & 3) * 2;

    for (int kt = 0; kt < ktiles; kt++) {
        const int s = kt & 1;
        if (kt + 1 < ktiles) { load_kv(kt + 1, s ^ 1); CP_WAIT(1); }
        else                 { CP_WAIT(0); }
        __syncthreads();

        const uint32_t kb = sbase + s * AT_STAGE;
        const uint32_t vb = kb + AT_KTILE;
        const int k0 = kt * 64;

        // ---- S = Q K^T (single pass) ----
        float sf[8][4];
#pragma unroll
        for (int nt = 0; nt < 8; nt++)
#pragma unroll
            for (int j = 0; j < 4; j++) sf[nt][j] = 0.f;

#pragma unroll
        for (int ks = 0; ks < 4; ks++) {
            uint32_t bh[8][2];
#pragma unroll
            for (int nt = 0; nt < 8; nt++) {
                uint32_t a = kb + (nt * 8 + br) * 144 + (ks * 16 + bcol) * 2;
                ldmat_x2(bh[nt], a);
            }
#pragma unroll
            for (int nt = 0; nt < 8; nt++) mma_f16(sf[nt], qf[ks], bh[nt]);
        }

        // ---- scale + causal mask + row max ----
        const bool domask = (kt >= ktiles - 2);
        float rm0 = -1e30f, rm1 = -1e30f;
#pragma unroll
        for (int nt = 0; nt < 8; nt++) {
            int kg = k0 + nt * 8 + lc2;
#pragma unroll
            for (int j = 0; j < 4; j++) {
                float v = sf[nt][j] * 0.125f;
                if (domask) {
                    int kcol = kg + (j & 1);
                    int qrow = (j < 2) ? qg0 : qg1;
                    if (kcol > qrow) v = -1e30f;
                }
                sf[nt][j] = v;
                if (j < 2) rm0 = fmaxf(rm0, v); else rm1 = fmaxf(rm1, v);
            }
        }
        rm0 = fmaxf(rm0, __shfl_xor_sync(0xffffffffu, rm0, 1));
        rm0 = fmaxf(rm0, __shfl_xor_sync(0xffffffffu, rm0, 2));
        rm1 = fmaxf(rm1, __shfl_xor_sync(0xffffffffu, rm1, 1));
        rm1 = fmaxf(rm1, __shfl_xor_sync(0xffffffffu, rm1, 2));

        float nm0 = fmaxf(m0, rm0), nm1 = fmaxf(m1, rm1);
        float c0 = __expf(m0 - nm0), c1 = __expf(m1 - nm1);

        // ---- exp + row sum + pack P (single fp16) ----
        float rs0 = 0.f, rs1 = 0.f;
        uint32_t ph[8][2];
#pragma unroll
        for (int nt = 0; nt < 8; nt++) {
            float p0 = __expf(sf[nt][0] - nm0);
            float p1 = __expf(sf[nt][1] - nm0);
            float p2 = __expf(sf[nt][2] - nm1);
            float p3 = __expf(sf[nt][3] - nm1);
            rs0 += p0 + p1;
            rs1 += p2 + p3;
            __half2 h01 = __floats2half2_rn(p0, p1);
            __half2 h23 = __floats2half2_rn(p2, p3);
            ph[nt][0] = *(uint32_t*)&h01;
            ph[nt][1] = *(uint32_t*)&h23;
        }
        rs0 += __shfl_xor_sync(0xffffffffu, rs0, 1);
        rs0 += __shfl_xor_sync(0xffffffffu, rs0, 2);
        rs1 += __shfl_xor_sync(0xffffffffu, rs1, 1);
        rs1 += __shfl_xor_sync(0xffffffffu, rs1, 2);

        l0 = l0 * c0 + rs0;
        l1 = l1 * c1 + rs1;
        m0 = nm0;
        m1 = nm1;

#pragma unroll
        for (int nt = 0; nt < 8; nt++) {
            o[nt][0] *= c0; o[nt][1] *= c0;
            o[nt][2] *= c1; o[nt][3] *= c1;
        }

        // ---- O += P V (single pass) ----
#pragma unroll
        for (int ks = 0; ks < 4; ks++) {
            uint32_t bh[8][2];
#pragma unroll
            for (int nt = 0; nt < 8; nt++) {
                uint32_t a = vb + (nt * 8 + br) * 144 + (ks * 16 + bcol) * 2;
                ldmat_x2(bh[nt], a);
            }
            uint32_t pah[4] = {ph[2 * ks][0], ph[2 * ks][1],
                               ph[2 * ks + 1][0], ph[2 * ks + 1][1]};
#pragma unroll
            for (int nt = 0; nt < 8; nt++) mma_f16(o[nt], pah, bh[nt]);
        }
        __syncthreads();
    }

    // ---- epilogue: O/l -> single fp16, [b*Q + q, h*64 + d] ----
    float inv0 = 1.0f / l0, inv1 = 1.0f / l1;
    int gr0 = b * QL_ + q0 + wid * 16 + (lane >> 2);
    int gr1 = gr0 + 8;
#pragma unroll
    for (int nt = 0; nt < 8; nt++) {
        int gc = h * 64 + nt * 8 + lc2;
        __half2 h01 = __floats2half2_rn(o[nt][0] * inv0, o[nt][1] * inv0);
        __half2 h23 = __floats2half2_rn(o[nt][2] * inv1, o[nt][3] * inv1);
        *(__half2*)&O[(size_t)gr0 * HID_ + gc] = h01;
        *(__half2*)&O[(size_t)gr1 * HID_ + gc] = h23;
    }
}

// ===========================================================================
extern "C" void kernel_launch(void* const* d_in, const int* in_sizes, int n_in,
                              void* d_out, int out_size)
{
    const float* X  = (const float*)d_in[0];
    const float* Wq = (const float*)d_in[2];
    const float* Wk = (const float*)d_in[3];
    const float* Wv = (const float*)d_in[4];
    const float* Wo = (const float*)d_in[5];
    float* out = (float*)d_out;

    float *cp, *sp;
    __half *x16, *wp, *wop, *a16, *qb, *kb, *v16, *vt;
    cudaGetSymbolAddress((void**)&cp, g_cos);
    cudaGetSymbolAddress((void**)&sp, g_sin);
    cudaGetSymbolAddress((void**)&x16, g_X16);
    cudaGetSymbolAddress((void**)&wp,  g_W);
    cudaGetSymbolAddress((void**)&wop, g_Wo);
    cudaGetSymbolAddress((void**)&a16, g_A16);
    cudaGetSymbolAddress((void**)&qb,  g_Qb);
    cudaGetSymbolAddress((void**)&kb,  g_Kb);
    cudaGetSymbolAddress((void**)&v16, g_V16);
    cudaGetSymbolAddress((void**)&vt,  g_Vt);

    const int M = B_ * QL_;   // 4096

    cudaFuncSetAttribute((const void*)mma_gemm<1>,
                         cudaFuncAttributeMaxDynamicSharedMemorySize, MMA_SMEM_SINGLE);
    cudaFuncSetAttribute((const void*)mma_gemm<0>,
                         cudaFuncAttributeMaxDynamicSharedMemorySize, MMA_SMEM_SINGLE);
    cudaFuncSetAttribute(attn_mma, cudaFuncAttributeMaxDynamicSharedMemorySize, AT_SMEM);

    // prep (rope table must precede QKV gemm — its epilogue consumes it)
    rope_table_kernel<<<(QL_ * 32 + 255) / 256, 256>>>(cp, sp, QL_);
    round_half_kernel<<<(M * HID_ + 255) / 256, 256>>>(X, x16, M * HID_);
    transpose_half_kernel<<<dim3(2048 / 32, HID_ / 32), dim3(32, 8)>>>(Wq, wp, HID_, 2048, 0);
    transpose_half_kernel<<<dim3(512 / 32,  HID_ / 32), dim3(32, 8)>>>(Wk, wp, HID_, 512, 2048);
    transpose_half_kernel<<<dim3(512 / 32,  HID_ / 32), dim3(32, 8)>>>(Wv, wp, HID_, 512, 2560);

    // fused QKV projection + RoPE + fp16 conversion (single pass)
    mma_gemm<1><<<dim3(3072 / 256, M / 128), 256, MMA_SMEM_SINGLE>>>(
        x16, wp, nullptr, qb, kb, v16, cp, sp, M, 3072, HID_);

    // V^T ; Wo transpose
    vtrans_h_kernel<<<dim3(QL_ / 32, 2, B_ * KVH_), dim3(32, 8)>>>(v16, vt);
    transpose_half_kernel<<<dim3(2048 / 32, HID_ / 32), dim3(32, 8)>>>(Wo, wop, HID_, 2048, 0);

    // Attention on tensor cores (all single fp16), single-fp16 output
    attn_mma<<<dim3(QL_ / 128, NH_, B_), 256, AT_SMEM>>>(qb, kb, vt, a16);

    // Output projection (A single, 1 pass)
    mma_gemm<0><<<dim3(HID_ / 256, M / 128), 256, MMA_SMEM_SINGLE>>>(
        a16, wop, out, nullptr, nullptr, nullptr, nullptr, nullptr,
        M, HID_, HID_);
}